// round 12
// baseline (speedup 1.0000x reference)
#include <cuda_runtime.h>
#include <cuda_bf16.h>
#include <math.h>
#include <stdint.h>

// ---------------- problem constants ----------------
#define BB 2
#define SS 2048
#define DD 1024
#define HH 16
#define HD 64
#define LL 8
#define VV 32000
#define MM (BB*SS)          // 4096 rows
#define QKVS (3*DD)
#define FFS  (2*DD)

// ---------------- weight offsets (int8 2-word planes + per-row scales) -----
#define WMAT (DD*DD)
#define QKV_OFF 0                       // layer stride 3*WMAT
#define WO_OFF  (3*LL*WMAT)
#define W13_OFF (4*LL*WMAT)             // layer stride 2*WMAT
#define W2_OFF  (6*LL*WMAT)
#define WOUT_OFF (7*LL*WMAT)
#define WTOT (WOUT_OFF + (size_t)VV*DD)
#define WROWS (7*LL*DD + VV)

// ---------------- scratch (device globals) ----------
__device__ float g_x[MM*DD];            // residual stream (fp32)
__device__ float g_o[MM*DD];            // attention output (fp32)
__device__ float g_ff32[MM*FFS];        // w1/w3 outputs (fp32)
__device__ int8_t g_w1q[WTOT];
__device__ int8_t g_w2q[WTOT];
__device__ float  g_wsc[WROWS];
__device__ int8_t g_a1[MM*DD];
__device__ int8_t g_a2[MM*DD];
__device__ float  g_asc[MM];
__device__ __nv_bfloat16 g_qkvh[MM*QKVS];
__device__ __nv_bfloat16 g_qkvl[MM*QKVS];

// ================= helpers =================
__device__ __forceinline__ uint32_t smem_u32(const void* p) {
    uint32_t a;
    asm("{ .reg .u64 t; cvta.to.shared.u64 t, %1; cvt.u32.u64 %0, t; }"
        : "=r"(a) : "l"(p));
    return a;
}
#define CP16(dst, src) \
    asm volatile("cp.async.cg.shared.global [%0], [%1], 16;" :: "r"(dst), "l"(src))
#define CP8(dst, src) \
    asm volatile("cp.async.ca.shared.global [%0], [%1], 8;" :: "r"(dst), "l"(src))
#define CP_COMMIT() asm volatile("cp.async.commit_group;" ::: "memory")
#define CP_WAIT1()  asm volatile("cp.async.wait_group 1;" ::: "memory")
#define CP_WAIT0()  asm volatile("cp.async.wait_group 0;" ::: "memory")
#define LDSM4(r, addr) \
    asm volatile("ldmatrix.sync.aligned.m8n8.x4.shared.b16 {%0,%1,%2,%3}, [%4];" \
        : "=r"((r)[0]), "=r"((r)[1]), "=r"((r)[2]), "=r"((r)[3]) : "r"(addr))
#define LDSM4T(r, addr) \
    asm volatile("ldmatrix.sync.aligned.m8n8.x4.trans.shared.b16 {%0,%1,%2,%3}, [%4];" \
        : "=r"((r)[0]), "=r"((r)[1]), "=r"((r)[2]), "=r"((r)[3]) : "r"(addr))
#define MMA16816(c, a, b0v, b1v) \
    asm volatile("mma.sync.aligned.m16n8k16.row.col.f32.bf16.bf16.f32 " \
        "{%0,%1,%2,%3}, {%4,%5,%6,%7}, {%8,%9}, {%0,%1,%2,%3};" \
        : "+f"((c)[0]), "+f"((c)[1]), "+f"((c)[2]), "+f"((c)[3]) \
        : "r"((a)[0]), "r"((a)[1]), "r"((a)[2]), "r"((a)[3]), "r"(b0v), "r"(b1v))
#define MMAI8(c, a, b0v, b1v) \
    asm volatile("mma.sync.aligned.m16n8k32.row.col.s32.s8.s8.s32 " \
        "{%0,%1,%2,%3}, {%4,%5,%6,%7}, {%8,%9}, {%0,%1,%2,%3};" \
        : "+r"((c)[0]), "+r"((c)[1]), "+r"((c)[2]), "+r"((c)[3]) \
        : "r"((a)[0]), "r"((a)[1]), "r"((a)[2]), "r"((a)[3]), "r"(b0v), "r"(b1v))

__device__ __forceinline__ void split1(float x, __nv_bfloat16& h, __nv_bfloat16& l) {
    h = __float2bfloat16(x);
    l = __float2bfloat16(x - __bfloat162float(h));
}
__device__ __forceinline__ void quant2(float v, float s, float inv, int8_t& q1, int8_t& q2) {
    int a = __float2int_rn(v * inv);
    a = a > 127 ? 127 : (a < -127 ? -127 : a);
    float r = v - (float)a * s;
    int b = __float2int_rn(r * inv * 128.f);
    b = b > 127 ? 127 : (b < -127 ? -127 : b);
    q1 = (int8_t)a; q2 = (int8_t)b;
}

// ---------------- per-row int8 2-word quantization (rows of length K) ------
__global__ void quant_rows(const float* __restrict__ src,
                           int8_t* __restrict__ q1, int8_t* __restrict__ q2,
                           float* __restrict__ sc, int K) {
    int row = blockIdx.x;
    const float* x = src + (size_t)row * K;
    int tid = threadIdx.x;
    float mx = 0.f;
    for (int i = tid * 4; i < K; i += 1024) {
        float4 v = *(const float4*)(x + i);
        mx = fmaxf(mx, fmaxf(fmaxf(fabsf(v.x), fabsf(v.y)),
                             fmaxf(fabsf(v.z), fabsf(v.w))));
    }
    #pragma unroll
    for (int o = 16; o; o >>= 1) mx = fmaxf(mx, __shfl_xor_sync(0xffffffffu, mx, o));
    __shared__ float wmax[8];
    if ((tid & 31) == 0) wmax[tid >> 5] = mx;
    __syncthreads();
    __shared__ float s_s, s_inv;
    if (tid == 0) {
        float m = 0.f;
        #pragma unroll
        for (int i = 0; i < 8; i++) m = fmaxf(m, wmax[i]);
        float s = fmaxf(m, 1e-20f) / 127.f;
        s_s = s; s_inv = 1.f / s;
    }
    __syncthreads();
    float s = s_s, inv = s_inv;
    for (int i = tid * 4; i < K; i += 1024) {
        float4 v = *(const float4*)(x + i);
        char4 c1, c2;
        quant2(v.x, s, inv, (int8_t&)c1.x, (int8_t&)c2.x);
        quant2(v.y, s, inv, (int8_t&)c1.y, (int8_t&)c2.y);
        quant2(v.z, s, inv, (int8_t&)c1.z, (int8_t&)c2.z);
        quant2(v.w, s, inv, (int8_t&)c1.w, (int8_t&)c2.w);
        *(char4*)(q1 + (size_t)row * K + i) = c1;
        *(char4*)(q2 + (size_t)row * K + i) = c2;
    }
    if (tid == 0) sc[row] = s;
}

// ---------------- layernorm -> int8 2-word quantized row -------------------
__global__ void ln_q(const float* __restrict__ x,
                     const float* __restrict__ gw, const float* __restrict__ bw,
                     int8_t* __restrict__ q1, int8_t* __restrict__ q2,
                     float* __restrict__ sc) {
    __shared__ float vals[DD];
    int row = blockIdx.x;
    const float* xr = x + (size_t)row * DD;
    int tid = threadIdx.x;
    float s = 0.f, s2 = 0.f;
    for (int i = tid; i < DD; i += 256) {
        float v = xr[i];
        s += v; s2 = fmaf(v, v, s2);
    }
    __shared__ float rs[8], rs2[8];
    #pragma unroll
    for (int o = 16; o; o >>= 1) {
        s  += __shfl_down_sync(0xffffffffu, s,  o);
        s2 += __shfl_down_sync(0xffffffffu, s2, o);
    }
    if ((tid & 31) == 0) { rs[tid >> 5] = s; rs2[tid >> 5] = s2; }
    __syncthreads();
    __shared__ float mean_s, rstd_s;
    if (tid == 0) {
        float ts = 0.f, ts2 = 0.f;
        #pragma unroll
        for (int i = 0; i < 8; i++) { ts += rs[i]; ts2 += rs2[i]; }
        float m = ts / (float)DD;
        mean_s = m;
        rstd_s = rsqrtf(ts2 / (float)DD - m * m + 1e-5f);
    }
    __syncthreads();
    float m = mean_s, r = rstd_s, mx = 0.f;
    for (int i = tid; i < DD; i += 256) {
        float v = (xr[i] - m) * r * gw[i] + bw[i];
        vals[i] = v;
        mx = fmaxf(mx, fabsf(v));
    }
    #pragma unroll
    for (int o = 16; o; o >>= 1) mx = fmaxf(mx, __shfl_xor_sync(0xffffffffu, mx, o));
    __shared__ float wmax[8];
    if ((tid & 31) == 0) wmax[tid >> 5] = mx;
    __syncthreads();
    __shared__ float qs_s, qi_s;
    if (tid == 0) {
        float mm = 0.f;
        #pragma unroll
        for (int i = 0; i < 8; i++) mm = fmaxf(mm, wmax[i]);
        float qs = fmaxf(mm, 1e-20f) / 127.f;
        qs_s = qs; qi_s = 1.f / qs;
    }
    __syncthreads();
    float qs = qs_s, qi = qi_s;
    {
        int i = tid * 4;
        char4 c1, c2;
        quant2(vals[i+0], qs, qi, (int8_t&)c1.x, (int8_t&)c2.x);
        quant2(vals[i+1], qs, qi, (int8_t&)c1.y, (int8_t&)c2.y);
        quant2(vals[i+2], qs, qi, (int8_t&)c1.z, (int8_t&)c2.z);
        quant2(vals[i+3], qs, qi, (int8_t&)c1.w, (int8_t&)c2.w);
        *(char4*)(q1 + (size_t)row * DD + i) = c1;
        *(char4*)(q2 + (size_t)row * DD + i) = c2;
    }
    if (tid == 0) sc[row] = qs;
}

// ---------------- SwiGLU (fp32 ff in) -> int8 quantized row ----------------
__global__ void swiglu_q(const float* __restrict__ ff,
                         int8_t* __restrict__ q1, int8_t* __restrict__ q2,
                         float* __restrict__ sc) {
    __shared__ float vals[DD];
    int row = blockIdx.x;
    const float* fr = ff + (size_t)row * FFS;
    int tid = threadIdx.x;
    float mx = 0.f;
    for (int i = tid; i < DD; i += 256) {
        float a = fr[i], c = fr[i + DD];
        float g = a / (1.f + __expf(-a)) * c;
        vals[i] = g;
        mx = fmaxf(mx, fabsf(g));
    }
    #pragma unroll
    for (int o = 16; o; o >>= 1) mx = fmaxf(mx, __shfl_xor_sync(0xffffffffu, mx, o));
    __shared__ float wmax[8];
    if ((tid & 31) == 0) wmax[tid >> 5] = mx;
    __syncthreads();
    __shared__ float qs_s, qi_s;
    if (tid == 0) {
        float mm = 0.f;
        #pragma unroll
        for (int i = 0; i < 8; i++) mm = fmaxf(mm, wmax[i]);
        float qs = fmaxf(mm, 1e-20f) / 127.f;
        qs_s = qs; qi_s = 1.f / qs;
    }
    __syncthreads();
    float qs = qs_s, qi = qi_s;
    {
        int i = tid * 4;
        char4 c1, c2;
        quant2(vals[i+0], qs, qi, (int8_t&)c1.x, (int8_t&)c2.x);
        quant2(vals[i+1], qs, qi, (int8_t&)c1.y, (int8_t&)c2.y);
        quant2(vals[i+2], qs, qi, (int8_t&)c1.z, (int8_t&)c2.z);
        quant2(vals[i+3], qs, qi, (int8_t&)c1.w, (int8_t&)c2.w);
        *(char4*)(q1 + (size_t)row * DD + i) = c1;
        *(char4*)(q2 + (size_t)row * DD + i) = c2;
    }
    if (tid == 0) sc[row] = qs;
}

// ================= int8 Ozaki GEMM =================
// C[M,N] = (sA.A)·(sB.W)^T, A≈sA(A1+A2/128), W≈sB(B1+B2/128), drop A2B2.
// Tile 128x128, BK=64, 512 thr (16 warps 4x4, warp tile 32x32), occ 1.
#define RS 80
#define IPLANE (128*RS)      // 10240
#define ISTAGE (4*IPLANE)    // 40960
#define IGSMEM (2*ISTAGE)    // 81920

template<int OUTMODE>   // 0: fp32 C   1: fp32 C with residual R   2: bf16 hi/lo split
__global__ void __launch_bounds__(512, 1)
gemm_i8(const int8_t* __restrict__ A1, const int8_t* __restrict__ A2,
        const float* __restrict__ sA,
        const int8_t* __restrict__ B1, const int8_t* __restrict__ B2,
        const float* __restrict__ sB,
        const float* __restrict__ R, float* __restrict__ C,
        __nv_bfloat16* __restrict__ Chi, __nv_bfloat16* __restrict__ Clo,
        int N, int K) {
    extern __shared__ char sm_raw[];
    uint32_t sb = smem_u32(sm_raw);
    int tid = threadIdx.x, lane = tid & 31, wid = tid >> 5;
    int wm = wid & 3, wn = wid >> 2;
    int m0 = blockIdx.y * 128, n0 = blockIdx.x * 128;
    const int8_t* srcs[4] = {A1, A2, B1, B2};
    int nslab = K / 64;
    int prow = tid & 127, ppl = tid >> 7;

    {   // prologue: plane ppl, row prow, 64 bytes
        int rb = (ppl < 2) ? m0 : n0;
        const int8_t* g = srcs[ppl] + (size_t)(rb + prow) * K;
        uint32_t d = sb + ppl * IPLANE + prow * RS;
        CP16(d, g); CP16(d + 16, g + 16);
        CP16(d + 32, g + 32); CP16(d + 48, g + 48);
        CP_COMMIT();
    }

    int d11[2][4][4] = {};
    int d12[2][4][4] = {};
    int gq = lane >> 3, rr = lane & 7;

    for (int s = 0; s < nslab; s++) {
        if (s + 1 < nslab) {
            uint32_t stb = sb + ((s + 1) & 1) * ISTAGE;
            int k0 = (s + 1) * 64;
            int rb = (ppl < 2) ? m0 : n0;
            const int8_t* g = srcs[ppl] + (size_t)(rb + prow) * K + k0;
            uint32_t d = stb + ppl * IPLANE + prow * RS;
            CP16(d, g); CP16(d + 16, g + 16);
            CP16(d + 32, g + 32); CP16(d + 48, g + 48);
            CP_COMMIT();
            CP_WAIT1();
        } else {
            CP_WAIT0();
        }
        __syncthreads();

        uint32_t stb = sb + (s & 1) * ISTAGE;
        #pragma unroll
        for (int kc = 0; kc < 2; kc++) {
            uint32_t a1f[2][4], a2f[2][4];
            #pragma unroll
            for (int mf = 0; mf < 2; mf++) {
                int row = wm * 32 + mf * 16 + (gq & 1) * 8 + rr;
                uint32_t ad = stb + row * RS + kc * 32 + (gq >> 1) * 16;
                LDSM4(a1f[mf], ad);
                LDSM4(a2f[mf], ad + IPLANE);
            }
            #pragma unroll
            for (int np = 0; np < 2; np++) {
                uint32_t b1f[4], b2f[4];
                int row = wn * 32 + np * 16 + (gq >> 1) * 8 + rr;
                uint32_t ad = stb + 2 * IPLANE + row * RS + kc * 32 + (gq & 1) * 16;
                LDSM4(b1f, ad);
                LDSM4(b2f, ad + IPLANE);
                #pragma unroll
                for (int mf = 0; mf < 2; mf++) {
                    MMAI8(d11[mf][np*2],   a1f[mf], b1f[0], b1f[1]);
                    MMAI8(d12[mf][np*2],   a2f[mf], b1f[0], b1f[1]);
                    MMAI8(d12[mf][np*2],   a1f[mf], b2f[0], b2f[1]);
                    MMAI8(d11[mf][np*2+1], a1f[mf], b1f[2], b1f[3]);
                    MMAI8(d12[mf][np*2+1], a2f[mf], b1f[2], b1f[3]);
                    MMAI8(d12[mf][np*2+1], a1f[mf], b2f[2], b2f[3]);
                }
            }
        }
        __syncthreads();
    }

    // epilogue
    int rbase = m0 + wm * 32 + (lane >> 2);
    int cbase = n0 + wn * 32 + (lane & 3) * 2;
    #pragma unroll
    for (int mf = 0; mf < 2; mf++) {
        int row = rbase + mf * 16;
        float sa0 = sA[row], sa1 = sA[row + 8];
        #pragma unroll
        for (int nf = 0; nf < 4; nf++) {
            int col = cbase + nf * 8;
            float sb0 = sB[col], sb1 = sB[col + 1];
            float v0 = sa0 * sb0 * ((float)d11[mf][nf][0] + (float)d12[mf][nf][0] * 0.0078125f);
            float v1 = sa0 * sb1 * ((float)d11[mf][nf][1] + (float)d12[mf][nf][1] * 0.0078125f);
            float v2 = sa1 * sb0 * ((float)d11[mf][nf][2] + (float)d12[mf][nf][2] * 0.0078125f);
            float v3 = sa1 * sb1 * ((float)d11[mf][nf][3] + (float)d12[mf][nf][3] * 0.0078125f);
            size_t a0 = (size_t)row * N + col;
            size_t a1 = (size_t)(row + 8) * N + col;
            if (OUTMODE == 2) {
                __nv_bfloat16 h0,h1,h2,h3,L0,L1,L2,L3;
                split1(v0, h0, L0); split1(v1, h1, L1);
                split1(v2, h2, L2); split1(v3, h3, L3);
                *(__nv_bfloat162*)(Chi + a0) = __halves2bfloat162(h0, h1);
                *(__nv_bfloat162*)(Clo + a0) = __halves2bfloat162(L0, L1);
                *(__nv_bfloat162*)(Chi + a1) = __halves2bfloat162(h2, h3);
                *(__nv_bfloat162*)(Clo + a1) = __halves2bfloat162(L2, L3);
            } else {
                if (OUTMODE == 1) {
                    float2 r0 = *(const float2*)(R + a0);
                    float2 r1 = *(const float2*)(R + a1);
                    v0 += r0.x; v1 += r0.y; v2 += r1.x; v3 += r1.y;
                }
                *(float2*)(C + a0) = make_float2(v0, v1);
                *(float2*)(C + a1) = make_float2(v2, v3);
            }
        }
    }
}

// ================= mma.sync flash attention (bf16 planes, fp32 out) =======
#define ALD 72
#define APLANE (64*ALD*2)
#define ASMEM  (6*APLANE)

__global__ void __launch_bounds__(128)
attn_mma(const __nv_bfloat16* __restrict__ Ph, const __nv_bfloat16* __restrict__ Pl,
         float* __restrict__ O) {
    extern __shared__ char asmr[];
    uint32_t sb = smem_u32(asmr);
    const uint32_t QH = sb, QL = sb + APLANE, KH = sb + 2*APLANE,
                   KL = sb + 3*APLANE, VH = sb + 4*APLANE, VL = sb + 5*APLANE;

    int tid = threadIdx.x, lane = tid & 31, w = tid >> 5;
    int gq = lane >> 3, rr = lane & 7;
    int bh = blockIdx.y;
    int b = bh / HH, h = bh % HH;
    int qt = blockIdx.x;
    float slope = exp2f(-0.5f * (float)(h + 1));

    int lrow = tid >> 4;
    int lcol = (tid & 15) * 4;

    #pragma unroll
    for (int pass = 0; pass < 8; pass++) {
        int row = lrow + pass * 8;
        size_t ga = (size_t)(b*SS + qt*64 + row) * QKVS + h*HD + lcol;
        uint32_t off = (row*ALD + lcol) * 2;
        CP8(QH + off, Ph + ga);
        CP8(QL + off, Pl + ga);
    }
    CP_COMMIT();
    CP_WAIT0();
    __syncthreads();

    uint32_t qh[4][4], ql[4][4];
    #pragma unroll
    for (int kk = 0; kk < 4; kk++) {
        uint32_t off = ((w*16 + (gq & 1)*8 + rr)*ALD + kk*16 + (gq >> 1)*8) * 2;
        LDSM4(qh[kk], QH + off);
        LDSM4(ql[kk], QL + off);
    }

    float m0r = -INFINITY, m1r = -INFINITY, l0s = 0.f, l1s = 0.f;
    float o[8][4] = {};
    int qg0 = qt*64 + w*16 + (lane >> 2);
    int qg1 = qg0 + 8;

    for (int kt = 0; kt <= qt; kt++) {
        __syncthreads();
        #pragma unroll
        for (int pass = 0; pass < 8; pass++) {
            int row = lrow + pass * 8;
            size_t gr = (size_t)(b*SS + kt*64 + row) * QKVS + h*HD + lcol;
            uint32_t off = (row*ALD + lcol) * 2;
            CP8(KH + off, Ph + gr + DD);
            CP8(KL + off, Pl + gr + DD);
            CP8(VH + off, Ph + gr + 2*DD);
            CP8(VL + off, Pl + gr + 2*DD);
        }
        CP_COMMIT();
        CP_WAIT0();
        __syncthreads();

        float s[8][4] = {};
        #pragma unroll
        for (int kk = 0; kk < 4; kk++) {
            #pragma unroll
            for (int np = 0; np < 4; np++) {
                uint32_t kb[4], kl2[4];
                uint32_t off = ((np*16 + (gq >> 1)*8 + rr)*ALD + kk*16 + (gq & 1)*8) * 2;
                LDSM4(kb, KH + off);
                LDSM4(kl2, KL + off);
                MMA16816(s[np*2],   qh[kk], kb[0], kb[1]);
                MMA16816(s[np*2],   ql[kk], kb[0], kb[1]);
                MMA16816(s[np*2],   qh[kk], kl2[0], kl2[1]);
                MMA16816(s[np*2+1], qh[kk], kb[2], kb[3]);
                MMA16816(s[np*2+1], ql[kk], kb[2], kb[3]);
                MMA16816(s[np*2+1], qh[kk], kl2[2], kl2[3]);
            }
        }

        #pragma unroll
        for (int nf = 0; nf < 8; nf++) {
            #pragma unroll
            for (int c = 0; c < 2; c++) {
                int kg = kt*64 + nf*8 + (lane & 3)*2 + c;
                float sv0 = s[nf][c]   * 0.125f;
                float sv1 = s[nf][2+c] * 0.125f;
                s[nf][c]   = (kg <= qg0) ? sv0 + slope*(float)(kg - qg0) : -1e30f;
                s[nf][2+c] = (kg <= qg1) ? sv1 + slope*(float)(kg - qg1) : -1e30f;
            }
        }

        float mx0 = -1e30f, mx1 = -1e30f;
        #pragma unroll
        for (int nf = 0; nf < 8; nf++) {
            mx0 = fmaxf(mx0, fmaxf(s[nf][0], s[nf][1]));
            mx1 = fmaxf(mx1, fmaxf(s[nf][2], s[nf][3]));
        }
        #pragma unroll
        for (int off = 1; off <= 2; off <<= 1) {
            mx0 = fmaxf(mx0, __shfl_xor_sync(0xffffffffu, mx0, off));
            mx1 = fmaxf(mx1, __shfl_xor_sync(0xffffffffu, mx1, off));
        }
        float mn0 = fmaxf(m0r, mx0), mn1 = fmaxf(m1r, mx1);
        float al0 = __expf(m0r - mn0), al1 = __expf(m1r - mn1);
        float rs0 = 0.f, rs1 = 0.f;
        #pragma unroll
        for (int nf = 0; nf < 8; nf++) {
            s[nf][0] = __expf(s[nf][0] - mn0);
            s[nf][1] = __expf(s[nf][1] - mn0);
            s[nf][2] = __expf(s[nf][2] - mn1);
            s[nf][3] = __expf(s[nf][3] - mn1);
            rs0 += s[nf][0] + s[nf][1];
            rs1 += s[nf][2] + s[nf][3];
        }
        #pragma unroll
        for (int off = 1; off <= 2; off <<= 1) {
            rs0 += __shfl_xor_sync(0xffffffffu, rs0, off);
            rs1 += __shfl_xor_sync(0xffffffffu, rs1, off);
        }
        l0s = l0s * al0 + rs0;
        l1s = l1s * al1 + rs1;
        m0r = mn0; m1r = mn1;

        #pragma unroll
        for (int nf = 0; nf < 8; nf++) {
            o[nf][0] *= al0; o[nf][1] *= al0;
            o[nf][2] *= al1; o[nf][3] *= al1;
        }

        #pragma unroll
        for (int kk = 0; kk < 4; kk++) {
            uint32_t Ah[4], Al2[4];
            #pragma unroll
            for (int half = 0; half < 2; half++) {
                float* sv = s[2*kk + half];
                __nv_bfloat162 h01 = __floats2bfloat162_rn(sv[0], sv[1]);
                __nv_bfloat162 h23 = __floats2bfloat162_rn(sv[2], sv[3]);
                __nv_bfloat162 L01 = __floats2bfloat162_rn(
                    sv[0] - __bfloat162float(__low2bfloat16(h01)),
                    sv[1] - __bfloat162float(__high2bfloat16(h01)));
                __nv_bfloat162 L23 = __floats2bfloat162_rn(
                    sv[2] - __bfloat162float(__low2bfloat16(h23)),
                    sv[3] - __bfloat162float(__high2bfloat16(h23)));
                Ah[half*2 + 0] = *(uint32_t*)&h01;
                Ah[half*2 + 1] = *(uint32_t*)&h23;
                Al2[half*2 + 0] = *(uint32_t*)&L01;
                Al2[half*2 + 1] = *(uint32_t*)&L23;
            }
            #pragma unroll
            for (int np = 0; np < 4; np++) {
                uint32_t vb[4], vl2[4];
                uint32_t off = ((kk*16 + (gq & 1)*8 + rr)*ALD + np*16 + (gq >> 1)*8) * 2;
                LDSM4T(vb, VH + off);
                LDSM4T(vl2, VL + off);
                MMA16816(o[np*2],   Ah,  vb[0], vb[1]);
                MMA16816(o[np*2],   Al2, vb[0], vb[1]);
                MMA16816(o[np*2],   Ah,  vl2[0], vl2[1]);
                MMA16816(o[np*2+1], Ah,  vb[2], vb[3]);
                MMA16816(o[np*2+1], Al2, vb[2], vb[3]);
                MMA16816(o[np*2+1], Ah,  vl2[2], vl2[3]);
            }
        }
    }

    float inv0 = 1.f / l0s, inv1 = 1.f / l1s;
    int row0 = b*SS + qt*64 + w*16 + (lane >> 2);
    int colb = h*HD + (lane & 3)*2;
    #pragma unroll
    for (int nf = 0; nf < 8; nf++) {
        size_t a0 = (size_t)row0 * DD + colb + nf*8;
        size_t a1 = (size_t)(row0 + 8) * DD + colb + nf*8;
        *(float2*)(O + a0) = make_float2(o[nf][0]*inv0, o[nf][1]*inv0);
        *(float2*)(O + a1) = make_float2(o[nf][2]*inv1, o[nf][3]*inv1);
    }
}

// ---------------- embedding lookup ----------------
__global__ void embed_kernel(const int* __restrict__ tokens,
                             const float* __restrict__ emb,
                             float* __restrict__ x) {
    int row = blockIdx.x;
    int tok = tokens[row];
    const float4* src = (const float4*)(emb + (size_t)tok * DD);
    float4* dst = (float4*)(x + (size_t)row * DD);
    for (int i = threadIdx.x; i < DD/4; i += blockDim.x) dst[i] = src[i];
}

// ---------------- launch ----------------
extern "C" void kernel_launch(void* const* d_in, const int* in_sizes, int n_in,
                              void* d_out, int out_size) {
    const int*   tokens = (const int*)d_in[0];
    const float* emb    = (const float*)d_in[1];
    const float* wq     = (const float*)d_in[2];
    const float* wk     = (const float*)d_in[3];
    const float* wv     = (const float*)d_in[4];
    const float* wo     = (const float*)d_in[5];
    const float* ln1_g  = (const float*)d_in[6];
    const float* ln1_b  = (const float*)d_in[7];
    const float* ln2_g  = (const float*)d_in[8];
    const float* ln2_b  = (const float*)d_in[9];
    const float* w1     = (const float*)d_in[10];
    const float* w2     = (const float*)d_in[11];
    const float* w3     = (const float*)d_in[12];
    const float* lnf_g  = (const float*)d_in[13];
    const float* lnf_b  = (const float*)d_in[14];
    const float* w_out  = (const float*)d_in[15];
    float* out = (float*)d_out;

    float *px, *po, *pff;
    cudaGetSymbolAddress((void**)&px, g_x);
    cudaGetSymbolAddress((void**)&po, g_o);
    cudaGetSymbolAddress((void**)&pff, g_ff32);
    int8_t *w1q, *w2q, *a1, *a2;
    float *wsc, *asc;
    cudaGetSymbolAddress((void**)&w1q, g_w1q);
    cudaGetSymbolAddress((void**)&w2q, g_w2q);
    cudaGetSymbolAddress((void**)&wsc, g_wsc);
    cudaGetSymbolAddress((void**)&a1, g_a1);
    cudaGetSymbolAddress((void**)&a2, g_a2);
    cudaGetSymbolAddress((void**)&asc, g_asc);
    __nv_bfloat16 *qkvh, *qkvl;
    cudaGetSymbolAddress((void**)&qkvh, g_qkvh);
    cudaGetSymbolAddress((void**)&qkvl, g_qkvl);

    cudaFuncSetAttribute(attn_mma,
                         cudaFuncAttributeMaxDynamicSharedMemorySize, ASMEM);
    cudaFuncSetAttribute(gemm_i8<0>,
                         cudaFuncAttributeMaxDynamicSharedMemorySize, IGSMEM);
    cudaFuncSetAttribute(gemm_i8<1>,
                         cudaFuncAttributeMaxDynamicSharedMemorySize, IGSMEM);
    cudaFuncSetAttribute(gemm_i8<2>,
                         cudaFuncAttributeMaxDynamicSharedMemorySize, IGSMEM);

    // ---- quantize all weights (per-row scale, 2-word int8) ----
    for (int l = 0; l < LL; l++) {
        size_t so = (size_t)l * WMAT;
        size_t qo = QKV_OFF + (size_t)l * 3 * WMAT;
        quant_rows<<<DD, 256>>>(wq + so, w1q + qo,          w2q + qo,          wsc + qo/DD,          DD);
        quant_rows<<<DD, 256>>>(wk + so, w1q + qo + WMAT,   w2q + qo + WMAT,   wsc + (qo+WMAT)/DD,   DD);
        quant_rows<<<DD, 256>>>(wv + so, w1q + qo + 2*WMAT, w2q + qo + 2*WMAT, wsc + (qo+2*WMAT)/DD, DD);
        size_t fo = W13_OFF + (size_t)l * 2 * WMAT;
        quant_rows<<<DD, 256>>>(w1 + so, w1q + fo,          w2q + fo,          wsc + fo/DD,          DD);
        quant_rows<<<DD, 256>>>(w3 + so, w1q + fo + WMAT,   w2q + fo + WMAT,   wsc + (fo+WMAT)/DD,   DD);
    }
    quant_rows<<<LL*DD, 256>>>(wo, w1q + WO_OFF, w2q + WO_OFF, wsc + WO_OFF/DD, DD);
    quant_rows<<<LL*DD, 256>>>(w2, w1q + W2_OFF, w2q + W2_OFF, wsc + W2_OFF/DD, DD);
    quant_rows<<<VV, 256>>>(w_out, w1q + WOUT_OFF, w2q + WOUT_OFF, wsc + WOUT_OFF/DD, DD);

    embed_kernel<<<MM, 256>>>(tokens, emb, px);

    dim3 gQKV(QKVS/128, MM/128);
    dim3 gD(DD/128, MM/128);
    dim3 gFF(FFS/128, MM/128);
    for (int l = 0; l < LL; l++) {
        size_t qo = QKV_OFF + (size_t)l * 3 * WMAT;
        size_t oo = WO_OFF + (size_t)l * WMAT;
        size_t fo = W13_OFF + (size_t)l * 2 * WMAT;
        size_t to = W2_OFF + (size_t)l * WMAT;

        // attention
        ln_q<<<MM, 256>>>(px, ln1_g + l*DD, ln1_b + l*DD, a1, a2, asc);
        gemm_i8<2><<<gQKV, 512, IGSMEM>>>(a1, a2, asc,
                                          w1q + qo, w2q + qo, wsc + qo/DD,
                                          nullptr, nullptr, qkvh, qkvl, QKVS, DD);
        attn_mma<<<dim3(SS/64, BB*HH), 128, ASMEM>>>(qkvh, qkvl, po);
        quant_rows<<<MM, 256>>>(po, a1, a2, asc, DD);
        gemm_i8<1><<<gD, 512, IGSMEM>>>(a1, a2, asc,
                                        w1q + oo, w2q + oo, wsc + oo/DD,
                                        px, px, nullptr, nullptr, DD, DD);

        // SwiGLU FFN
        ln_q<<<MM, 256>>>(px, ln2_g + l*DD, ln2_b + l*DD, a1, a2, asc);
        gemm_i8<0><<<gFF, 512, IGSMEM>>>(a1, a2, asc,
                                         w1q + fo, w2q + fo, wsc + fo/DD,
                                         nullptr, pff, nullptr, nullptr, FFS, DD);
        swiglu_q<<<MM, 256>>>(pff, a1, a2, asc);
        gemm_i8<1><<<gD, 512, IGSMEM>>>(a1, a2, asc,
                                        w1q + to, w2q + to, wsc + to/DD,
                                        px, px, nullptr, nullptr, DD, DD);
    }

    // final LN + logits
    ln_q<<<MM, 256>>>(px, lnf_g, lnf_b, a1, a2, asc);
    gemm_i8<0><<<dim3(VV/128, MM/128), 512, IGSMEM>>>(
        a1, a2, asc, w1q + WOUT_OFF, w2q + WOUT_OFF, wsc + WOUT_OFF/DD,
        nullptr, out, nullptr, nullptr, VV, DD);
}

// round 13
// speedup vs baseline: 2.6030x; 2.6030x over previous
#include <cuda_runtime.h>
#include <cuda_bf16.h>
#include <cuda_fp16.h>
#include <math.h>
#include <stdint.h>

// ---------------- problem constants ----------------
#define BB 2
#define SS 2048
#define DD 1024
#define HH 16
#define HD 64
#define LL 8
#define VV 32000
#define MM (BB*SS)          // 4096 rows
#define QKVS (3*DD)
#define FFS  (2*DD)

// ---------------- weight plane offsets ----------------
#define WMAT (DD*DD)
#define QKV_OFF 0                       // layer stride 3*WMAT (q,k,v row-blocks)
#define WO_OFF  (3*LL*WMAT)
#define W13_OFF (4*LL*WMAT)             // layer stride 2*WMAT (w1, w3 row-blocks)
#define W2_OFF  (6*LL*WMAT)
#define WOUT_OFF (7*LL*WMAT)            // fp16 single plane lives here
#define WTOT (WOUT_OFF + (size_t)VV*DD)

// ---------------- scratch (device globals) ----------
__device__ float g_x[MM*DD];
__device__ __nv_bfloat16 g_whi[WTOT];
__device__ __nv_bfloat16 g_wlo[WTOT];
__device__ __nv_bfloat16 g_ahi[MM*DD];
__device__ __nv_bfloat16 g_alo[MM*DD];
__device__ __nv_bfloat16 g_qkvh[MM*QKVS];
__device__ __nv_bfloat16 g_qkvl[MM*QKVS];
__device__ __nv_bfloat16 g_ffh[MM*FFS];
__device__ __nv_bfloat16 g_ffl[MM*FFS];

// ================= helpers =================
__device__ __forceinline__ uint32_t smem_u32(const void* p) {
    uint32_t a;
    asm("{ .reg .u64 t; cvta.to.shared.u64 t, %1; cvt.u32.u64 %0, t; }"
        : "=r"(a) : "l"(p));
    return a;
}
#define CP16(dst, src) \
    asm volatile("cp.async.cg.shared.global [%0], [%1], 16;" :: "r"(dst), "l"(src))
#define CP8(dst, src) \
    asm volatile("cp.async.ca.shared.global [%0], [%1], 8;" :: "r"(dst), "l"(src))
#define CP_COMMIT() asm volatile("cp.async.commit_group;" ::: "memory")
#define CP_WAIT1()  asm volatile("cp.async.wait_group 1;" ::: "memory")
#define CP_WAIT0()  asm volatile("cp.async.wait_group 0;" ::: "memory")
#define LDSM4(r, addr) \
    asm volatile("ldmatrix.sync.aligned.m8n8.x4.shared.b16 {%0,%1,%2,%3}, [%4];" \
        : "=r"((r)[0]), "=r"((r)[1]), "=r"((r)[2]), "=r"((r)[3]) : "r"(addr))
#define LDSM4T(r, addr) \
    asm volatile("ldmatrix.sync.aligned.m8n8.x4.trans.shared.b16 {%0,%1,%2,%3}, [%4];" \
        : "=r"((r)[0]), "=r"((r)[1]), "=r"((r)[2]), "=r"((r)[3]) : "r"(addr))
#define MMA16816(c, a, b0v, b1v) \
    asm volatile("mma.sync.aligned.m16n8k16.row.col.f32.bf16.bf16.f32 " \
        "{%0,%1,%2,%3}, {%4,%5,%6,%7}, {%8,%9}, {%0,%1,%2,%3};" \
        : "+f"((c)[0]), "+f"((c)[1]), "+f"((c)[2]), "+f"((c)[3]) \
        : "r"((a)[0]), "r"((a)[1]), "r"((a)[2]), "r"((a)[3]), "r"(b0v), "r"(b1v))
#define MMAH(c, a, b0v, b1v) \
    asm volatile("mma.sync.aligned.m16n8k16.row.col.f32.f16.f16.f32 " \
        "{%0,%1,%2,%3}, {%4,%5,%6,%7}, {%8,%9}, {%0,%1,%2,%3};" \
        : "+f"((c)[0]), "+f"((c)[1]), "+f"((c)[2]), "+f"((c)[3]) \
        : "r"((a)[0]), "r"((a)[1]), "r"((a)[2]), "r"((a)[3]), "r"(b0v), "r"(b1v))

__device__ __forceinline__ void split1(float x, __nv_bfloat16& h, __nv_bfloat16& l) {
    h = __float2bfloat16(x);
    l = __float2bfloat16(x - __bfloat162float(h));
}

// ---------------- fp32 -> (hi, lo) bf16 split (weights) ----------------
__global__ void conv_split(const float* __restrict__ src,
                           __nv_bfloat16* __restrict__ hi,
                           __nv_bfloat16* __restrict__ lo, int n4) {
    int i = blockIdx.x * 256 + threadIdx.x;
    if (i >= n4) return;
    float4 v = ((const float4*)src)[i];
    __nv_bfloat16 h0, h1, h2, h3, l0, l1, l2, l3;
    split1(v.x, h0, l0); split1(v.y, h1, l1);
    split1(v.z, h2, l2); split1(v.w, h3, l3);
    ((ushort4*)hi)[i] = make_ushort4(__bfloat16_as_ushort(h0), __bfloat16_as_ushort(h1),
                                     __bfloat16_as_ushort(h2), __bfloat16_as_ushort(h3));
    ((ushort4*)lo)[i] = make_ushort4(__bfloat16_as_ushort(l0), __bfloat16_as_ushort(l1),
                                     __bfloat16_as_ushort(l2), __bfloat16_as_ushort(l3));
}

// ---------------- fp32 -> fp16 plane (logits weights) ----------------
__global__ void conv_h(const float* __restrict__ src, __half* __restrict__ dst, int n4) {
    int i = blockIdx.x * 256 + threadIdx.x;
    if (i >= n4) return;
    float4 v = ((const float4*)src)[i];
    __half2 a = __floats2half2_rn(v.x, v.y);
    __half2 b = __floats2half2_rn(v.z, v.w);
    ((uint2*)dst)[i] = make_uint2(*(uint32_t*)&a, *(uint32_t*)&b);
}

// ================= mma.sync split-bf16 GEMM (R6-proven config) =============
// C[M,N] = A[M,K] @ W[N,K]^T. 128x128 tile, BK=32, 256 thr (8 warps 4x2,
// warp tile 32x64), double buffered, occ 2.
#define PLANE_B 10240
#define STAGE_B (4*PLANE_B)
#define GSMEM   (2*STAGE_B)

template<bool RESID, bool SPLITOUT>
__global__ void __launch_bounds__(256, 2)
gemm_mma(const __nv_bfloat16* __restrict__ Ahi, const __nv_bfloat16* __restrict__ Alo,
         const __nv_bfloat16* __restrict__ Bhi, const __nv_bfloat16* __restrict__ Blo,
         const float* __restrict__ R, float* __restrict__ C,
         __nv_bfloat16* __restrict__ Chi, __nv_bfloat16* __restrict__ Clo,
         int N, int K) {
    extern __shared__ char sm_raw[];
    uint32_t sb = smem_u32(sm_raw);
    int tid = threadIdx.x, lane = tid & 31, wid = tid >> 5;
    int wm = wid & 3, wn = wid >> 2;
    int m0 = blockIdx.y * 128, n0 = blockIdx.x * 128;

    int prow = tid >> 1;
    int pc   = (tid & 1) * 2;
    const __nv_bfloat16* srcs[4] = {Ahi, Alo, Bhi, Blo};
    int nslab = K / 32;

    {
        #pragma unroll
        for (int p = 0; p < 4; p++) {
            int rb = (p < 2) ? m0 : n0;
            const __nv_bfloat16* g = srcs[p] + (size_t)(rb + prow) * K + pc * 8;
            uint32_t d = sb + p * PLANE_B + prow * 80 + pc * 16;
            CP16(d, g);
            CP16(d + 16, g + 8);
        }
        CP_COMMIT();
    }

    float acc[2][8][4] = {};
    int gq = lane >> 3, rr = lane & 7;

    for (int s = 0; s < nslab; s++) {
        if (s + 1 < nslab) {
            uint32_t stb = sb + ((s + 1) & 1) * STAGE_B;
            int k0 = (s + 1) * 32;
            #pragma unroll
            for (int p = 0; p < 4; p++) {
                int rb = (p < 2) ? m0 : n0;
                const __nv_bfloat16* g = srcs[p] + (size_t)(rb + prow) * K + k0 + pc * 8;
                uint32_t d = stb + p * PLANE_B + prow * 80 + pc * 16;
                CP16(d, g);
                CP16(d + 16, g + 8);
            }
            CP_COMMIT();
            CP_WAIT1();
        } else {
            CP_WAIT0();
        }
        __syncthreads();

        uint32_t stb = sb + (s & 1) * STAGE_B;
        #pragma unroll
        for (int ks = 0; ks < 2; ks++) {
            uint32_t ah[2][4], al[2][4];
            #pragma unroll
            for (int mf = 0; mf < 2; mf++) {
                int row = wm * 32 + mf * 16 + (gq & 1) * 8 + rr;
                int col = ks * 16 + (gq >> 1) * 8;
                uint32_t a = stb + row * 80 + col * 2;
                LDSM4(ah[mf], a);
                LDSM4(al[mf], a + PLANE_B);
            }
            #pragma unroll
            for (int np = 0; np < 4; np++) {
                uint32_t bh[4], bl[4];
                int row = wn * 64 + np * 16 + (gq >> 1) * 8 + rr;
                int col = ks * 16 + (gq & 1) * 8;
                uint32_t a = stb + 2 * PLANE_B + row * 80 + col * 2;
                LDSM4(bh, a);
                LDSM4(bl, a + PLANE_B);
                #pragma unroll
                for (int mf = 0; mf < 2; mf++) {
                    MMA16816(acc[mf][np*2],   ah[mf], bh[0], bh[1]);
                    MMA16816(acc[mf][np*2],   al[mf], bh[0], bh[1]);
                    MMA16816(acc[mf][np*2],   ah[mf], bl[0], bl[1]);
                    MMA16816(acc[mf][np*2+1], ah[mf], bh[2], bh[3]);
                    MMA16816(acc[mf][np*2+1], al[mf], bh[2], bh[3]);
                    MMA16816(acc[mf][np*2+1], ah[mf], bl[2], bl[3]);
                }
            }
        }
        __syncthreads();
    }

    int rbase = m0 + wm * 32 + (lane >> 2);
    int cbase = n0 + wn * 64 + (lane & 3) * 2;
    #pragma unroll
    for (int mf = 0; mf < 2; mf++) {
        #pragma unroll
        for (int nf = 0; nf < 8; nf++) {
            int row = rbase + mf * 16;
            int col = cbase + nf * 8;
            float v0 = acc[mf][nf][0], v1 = acc[mf][nf][1];
            float v2 = acc[mf][nf][2], v3 = acc[mf][nf][3];
            size_t a0 = (size_t)row * N + col;
            size_t a1 = (size_t)(row + 8) * N + col;
            if (SPLITOUT) {
                __nv_bfloat16 h0,h1,h2,h3,L0,L1,L2,L3;
                split1(v0, h0, L0); split1(v1, h1, L1);
                split1(v2, h2, L2); split1(v3, h3, L3);
                *(__nv_bfloat162*)(Chi + a0) = __halves2bfloat162(h0, h1);
                *(__nv_bfloat162*)(Clo + a0) = __halves2bfloat162(L0, L1);
                *(__nv_bfloat162*)(Chi + a1) = __halves2bfloat162(h2, h3);
                *(__nv_bfloat162*)(Clo + a1) = __halves2bfloat162(L2, L3);
            } else {
                if (RESID) {
                    float2 r0 = *(const float2*)(R + a0);
                    float2 r1 = *(const float2*)(R + a1);
                    v0 += r0.x; v1 += r0.y; v2 += r1.x; v3 += r1.y;
                }
                *(float2*)(C + a0) = make_float2(v0, v1);
                *(float2*)(C + a1) = make_float2(v2, v3);
            }
        }
    }
}

// ================= plain fp16 GEMM (logits head) =================
// C[M,N] = A[M,K] @ W[N,K]^T, fp16 single plane each, fp32 accum.
// Same tiling as gemm_mma; 2 smem planes, 1 MMA per fragment pair.
#define HSTAGE (2*PLANE_B)
#define HGSMEM (2*HSTAGE)

__global__ void __launch_bounds__(256, 2)
gemm_f16(const __half* __restrict__ A, const __half* __restrict__ B,
         float* __restrict__ C, int N, int K) {
    extern __shared__ char sm_raw[];
    uint32_t sb = smem_u32(sm_raw);
    int tid = threadIdx.x, lane = tid & 31, wid = tid >> 5;
    int wm = wid & 3, wn = wid >> 2;
    int m0 = blockIdx.y * 128, n0 = blockIdx.x * 128;

    int prow = tid >> 1;
    int pc   = (tid & 1) * 2;
    const __half* srcs[2] = {A, B};
    int nslab = K / 32;

    {
        #pragma unroll
        for (int p = 0; p < 2; p++) {
            int rb = p ? n0 : m0;
            const __half* g = srcs[p] + (size_t)(rb + prow) * K + pc * 8;
            uint32_t d = sb + p * PLANE_B + prow * 80 + pc * 16;
            CP16(d, g);
            CP16(d + 16, g + 8);
        }
        CP_COMMIT();
    }

    float acc[2][8][4] = {};
    int gq = lane >> 3, rr = lane & 7;

    for (int s = 0; s < nslab; s++) {
        if (s + 1 < nslab) {
            uint32_t stb = sb + ((s + 1) & 1) * HSTAGE;
            int k0 = (s + 1) * 32;
            #pragma unroll
            for (int p = 0; p < 2; p++) {
                int rb = p ? n0 : m0;
                const __half* g = srcs[p] + (size_t)(rb + prow) * K + k0 + pc * 8;
                uint32_t d = stb + p * PLANE_B + prow * 80 + pc * 16;
                CP16(d, g);
                CP16(d + 16, g + 8);
            }
            CP_COMMIT();
            CP_WAIT1();
        } else {
            CP_WAIT0();
        }
        __syncthreads();

        uint32_t stb = sb + (s & 1) * HSTAGE;
        #pragma unroll
        for (int ks = 0; ks < 2; ks++) {
            uint32_t ah[2][4];
            #pragma unroll
            for (int mf = 0; mf < 2; mf++) {
                int row = wm * 32 + mf * 16 + (gq & 1) * 8 + rr;
                int col = ks * 16 + (gq >> 1) * 8;
                LDSM4(ah[mf], stb + row * 80 + col * 2);
            }
            #pragma unroll
            for (int np = 0; np < 4; np++) {
                uint32_t bh[4];
                int row = wn * 64 + np * 16 + (gq >> 1) * 8 + rr;
                int col = ks * 16 + (gq & 1) * 8;
                LDSM4(bh, stb + PLANE_B + row * 80 + col * 2);
                #pragma unroll
                for (int mf = 0; mf < 2; mf++) {
                    MMAH(acc[mf][np*2],   ah[mf], bh[0], bh[1]);
                    MMAH(acc[mf][np*2+1], ah[mf], bh[2], bh[3]);
                }
            }
        }
        __syncthreads();
    }

    int rbase = m0 + wm * 32 + (lane >> 2);
    int cbase = n0 + wn * 64 + (lane & 3) * 2;
    #pragma unroll
    for (int mf = 0; mf < 2; mf++) {
        #pragma unroll
        for (int nf = 0; nf < 8; nf++) {
            int row = rbase + mf * 16;
            int col = cbase + nf * 8;
            size_t a0 = (size_t)row * N + col;
            size_t a1 = (size_t)(row + 8) * N + col;
            *(float2*)(C + a0) = make_float2(acc[mf][nf][0], acc[mf][nf][1]);
            *(float2*)(C + a1) = make_float2(acc[mf][nf][2], acc[mf][nf][3]);
        }
    }
}

// ================= mma.sync flash attention =================
// V stored ROW-MAJOR [key][hd]; PV B-frags via ldmatrix.trans.
#define ALD 72
#define APLANE (64*ALD*2)
#define ASMEM  (6*APLANE)

__global__ void __launch_bounds__(128)
attn_mma(const __nv_bfloat16* __restrict__ Ph, const __nv_bfloat16* __restrict__ Pl,
         __nv_bfloat16* __restrict__ Ohi, __nv_bfloat16* __restrict__ Olo) {
    extern __shared__ char asmr[];
    uint32_t sb = smem_u32(asmr);
    const uint32_t QH = sb, QL = sb + APLANE, KH = sb + 2*APLANE,
                   KL = sb + 3*APLANE, VH = sb + 4*APLANE, VL = sb + 5*APLANE;

    int tid = threadIdx.x, lane = tid & 31, w = tid >> 5;
    int gq = lane >> 3, rr = lane & 7;
    int bh = blockIdx.y;
    int b = bh / HH, h = bh % HH;
    int qt = blockIdx.x;
    float slope = exp2f(-0.5f * (float)(h + 1));

    int lrow = tid >> 4;          // 0..7
    int lcol = (tid & 15) * 4;    // 0..60

    #pragma unroll
    for (int pass = 0; pass < 8; pass++) {
        int row = lrow + pass * 8;
        size_t ga = (size_t)(b*SS + qt*64 + row) * QKVS + h*HD + lcol;
        uint32_t off = (row*ALD + lcol) * 2;
        CP8(QH + off, Ph + ga);
        CP8(QL + off, Pl + ga);
    }
    CP_COMMIT();
    CP_WAIT0();
    __syncthreads();

    uint32_t qh[4][4], ql[4][4];
    #pragma unroll
    for (int kk = 0; kk < 4; kk++) {
        uint32_t off = ((w*16 + (gq & 1)*8 + rr)*ALD + kk*16 + (gq >> 1)*8) * 2;
        LDSM4(qh[kk], QH + off);
        LDSM4(ql[kk], QL + off);
    }

    float m0r = -INFINITY, m1r = -INFINITY, l0s = 0.f, l1s = 0.f;
    float o[8][4] = {};
    int qg0 = qt*64 + w*16 + (lane >> 2);
    int qg1 = qg0 + 8;

    for (int kt = 0; kt <= qt; kt++) {
        __syncthreads();
        #pragma unroll
        for (int pass = 0; pass < 8; pass++) {
            int row = lrow + pass * 8;
            size_t gr = (size_t)(b*SS + kt*64 + row) * QKVS + h*HD + lcol;
            uint32_t off = (row*ALD + lcol) * 2;
            CP8(KH + off, Ph + gr + DD);
            CP8(KL + off, Pl + gr + DD);
            CP8(VH + off, Ph + gr + 2*DD);
            CP8(VL + off, Pl + gr + 2*DD);
        }
        CP_COMMIT();
        CP_WAIT0();
        __syncthreads();

        float s[8][4] = {};
        #pragma unroll
        for (int kk = 0; kk < 4; kk++) {
            #pragma unroll
            for (int np = 0; np < 4; np++) {
                uint32_t kb[4], kl2[4];
                uint32_t off = ((np*16 + (gq >> 1)*8 + rr)*ALD + kk*16 + (gq & 1)*8) * 2;
                LDSM4(kb, KH + off);
                LDSM4(kl2, KL + off);
                MMA16816(s[np*2],   qh[kk], kb[0], kb[1]);
                MMA16816(s[np*2],   ql[kk], kb[0], kb[1]);
                MMA16816(s[np*2],   qh[kk], kl2[0], kl2[1]);
                MMA16816(s[np*2+1], qh[kk], kb[2], kb[3]);
                MMA16816(s[np*2+1], ql[kk], kb[2], kb[3]);
                MMA16816(s[np*2+1], qh[kk], kl2[2], kl2[3]);
            }
        }

        #pragma unroll
        for (int nf = 0; nf < 8; nf++) {
            #pragma unroll
            for (int c = 0; c < 2; c++) {
                int kg = kt*64 + nf*8 + (lane & 3)*2 + c;
                float sv0 = s[nf][c]   * 0.125f;
                float sv1 = s[nf][2+c] * 0.125f;
                s[nf][c]   = (kg <= qg0) ? sv0 + slope*(float)(kg - qg0) : -1e30f;
                s[nf][2+c] = (kg <= qg1) ? sv1 + slope*(float)(kg - qg1) : -1e30f;
            }
        }

        float mx0 = -1e30f, mx1 = -1e30f;
        #pragma unroll
        for (int nf = 0; nf < 8; nf++) {
            mx0 = fmaxf(mx0, fmaxf(s[nf][0], s[nf][1]));
            mx1 = fmaxf(mx1, fmaxf(s[nf][2], s[nf][3]));
        }
        #pragma unroll
        for (int off = 1; off <= 2; off <<= 1) {
            mx0 = fmaxf(mx0, __shfl_xor_sync(0xffffffffu, mx0, off));
            mx1 = fmaxf(mx1, __shfl_xor_sync(0xffffffffu, mx1, off));
        }
        float mn0 = fmaxf(m0r, mx0), mn1 = fmaxf(m1r, mx1);
        float al0 = __expf(m0r - mn0), al1 = __expf(m1r - mn1);
        float rs0 = 0.f, rs1 = 0.f;
        #pragma unroll
        for (int nf = 0; nf < 8; nf++) {
            s[nf][0] = __expf(s[nf][0] - mn0);
            s[nf][1] = __expf(s[nf][1] - mn0);
            s[nf][2] = __expf(s[nf][2] - mn1);
            s[nf][3] = __expf(s[nf][3] - mn1);
            rs0 += s[nf][0] + s[nf][1];
            rs1 += s[nf][2] + s[nf][3];
        }
        #pragma unroll
        for (int off = 1; off <= 2; off <<= 1) {
            rs0 += __shfl_xor_sync(0xffffffffu, rs0, off);
            rs1 += __shfl_xor_sync(0xffffffffu, rs1, off);
        }
        l0s = l0s * al0 + rs0;
        l1s = l1s * al1 + rs1;
        m0r = mn0; m1r = mn1;

        #pragma unroll
        for (int nf = 0; nf < 8; nf++) {
            o[nf][0] *= al0; o[nf][1] *= al0;
            o[nf][2] *= al1; o[nf][3] *= al1;
        }

        #pragma unroll
        for (int kk = 0; kk < 4; kk++) {
            uint32_t Ah[4], Al2[4];
            #pragma unroll
            for (int half = 0; half < 2; half++) {
                float* sv = s[2*kk + half];
                __nv_bfloat162 h01 = __floats2bfloat162_rn(sv[0], sv[1]);
                __nv_bfloat162 h23 = __floats2bfloat162_rn(sv[2], sv[3]);
                __nv_bfloat162 L01 = __floats2bfloat162_rn(
                    sv[0] - __bfloat162float(__low2bfloat16(h01)),
                    sv[1] - __bfloat162float(__high2bfloat16(h01)));
                __nv_bfloat162 L23 = __floats2bfloat162_rn(
                    sv[2] - __bfloat162float(__low2bfloat16(h23)),
                    sv[3] - __bfloat162float(__high2bfloat16(h23)));
                Ah[half*2 + 0] = *(uint32_t*)&h01;
                Ah[half*2 + 1] = *(uint32_t*)&h23;
                Al2[half*2 + 0] = *(uint32_t*)&L01;
                Al2[half*2 + 1] = *(uint32_t*)&L23;
            }
            #pragma unroll
            for (int np = 0; np < 4; np++) {
                uint32_t vb[4], vl2[4];
                uint32_t off = ((kk*16 + (gq & 1)*8 + rr)*ALD + np*16 + (gq >> 1)*8) * 2;
                LDSM4T(vb, VH + off);
                LDSM4T(vl2, VL + off);
                MMA16816(o[np*2],   Ah,  vb[0], vb[1]);
                MMA16816(o[np*2],   Al2, vb[0], vb[1]);
                MMA16816(o[np*2],   Ah,  vl2[0], vl2[1]);
                MMA16816(o[np*2+1], Ah,  vb[2], vb[3]);
                MMA16816(o[np*2+1], Al2, vb[2], vb[3]);
                MMA16816(o[np*2+1], Ah,  vl2[2], vl2[3]);
            }
        }
    }

    float inv0 = 1.f / l0s, inv1 = 1.f / l1s;
    int row0 = b*SS + qt*64 + w*16 + (lane >> 2);
    int colb = h*HD + (lane & 3)*2;
    #pragma unroll
    for (int nf = 0; nf < 8; nf++) {
        float v0 = o[nf][0]*inv0, v1 = o[nf][1]*inv0;
        float v2 = o[nf][2]*inv1, v3 = o[nf][3]*inv1;
        size_t a0 = (size_t)row0 * DD + colb + nf*8;
        size_t a1 = (size_t)(row0 + 8) * DD + colb + nf*8;
        __nv_bfloat16 h0,h1,h2,h3,L0,L1,L2,L3;
        split1(v0, h0, L0); split1(v1, h1, L1);
        split1(v2, h2, L2); split1(v3, h3, L3);
        *(__nv_bfloat162*)(Ohi + a0) = __halves2bfloat162(h0, h1);
        *(__nv_bfloat162*)(Olo + a0) = __halves2bfloat162(L0, L1);
        *(__nv_bfloat162*)(Ohi + a1) = __halves2bfloat162(h2, h3);
        *(__nv_bfloat162*)(Olo + a1) = __halves2bfloat162(L2, L3);
    }
}

// ---------------- embedding lookup ----------------
__global__ void embed_kernel(const int* __restrict__ tokens,
                             const float* __restrict__ emb,
                             float* __restrict__ x) {
    int row = blockIdx.x;
    int tok = tokens[row];
    const float4* src = (const float4*)(emb + (size_t)tok * DD);
    float4* dst = (float4*)(x + (size_t)row * DD);
    for (int i = threadIdx.x; i < DD/4; i += blockDim.x) dst[i] = src[i];
}

// ---------------- layernorm -> bf16 hi/lo planes ----------------
__global__ void ln_kernel(const float* __restrict__ x,
                          const float* __restrict__ gw,
                          const float* __restrict__ bw,
                          __nv_bfloat16* __restrict__ hi,
                          __nv_bfloat16* __restrict__ lo) {
    int row = blockIdx.x;
    const float* xr = x + (size_t)row * DD;
    float s = 0.f, s2 = 0.f;
    for (int i = threadIdx.x; i < DD; i += 256) {
        float v = xr[i];
        s += v;
        s2 = fmaf(v, v, s2);
    }
    __shared__ float rs[8], rs2[8];
    #pragma unroll
    for (int o = 16; o > 0; o >>= 1) {
        s  += __shfl_down_sync(0xffffffffu, s,  o);
        s2 += __shfl_down_sync(0xffffffffu, s2, o);
    }
    int w = threadIdx.x >> 5;
    if ((threadIdx.x & 31) == 0) { rs[w] = s; rs2[w] = s2; }
    __syncthreads();
    __shared__ float mean_s, rstd_s;
    if (threadIdx.x == 0) {
        float ts = 0.f, ts2 = 0.f;
        #pragma unroll
        for (int i = 0; i < 8; i++) { ts += rs[i]; ts2 += rs2[i]; }
        float m = ts / (float)DD;
        float var = ts2 / (float)DD - m * m;
        mean_s = m;
        rstd_s = rsqrtf(var + 1e-5f);
    }
    __syncthreads();
    float m = mean_s, r = rstd_s;
    __nv_bfloat16* hrow = hi + (size_t)row * DD;
    __nv_bfloat16* lrow = lo + (size_t)row * DD;
    for (int i = threadIdx.x; i < DD; i += 256) {
        float v = (xr[i] - m) * r * gw[i] + bw[i];
        __nv_bfloat16 vh, vl;
        split1(v, vh, vl);
        hrow[i] = vh;
        lrow[i] = vl;
    }
}

// ---------------- final layernorm -> fp16 single plane ----------------
__global__ void ln_h(const float* __restrict__ x,
                     const float* __restrict__ gw,
                     const float* __restrict__ bw,
                     __half* __restrict__ out) {
    int row = blockIdx.x;
    const float* xr = x + (size_t)row * DD;
    float s = 0.f, s2 = 0.f;
    for (int i = threadIdx.x; i < DD; i += 256) {
        float v = xr[i];
        s += v;
        s2 = fmaf(v, v, s2);
    }
    __shared__ float rs[8], rs2[8];
    #pragma unroll
    for (int o = 16; o > 0; o >>= 1) {
        s  += __shfl_down_sync(0xffffffffu, s,  o);
        s2 += __shfl_down_sync(0xffffffffu, s2, o);
    }
    int w = threadIdx.x >> 5;
    if ((threadIdx.x & 31) == 0) { rs[w] = s; rs2[w] = s2; }
    __syncthreads();
    __shared__ float mean_s, rstd_s;
    if (threadIdx.x == 0) {
        float ts = 0.f, ts2 = 0.f;
        #pragma unroll
        for (int i = 0; i < 8; i++) { ts += rs[i]; ts2 += rs2[i]; }
        float m = ts / (float)DD;
        float var = ts2 / (float)DD - m * m;
        mean_s = m;
        rstd_s = rsqrtf(var + 1e-5f);
    }
    __syncthreads();
    float m = mean_s, r = rstd_s;
    __half* orow = out + (size_t)row * DD;
    for (int i = threadIdx.x; i < DD; i += 256) {
        float v = (xr[i] - m) * r * gw[i] + bw[i];
        orow[i] = __float2half(v);
    }
}

// ---------------- SwiGLU from packed ff planes -> bf16 hi/lo --------------
__global__ void swiglu_kernel(const __nv_bfloat16* __restrict__ fh,
                              const __nv_bfloat16* __restrict__ fl,
                              __nv_bfloat16* __restrict__ hi,
                              __nv_bfloat16* __restrict__ lo) {
    int i = blockIdx.x * 256 + threadIdx.x;   // over MM*DD/4 quads
    int row = i / (DD/4);
    int c4 = (i % (DD/4)) * 4;
    size_t fa = (size_t)row * FFS + c4;
    ushort4 ah4 = *(const ushort4*)(fh + fa);
    ushort4 al4 = *(const ushort4*)(fl + fa);
    ushort4 ch4 = *(const ushort4*)(fh + fa + DD);
    ushort4 cl4 = *(const ushort4*)(fl + fa + DD);
    float x0 = __bfloat162float(__ushort_as_bfloat16(ah4.x)) + __bfloat162float(__ushort_as_bfloat16(al4.x));
    float x1 = __bfloat162float(__ushort_as_bfloat16(ah4.y)) + __bfloat162float(__ushort_as_bfloat16(al4.y));
    float x2 = __bfloat162float(__ushort_as_bfloat16(ah4.z)) + __bfloat162float(__ushort_as_bfloat16(al4.z));
    float x3 = __bfloat162float(__ushort_as_bfloat16(ah4.w)) + __bfloat162float(__ushort_as_bfloat16(al4.w));
    float c0 = __bfloat162float(__ushort_as_bfloat16(ch4.x)) + __bfloat162float(__ushort_as_bfloat16(cl4.x));
    float c1 = __bfloat162float(__ushort_as_bfloat16(ch4.y)) + __bfloat162float(__ushort_as_bfloat16(cl4.y));
    float c2 = __bfloat162float(__ushort_as_bfloat16(ch4.z)) + __bfloat162float(__ushort_as_bfloat16(cl4.z));
    float c3 = __bfloat162float(__ushort_as_bfloat16(ch4.w)) + __bfloat162float(__ushort_as_bfloat16(cl4.w));
    float r0 = x0 / (1.f + __expf(-x0)) * c0;
    float r1 = x1 / (1.f + __expf(-x1)) * c1;
    float r2 = x2 / (1.f + __expf(-x2)) * c2;
    float r3 = x3 / (1.f + __expf(-x3)) * c3;
    __nv_bfloat16 h0,h1,h2,h3,l0,l1,l2,l3;
    split1(r0, h0, l0); split1(r1, h1, l1);
    split1(r2, h2, l2); split1(r3, h3, l3);
    size_t oa = (size_t)row * DD + c4;
    *(ushort4*)(hi + oa) = make_ushort4(__bfloat16_as_ushort(h0), __bfloat16_as_ushort(h1),
                                        __bfloat16_as_ushort(h2), __bfloat16_as_ushort(h3));
    *(ushort4*)(lo + oa) = make_ushort4(__bfloat16_as_ushort(l0), __bfloat16_as_ushort(l1),
                                        __bfloat16_as_ushort(l2), __bfloat16_as_ushort(l3));
}

// ---------------- launch ----------------
extern "C" void kernel_launch(void* const* d_in, const int* in_sizes, int n_in,
                              void* d_out, int out_size) {
    const int*   tokens = (const int*)d_in[0];
    const float* emb    = (const float*)d_in[1];
    const float* wq     = (const float*)d_in[2];
    const float* wk     = (const float*)d_in[3];
    const float* wv     = (const float*)d_in[4];
    const float* wo     = (const float*)d_in[5];
    const float* ln1_g  = (const float*)d_in[6];
    const float* ln1_b  = (const float*)d_in[7];
    const float* ln2_g  = (const float*)d_in[8];
    const float* ln2_b  = (const float*)d_in[9];
    const float* w1     = (const float*)d_in[10];
    const float* w2     = (const float*)d_in[11];
    const float* w3     = (const float*)d_in[12];
    const float* lnf_g  = (const float*)d_in[13];
    const float* lnf_b  = (const float*)d_in[14];
    const float* w_out  = (const float*)d_in[15];
    float* out = (float*)d_out;

    float* px;
    cudaGetSymbolAddress((void**)&px, g_x);
    __nv_bfloat16 *whi, *wlo, *ahi, *alo, *qkvh, *qkvl, *ffh, *ffl;
    cudaGetSymbolAddress((void**)&whi, g_whi);
    cudaGetSymbolAddress((void**)&wlo, g_wlo);
    cudaGetSymbolAddress((void**)&ahi, g_ahi);
    cudaGetSymbolAddress((void**)&alo, g_alo);
    cudaGetSymbolAddress((void**)&qkvh, g_qkvh);
    cudaGetSymbolAddress((void**)&qkvl, g_qkvl);
    cudaGetSymbolAddress((void**)&ffh, g_ffh);
    cudaGetSymbolAddress((void**)&ffl, g_ffl);

    cudaFuncSetAttribute(attn_mma,
                         cudaFuncAttributeMaxDynamicSharedMemorySize, ASMEM);
    cudaFuncSetAttribute(gemm_mma<false,true>,
                         cudaFuncAttributeMaxDynamicSharedMemorySize, GSMEM);
    cudaFuncSetAttribute(gemm_mma<true,false>,
                         cudaFuncAttributeMaxDynamicSharedMemorySize, GSMEM);
    cudaFuncSetAttribute(gemm_f16,
                         cudaFuncAttributeMaxDynamicSharedMemorySize, HGSMEM);

    // ---- convert weights: bf16 hi/lo planes (layers), fp16 plane (logits) ----
    {
        int n4 = WMAT / 4;
        for (int l = 0; l < LL; l++) {
            size_t so = (size_t)l * WMAT;
            size_t qo = QKV_OFF + (size_t)l * 3 * WMAT;
            conv_split<<<n4/256, 256>>>(wq + so, whi + qo,          wlo + qo,          n4);
            conv_split<<<n4/256, 256>>>(wk + so, whi + qo + WMAT,   wlo + qo + WMAT,   n4);
            conv_split<<<n4/256, 256>>>(wv + so, whi + qo + 2*WMAT, wlo + qo + 2*WMAT, n4);
            size_t fo = W13_OFF + (size_t)l * 2 * WMAT;
            conv_split<<<n4/256, 256>>>(w1 + so, whi + fo,          wlo + fo,          n4);
            conv_split<<<n4/256, 256>>>(w3 + so, whi + fo + WMAT,   wlo + fo + WMAT,   n4);
        }
        int n4L = (LL * WMAT) / 4;
        conv_split<<<n4L/256, 256>>>(wo, whi + WO_OFF, wlo + WO_OFF, n4L);
        conv_split<<<n4L/256, 256>>>(w2, whi + W2_OFF, wlo + W2_OFF, n4L);
        int n4o = (VV * DD) / 4;
        conv_h<<<n4o/256, 256>>>(w_out, (__half*)(whi + WOUT_OFF), n4o);
    }

    embed_kernel<<<MM, 256>>>(tokens, emb, px);

    dim3 gQKV(QKVS/128, MM/128);
    dim3 gD(DD/128, MM/128);
    dim3 gFF(FFS/128, MM/128);
    for (int l = 0; l < LL; l++) {
        size_t qo = QKV_OFF + (size_t)l * 3 * WMAT;
        size_t oo = WO_OFF + (size_t)l * WMAT;
        size_t fo = W13_OFF + (size_t)l * 2 * WMAT;
        size_t to = W2_OFF + (size_t)l * WMAT;

        // attention
        ln_kernel<<<MM, 256>>>(px, ln1_g + l*DD, ln1_b + l*DD, ahi, alo);
        gemm_mma<false,true><<<gQKV, 256, GSMEM>>>(ahi, alo, whi + qo, wlo + qo,
                                                   nullptr, nullptr, qkvh, qkvl, QKVS, DD);
        attn_mma<<<dim3(SS/64, BB*HH), 128, ASMEM>>>(qkvh, qkvl, ahi, alo);
        gemm_mma<true,false><<<gD, 256, GSMEM>>>(ahi, alo, whi + oo, wlo + oo,
                                                 px, px, nullptr, nullptr, DD, DD);

        // SwiGLU FFN
        ln_kernel<<<MM, 256>>>(px, ln2_g + l*DD, ln2_b + l*DD, ahi, alo);
        gemm_mma<false,true><<<gFF, 256, GSMEM>>>(ahi, alo, whi + fo, wlo + fo,
                                                  nullptr, nullptr, ffh, ffl, FFS, DD);
        swiglu_kernel<<<(MM*DD/4)/256, 256>>>(ffh, ffl, ahi, alo);
        gemm_mma<true,false><<<gD, 256, GSMEM>>>(ahi, alo, whi + to, wlo + to,
                                                 px, px, nullptr, nullptr, DD, DD);
    }

    // final LN (fp16) + plain-fp16 logits GEMM
    ln_h<<<MM, 256>>>(px, lnf_g, lnf_b, (__half*)ahi);
    gemm_f16<<<dim3(VV/128, MM/128), 256, HGSMEM>>>(
        (const __half*)ahi, (const __half*)(whi + WOUT_OFF), out, VV, DD);
}

// round 14
// speedup vs baseline: 2.8136x; 1.0809x over previous
#include <cuda_runtime.h>
#include <cuda_bf16.h>
#include <cuda_fp16.h>
#include <math.h>
#include <stdint.h>

// ---------------- problem constants ----------------
#define BB 2
#define SS 2048
#define DD 1024
#define HH 16
#define HD 64
#define LL 8
#define VV 32000
#define MM (BB*SS)          // 4096 rows
#define QKVS (3*DD)
#define FFS  (2*DD)

// ---------------- weight plane offsets ----------------
#define WMAT (DD*DD)
#define QKV_OFF 0                       // bf16 hi/lo, layer stride 3*WMAT
#define WO_OFF  (3*LL*WMAT)             // bf16 hi/lo
#define W13_OFF (4*LL*WMAT)             // fp16 single plane, layer stride 2*WMAT
#define W2_OFF  (6*LL*WMAT)             // fp16 single plane
#define WOUT_OFF (7*LL*WMAT)            // fp16 single plane
#define WTOT (WOUT_OFF + (size_t)VV*DD)

// ---------------- scratch (device globals) ----------
__device__ float g_x[MM*DD];
__device__ float g_ff32[MM*FFS];
__device__ __nv_bfloat16 g_whi[WTOT];
__device__ __nv_bfloat16 g_wlo[WTOT];
__device__ __nv_bfloat16 g_ahi[MM*DD];
__device__ __nv_bfloat16 g_alo[MM*DD];
__device__ __nv_bfloat16 g_qkvh[MM*QKVS];
__device__ __nv_bfloat16 g_qkvl[MM*QKVS];

// ================= helpers =================
__device__ __forceinline__ uint32_t smem_u32(const void* p) {
    uint32_t a;
    asm("{ .reg .u64 t; cvta.to.shared.u64 t, %1; cvt.u32.u64 %0, t; }"
        : "=r"(a) : "l"(p));
    return a;
}
#define CP16(dst, src) \
    asm volatile("cp.async.cg.shared.global [%0], [%1], 16;" :: "r"(dst), "l"(src))
#define CP8(dst, src) \
    asm volatile("cp.async.ca.shared.global [%0], [%1], 8;" :: "r"(dst), "l"(src))
#define CP_COMMIT() asm volatile("cp.async.commit_group;" ::: "memory")
#define CP_WAIT1()  asm volatile("cp.async.wait_group 1;" ::: "memory")
#define CP_WAIT0()  asm volatile("cp.async.wait_group 0;" ::: "memory")
#define LDSM4(r, addr) \
    asm volatile("ldmatrix.sync.aligned.m8n8.x4.shared.b16 {%0,%1,%2,%3}, [%4];" \
        : "=r"((r)[0]), "=r"((r)[1]), "=r"((r)[2]), "=r"((r)[3]) : "r"(addr))
#define LDSM4T(r, addr) \
    asm volatile("ldmatrix.sync.aligned.m8n8.x4.trans.shared.b16 {%0,%1,%2,%3}, [%4];" \
        : "=r"((r)[0]), "=r"((r)[1]), "=r"((r)[2]), "=r"((r)[3]) : "r"(addr))
#define MMA16816(c, a, b0v, b1v) \
    asm volatile("mma.sync.aligned.m16n8k16.row.col.f32.bf16.bf16.f32 " \
        "{%0,%1,%2,%3}, {%4,%5,%6,%7}, {%8,%9}, {%0,%1,%2,%3};" \
        : "+f"((c)[0]), "+f"((c)[1]), "+f"((c)[2]), "+f"((c)[3]) \
        : "r"((a)[0]), "r"((a)[1]), "r"((a)[2]), "r"((a)[3]), "r"(b0v), "r"(b1v))
#define MMAH(c, a, b0v, b1v) \
    asm volatile("mma.sync.aligned.m16n8k16.row.col.f32.f16.f16.f32 " \
        "{%0,%1,%2,%3}, {%4,%5,%6,%7}, {%8,%9}, {%0,%1,%2,%3};" \
        : "+f"((c)[0]), "+f"((c)[1]), "+f"((c)[2]), "+f"((c)[3]) \
        : "r"((a)[0]), "r"((a)[1]), "r"((a)[2]), "r"((a)[3]), "r"(b0v), "r"(b1v))

__device__ __forceinline__ void split1(float x, __nv_bfloat16& h, __nv_bfloat16& l) {
    h = __float2bfloat16(x);
    l = __float2bfloat16(x - __bfloat162float(h));
}
__device__ __forceinline__ void split1h(float x, __half& h, __half& l) {
    h = __float2half(x);
    l = __float2half(x - __half2float(h));
}

// ---------------- fp32 -> (hi, lo) bf16 split (weights), 4-way ILP --------
__global__ void conv_split(const float* __restrict__ src,
                           __nv_bfloat16* __restrict__ hi,
                           __nv_bfloat16* __restrict__ lo, int n4) {
    int i0 = blockIdx.x * 1024 + threadIdx.x;
    #pragma unroll
    for (int k = 0; k < 4; k++) {
        int i = i0 + k * 256;
        if (i >= n4) return;
        float4 v = ((const float4*)src)[i];
        __nv_bfloat16 h0, h1, h2, h3, l0, l1, l2, l3;
        split1(v.x, h0, l0); split1(v.y, h1, l1);
        split1(v.z, h2, l2); split1(v.w, h3, l3);
        ((ushort4*)hi)[i] = make_ushort4(__bfloat16_as_ushort(h0), __bfloat16_as_ushort(h1),
                                         __bfloat16_as_ushort(h2), __bfloat16_as_ushort(h3));
        ((ushort4*)lo)[i] = make_ushort4(__bfloat16_as_ushort(l0), __bfloat16_as_ushort(l1),
                                         __bfloat16_as_ushort(l2), __bfloat16_as_ushort(l3));
    }
}

// ---------------- fp32 -> fp16 plane (weights), 4-way ILP ----------------
__global__ void conv_h(const float* __restrict__ src, __half* __restrict__ dst, int n4) {
    int i0 = blockIdx.x * 1024 + threadIdx.x;
    #pragma unroll
    for (int k = 0; k < 4; k++) {
        int i = i0 + k * 256;
        if (i >= n4) return;
        float4 v = ((const float4*)src)[i];
        __half2 a = __floats2half2_rn(v.x, v.y);
        __half2 b = __floats2half2_rn(v.z, v.w);
        ((uint2*)dst)[i] = make_uint2(*(uint32_t*)&a, *(uint32_t*)&b);
    }
}

// ================= mma.sync split-bf16 GEMM (QKV / WO) =====================
#define PLANE_B 10240
#define STAGE_B (4*PLANE_B)
#define GSMEM   (2*STAGE_B)

template<bool RESID, bool SPLITOUT>
__global__ void __launch_bounds__(256, 2)
gemm_mma(const __nv_bfloat16* __restrict__ Ahi, const __nv_bfloat16* __restrict__ Alo,
         const __nv_bfloat16* __restrict__ Bhi, const __nv_bfloat16* __restrict__ Blo,
         const float* __restrict__ R, float* __restrict__ C,
         __nv_bfloat16* __restrict__ Chi, __nv_bfloat16* __restrict__ Clo,
         int N, int K) {
    extern __shared__ char sm_raw[];
    uint32_t sb = smem_u32(sm_raw);
    int tid = threadIdx.x, lane = tid & 31, wid = tid >> 5;
    int wm = wid & 3, wn = wid >> 2;
    int m0 = blockIdx.y * 128, n0 = blockIdx.x * 128;

    int prow = tid >> 1;
    int pc   = (tid & 1) * 2;
    const __nv_bfloat16* srcs[4] = {Ahi, Alo, Bhi, Blo};
    int nslab = K / 32;

    {
        #pragma unroll
        for (int p = 0; p < 4; p++) {
            int rb = (p < 2) ? m0 : n0;
            const __nv_bfloat16* g = srcs[p] + (size_t)(rb + prow) * K + pc * 8;
            uint32_t d = sb + p * PLANE_B + prow * 80 + pc * 16;
            CP16(d, g);
            CP16(d + 16, g + 8);
        }
        CP_COMMIT();
    }

    float acc[2][8][4] = {};
    int gq = lane >> 3, rr = lane & 7;

    for (int s = 0; s < nslab; s++) {
        if (s + 1 < nslab) {
            uint32_t stb = sb + ((s + 1) & 1) * STAGE_B;
            int k0 = (s + 1) * 32;
            #pragma unroll
            for (int p = 0; p < 4; p++) {
                int rb = (p < 2) ? m0 : n0;
                const __nv_bfloat16* g = srcs[p] + (size_t)(rb + prow) * K + k0 + pc * 8;
                uint32_t d = stb + p * PLANE_B + prow * 80 + pc * 16;
                CP16(d, g);
                CP16(d + 16, g + 8);
            }
            CP_COMMIT();
            CP_WAIT1();
        } else {
            CP_WAIT0();
        }
        __syncthreads();

        uint32_t stb = sb + (s & 1) * STAGE_B;
        #pragma unroll
        for (int ks = 0; ks < 2; ks++) {
            uint32_t ah[2][4], al[2][4];
            #pragma unroll
            for (int mf = 0; mf < 2; mf++) {
                int row = wm * 32 + mf * 16 + (gq & 1) * 8 + rr;
                int col = ks * 16 + (gq >> 1) * 8;
                uint32_t a = stb + row * 80 + col * 2;
                LDSM4(ah[mf], a);
                LDSM4(al[mf], a + PLANE_B);
            }
            #pragma unroll
            for (int np = 0; np < 4; np++) {
                uint32_t bh[4], bl[4];
                int row = wn * 64 + np * 16 + (gq >> 1) * 8 + rr;
                int col = ks * 16 + (gq & 1) * 8;
                uint32_t a = stb + 2 * PLANE_B + row * 80 + col * 2;
                LDSM4(bh, a);
                LDSM4(bl, a + PLANE_B);
                #pragma unroll
                for (int mf = 0; mf < 2; mf++) {
                    MMA16816(acc[mf][np*2],   ah[mf], bh[0], bh[1]);
                    MMA16816(acc[mf][np*2],   al[mf], bh[0], bh[1]);
                    MMA16816(acc[mf][np*2],   ah[mf], bl[0], bl[1]);
                    MMA16816(acc[mf][np*2+1], ah[mf], bh[2], bh[3]);
                    MMA16816(acc[mf][np*2+1], al[mf], bh[2], bh[3]);
                    MMA16816(acc[mf][np*2+1], ah[mf], bl[2], bl[3]);
                }
            }
        }
        __syncthreads();
    }

    int rbase = m0 + wm * 32 + (lane >> 2);
    int cbase = n0 + wn * 64 + (lane & 3) * 2;
    #pragma unroll
    for (int mf = 0; mf < 2; mf++) {
        #pragma unroll
        for (int nf = 0; nf < 8; nf++) {
            int row = rbase + mf * 16;
            int col = cbase + nf * 8;
            float v0 = acc[mf][nf][0], v1 = acc[mf][nf][1];
            float v2 = acc[mf][nf][2], v3 = acc[mf][nf][3];
            size_t a0 = (size_t)row * N + col;
            size_t a1 = (size_t)(row + 8) * N + col;
            if (SPLITOUT) {
                __nv_bfloat16 h0,h1,h2,h3,L0,L1,L2,L3;
                split1(v0, h0, L0); split1(v1, h1, L1);
                split1(v2, h2, L2); split1(v3, h3, L3);
                *(__nv_bfloat162*)(Chi + a0) = __halves2bfloat162(h0, h1);
                *(__nv_bfloat162*)(Clo + a0) = __halves2bfloat162(L0, L1);
                *(__nv_bfloat162*)(Chi + a1) = __halves2bfloat162(h2, h3);
                *(__nv_bfloat162*)(Clo + a1) = __halves2bfloat162(L2, L3);
            } else {
                if (RESID) {
                    float2 r0 = *(const float2*)(R + a0);
                    float2 r1 = *(const float2*)(R + a1);
                    v0 += r0.x; v1 += r0.y; v2 += r1.x; v3 += r1.y;
                }
                *(float2*)(C + a0) = make_float2(v0, v1);
                *(float2*)(C + a1) = make_float2(v2, v3);
            }
        }
    }
}

// ================= 2-term fp16 GEMM (FFN): D = (Ah+Al) @ Bq^T ==============
// A fp16 hi/lo planes (22-bit), B single fp16 plane. 3 smem planes, 2 MMAs
// per fragment pair. Same tiling: 128x128, BK=32, 256 thr, occ 2.
#define H2STAGE (3*PLANE_B)
#define H2SMEM  (2*H2STAGE)

template<bool RESID>
__global__ void __launch_bounds__(256, 2)
gemm_h2(const __half* __restrict__ Ahi, const __half* __restrict__ Alo,
        const __half* __restrict__ B,
        const float* __restrict__ R, float* __restrict__ C, int N, int K) {
    extern __shared__ char sm_raw[];
    uint32_t sb = smem_u32(sm_raw);
    int tid = threadIdx.x, lane = tid & 31, wid = tid >> 5;
    int wm = wid & 3, wn = wid >> 2;
    int m0 = blockIdx.y * 128, n0 = blockIdx.x * 128;

    int prow = tid >> 1;
    int pc   = (tid & 1) * 2;
    const __half* srcs[3] = {Ahi, Alo, B};
    int nslab = K / 32;

    {
        #pragma unroll
        for (int p = 0; p < 3; p++) {
            int rb = (p < 2) ? m0 : n0;
            const __half* g = srcs[p] + (size_t)(rb + prow) * K + pc * 8;
            uint32_t d = sb + p * PLANE_B + prow * 80 + pc * 16;
            CP16(d, g);
            CP16(d + 16, g + 8);
        }
        CP_COMMIT();
    }

    float acc[2][8][4] = {};
    int gq = lane >> 3, rr = lane & 7;

    for (int s = 0; s < nslab; s++) {
        if (s + 1 < nslab) {
            uint32_t stb = sb + ((s + 1) & 1) * H2STAGE;
            int k0 = (s + 1) * 32;
            #pragma unroll
            for (int p = 0; p < 3; p++) {
                int rb = (p < 2) ? m0 : n0;
                const __half* g = srcs[p] + (size_t)(rb + prow) * K + k0 + pc * 8;
                uint32_t d = stb + p * PLANE_B + prow * 80 + pc * 16;
                CP16(d, g);
                CP16(d + 16, g + 8);
            }
            CP_COMMIT();
            CP_WAIT1();
        } else {
            CP_WAIT0();
        }
        __syncthreads();

        uint32_t stb = sb + (s & 1) * H2STAGE;
        #pragma unroll
        for (int ks = 0; ks < 2; ks++) {
            uint32_t ah[2][4], al[2][4];
            #pragma unroll
            for (int mf = 0; mf < 2; mf++) {
                int row = wm * 32 + mf * 16 + (gq & 1) * 8 + rr;
                int col = ks * 16 + (gq >> 1) * 8;
                uint32_t a = stb + row * 80 + col * 2;
                LDSM4(ah[mf], a);
                LDSM4(al[mf], a + PLANE_B);
            }
            #pragma unroll
            for (int np = 0; np < 4; np++) {
                uint32_t bh[4];
                int row = wn * 64 + np * 16 + (gq >> 1) * 8 + rr;
                int col = ks * 16 + (gq & 1) * 8;
                LDSM4(bh, stb + 2 * PLANE_B + row * 80 + col * 2);
                #pragma unroll
                for (int mf = 0; mf < 2; mf++) {
                    MMAH(acc[mf][np*2],   ah[mf], bh[0], bh[1]);
                    MMAH(acc[mf][np*2],   al[mf], bh[0], bh[1]);
                    MMAH(acc[mf][np*2+1], ah[mf], bh[2], bh[3]);
                    MMAH(acc[mf][np*2+1], al[mf], bh[2], bh[3]);
                }
            }
        }
        __syncthreads();
    }

    int rbase = m0 + wm * 32 + (lane >> 2);
    int cbase = n0 + wn * 64 + (lane & 3) * 2;
    #pragma unroll
    for (int mf = 0; mf < 2; mf++) {
        #pragma unroll
        for (int nf = 0; nf < 8; nf++) {
            int row = rbase + mf * 16;
            int col = cbase + nf * 8;
            float v0 = acc[mf][nf][0], v1 = acc[mf][nf][1];
            float v2 = acc[mf][nf][2], v3 = acc[mf][nf][3];
            size_t a0 = (size_t)row * N + col;
            size_t a1 = (size_t)(row + 8) * N + col;
            if (RESID) {
                float2 r0 = *(const float2*)(R + a0);
                float2 r1 = *(const float2*)(R + a1);
                v0 += r0.x; v1 += r0.y; v2 += r1.x; v3 += r1.y;
            }
            *(float2*)(C + a0) = make_float2(v0, v1);
            *(float2*)(C + a1) = make_float2(v2, v3);
        }
    }
}

// ================= plain fp16 GEMM (logits head) =================
#define HSTAGE (2*PLANE_B)
#define HGSMEM (2*HSTAGE)

__global__ void __launch_bounds__(256, 2)
gemm_f16(const __half* __restrict__ A, const __half* __restrict__ B,
         float* __restrict__ C, int N, int K) {
    extern __shared__ char sm_raw[];
    uint32_t sb = smem_u32(sm_raw);
    int tid = threadIdx.x, lane = tid & 31, wid = tid >> 5;
    int wm = wid & 3, wn = wid >> 2;
    int m0 = blockIdx.y * 128, n0 = blockIdx.x * 128;

    int prow = tid >> 1;
    int pc   = (tid & 1) * 2;
    const __half* srcs[2] = {A, B};
    int nslab = K / 32;

    {
        #pragma unroll
        for (int p = 0; p < 2; p++) {
            int rb = p ? n0 : m0;
            const __half* g = srcs[p] + (size_t)(rb + prow) * K + pc * 8;
            uint32_t d = sb + p * PLANE_B + prow * 80 + pc * 16;
            CP16(d, g);
            CP16(d + 16, g + 8);
        }
        CP_COMMIT();
    }

    float acc[2][8][4] = {};
    int gq = lane >> 3, rr = lane & 7;

    for (int s = 0; s < nslab; s++) {
        if (s + 1 < nslab) {
            uint32_t stb = sb + ((s + 1) & 1) * HSTAGE;
            int k0 = (s + 1) * 32;
            #pragma unroll
            for (int p = 0; p < 2; p++) {
                int rb = p ? n0 : m0;
                const __half* g = srcs[p] + (size_t)(rb + prow) * K + k0 + pc * 8;
                uint32_t d = stb + p * PLANE_B + prow * 80 + pc * 16;
                CP16(d, g);
                CP16(d + 16, g + 8);
            }
            CP_COMMIT();
            CP_WAIT1();
        } else {
            CP_WAIT0();
        }
        __syncthreads();

        uint32_t stb = sb + (s & 1) * HSTAGE;
        #pragma unroll
        for (int ks = 0; ks < 2; ks++) {
            uint32_t ah[2][4];
            #pragma unroll
            for (int mf = 0; mf < 2; mf++) {
                int row = wm * 32 + mf * 16 + (gq & 1) * 8 + rr;
                int col = ks * 16 + (gq >> 1) * 8;
                LDSM4(ah[mf], stb + row * 80 + col * 2);
            }
            #pragma unroll
            for (int np = 0; np < 4; np++) {
                uint32_t bh[4];
                int row = wn * 64 + np * 16 + (gq >> 1) * 8 + rr;
                int col = ks * 16 + (gq & 1) * 8;
                LDSM4(bh, stb + PLANE_B + row * 80 + col * 2);
                #pragma unroll
                for (int mf = 0; mf < 2; mf++) {
                    MMAH(acc[mf][np*2],   ah[mf], bh[0], bh[1]);
                    MMAH(acc[mf][np*2+1], ah[mf], bh[2], bh[3]);
                }
            }
        }
        __syncthreads();
    }

    int rbase = m0 + wm * 32 + (lane >> 2);
    int cbase = n0 + wn * 64 + (lane & 3) * 2;
    #pragma unroll
    for (int mf = 0; mf < 2; mf++) {
        #pragma unroll
        for (int nf = 0; nf < 8; nf++) {
            int row = rbase + mf * 16;
            int col = cbase + nf * 8;
            size_t a0 = (size_t)row * N + col;
            size_t a1 = (size_t)(row + 8) * N + col;
            *(float2*)(C + a0) = make_float2(acc[mf][nf][0], acc[mf][nf][1]);
            *(float2*)(C + a1) = make_float2(acc[mf][nf][2], acc[mf][nf][3]);
        }
    }
}

// ================= mma.sync flash attention (bf16 split planes) ============
#define ALD 72
#define APLANE (64*ALD*2)
#define ASMEM  (6*APLANE)

__global__ void __launch_bounds__(128)
attn_mma(const __nv_bfloat16* __restrict__ Ph, const __nv_bfloat16* __restrict__ Pl,
         __nv_bfloat16* __restrict__ Ohi, __nv_bfloat16* __restrict__ Olo) {
    extern __shared__ char asmr[];
    uint32_t sb = smem_u32(asmr);
    const uint32_t QH = sb, QL = sb + APLANE, KH = sb + 2*APLANE,
                   KL = sb + 3*APLANE, VH = sb + 4*APLANE, VL = sb + 5*APLANE;

    int tid = threadIdx.x, lane = tid & 31, w = tid >> 5;
    int gq = lane >> 3, rr = lane & 7;
    int bh = blockIdx.y;
    int b = bh / HH, h = bh % HH;
    int qt = blockIdx.x;
    float slope = exp2f(-0.5f * (float)(h + 1));

    int lrow = tid >> 4;
    int lcol = (tid & 15) * 4;

    #pragma unroll
    for (int pass = 0; pass < 8; pass++) {
        int row = lrow + pass * 8;
        size_t ga = (size_t)(b*SS + qt*64 + row) * QKVS + h*HD + lcol;
        uint32_t off = (row*ALD + lcol) * 2;
        CP8(QH + off, Ph + ga);
        CP8(QL + off, Pl + ga);
    }
    CP_COMMIT();
    CP_WAIT0();
    __syncthreads();

    uint32_t qh[4][4], ql[4][4];
    #pragma unroll
    for (int kk = 0; kk < 4; kk++) {
        uint32_t off = ((w*16 + (gq & 1)*8 + rr)*ALD + kk*16 + (gq >> 1)*8) * 2;
        LDSM4(qh[kk], QH + off);
        LDSM4(ql[kk], QL + off);
    }

    float m0r = -INFINITY, m1r = -INFINITY, l0s = 0.f, l1s = 0.f;
    float o[8][4] = {};
    int qg0 = qt*64 + w*16 + (lane >> 2);
    int qg1 = qg0 + 8;

    for (int kt = 0; kt <= qt; kt++) {
        __syncthreads();
        #pragma unroll
        for (int pass = 0; pass < 8; pass++) {
            int row = lrow + pass * 8;
            size_t gr = (size_t)(b*SS + kt*64 + row) * QKVS + h*HD + lcol;
            uint32_t off = (row*ALD + lcol) * 2;
            CP8(KH + off, Ph + gr + DD);
            CP8(KL + off, Pl + gr + DD);
            CP8(VH + off, Ph + gr + 2*DD);
            CP8(VL + off, Pl + gr + 2*DD);
        }
        CP_COMMIT();
        CP_WAIT0();
        __syncthreads();

        float s[8][4] = {};
        #pragma unroll
        for (int kk = 0; kk < 4; kk++) {
            #pragma unroll
            for (int np = 0; np < 4; np++) {
                uint32_t kb[4], kl2[4];
                uint32_t off = ((np*16 + (gq >> 1)*8 + rr)*ALD + kk*16 + (gq & 1)*8) * 2;
                LDSM4(kb, KH + off);
                LDSM4(kl2, KL + off);
                MMA16816(s[np*2],   qh[kk], kb[0], kb[1]);
                MMA16816(s[np*2],   ql[kk], kb[0], kb[1]);
                MMA16816(s[np*2],   qh[kk], kl2[0], kl2[1]);
                MMA16816(s[np*2+1], qh[kk], kb[2], kb[3]);
                MMA16816(s[np*2+1], ql[kk], kb[2], kb[3]);
                MMA16816(s[np*2+1], qh[kk], kl2[2], kl2[3]);
            }
        }

        #pragma unroll
        for (int nf = 0; nf < 8; nf++) {
            #pragma unroll
            for (int c = 0; c < 2; c++) {
                int kg = kt*64 + nf*8 + (lane & 3)*2 + c;
                float sv0 = s[nf][c]   * 0.125f;
                float sv1 = s[nf][2+c] * 0.125f;
                s[nf][c]   = (kg <= qg0) ? sv0 + slope*(float)(kg - qg0) : -1e30f;
                s[nf][2+c] = (kg <= qg1) ? sv1 + slope*(float)(kg - qg1) : -1e30f;
            }
        }

        float mx0 = -1e30f, mx1 = -1e30f;
        #pragma unroll
        for (int nf = 0; nf < 8; nf++) {
            mx0 = fmaxf(mx0, fmaxf(s[nf][0], s[nf][1]));
            mx1 = fmaxf(mx1, fmaxf(s[nf][2], s[nf][3]));
        }
        #pragma unroll
        for (int off = 1; off <= 2; off <<= 1) {
            mx0 = fmaxf(mx0, __shfl_xor_sync(0xffffffffu, mx0, off));
            mx1 = fmaxf(mx1, __shfl_xor_sync(0xffffffffu, mx1, off));
        }
        float mn0 = fmaxf(m0r, mx0), mn1 = fmaxf(m1r, mx1);
        float al0 = __expf(m0r - mn0), al1 = __expf(m1r - mn1);
        float rs0 = 0.f, rs1 = 0.f;
        #pragma unroll
        for (int nf = 0; nf < 8; nf++) {
            s[nf][0] = __expf(s[nf][0] - mn0);
            s[nf][1] = __expf(s[nf][1] - mn0);
            s[nf][2] = __expf(s[nf][2] - mn1);
            s[nf][3] = __expf(s[nf][3] - mn1);
            rs0 += s[nf][0] + s[nf][1];
            rs1 += s[nf][2] + s[nf][3];
        }
        #pragma unroll
        for (int off = 1; off <= 2; off <<= 1) {
            rs0 += __shfl_xor_sync(0xffffffffu, rs0, off);
            rs1 += __shfl_xor_sync(0xffffffffu, rs1, off);
        }
        l0s = l0s * al0 + rs0;
        l1s = l1s * al1 + rs1;
        m0r = mn0; m1r = mn1;

        #pragma unroll
        for (int nf = 0; nf < 8; nf++) {
            o[nf][0] *= al0; o[nf][1] *= al0;
            o[nf][2] *= al1; o[nf][3] *= al1;
        }

        #pragma unroll
        for (int kk = 0; kk < 4; kk++) {
            uint32_t Ah[4], Al2[4];
            #pragma unroll
            for (int half = 0; half < 2; half++) {
                float* sv = s[2*kk + half];
                __nv_bfloat162 h01 = __floats2bfloat162_rn(sv[0], sv[1]);
                __nv_bfloat162 h23 = __floats2bfloat162_rn(sv[2], sv[3]);
                __nv_bfloat162 L01 = __floats2bfloat162_rn(
                    sv[0] - __bfloat162float(__low2bfloat16(h01)),
                    sv[1] - __bfloat162float(__high2bfloat16(h01)));
                __nv_bfloat162 L23 = __floats2bfloat162_rn(
                    sv[2] - __bfloat162float(__low2bfloat16(h23)),
                    sv[3] - __bfloat162float(__high2bfloat16(h23)));
                Ah[half*2 + 0] = *(uint32_t*)&h01;
                Ah[half*2 + 1] = *(uint32_t*)&h23;
                Al2[half*2 + 0] = *(uint32_t*)&L01;
                Al2[half*2 + 1] = *(uint32_t*)&L23;
            }
            #pragma unroll
            for (int np = 0; np < 4; np++) {
                uint32_t vb[4], vl2[4];
                uint32_t off = ((kk*16 + (gq & 1)*8 + rr)*ALD + np*16 + (gq >> 1)*8) * 2;
                LDSM4T(vb, VH + off);
                LDSM4T(vl2, VL + off);
                MMA16816(o[np*2],   Ah,  vb[0], vb[1]);
                MMA16816(o[np*2],   Al2, vb[0], vb[1]);
                MMA16816(o[np*2],   Ah,  vl2[0], vl2[1]);
                MMA16816(o[np*2+1], Ah,  vb[2], vb[3]);
                MMA16816(o[np*2+1], Al2, vb[2], vb[3]);
                MMA16816(o[np*2+1], Ah,  vl2[2], vl2[3]);
            }
        }
    }

    float inv0 = 1.f / l0s, inv1 = 1.f / l1s;
    int row0 = b*SS + qt*64 + w*16 + (lane >> 2);
    int colb = h*HD + (lane & 3)*2;
    #pragma unroll
    for (int nf = 0; nf < 8; nf++) {
        float v0 = o[nf][0]*inv0, v1 = o[nf][1]*inv0;
        float v2 = o[nf][2]*inv1, v3 = o[nf][3]*inv1;
        size_t a0 = (size_t)row0 * DD + colb + nf*8;
        size_t a1 = (size_t)(row0 + 8) * DD + colb + nf*8;
        __nv_bfloat16 h0,h1,h2,h3,L0,L1,L2,L3;
        split1(v0, h0, L0); split1(v1, h1, L1);
        split1(v2, h2, L2); split1(v3, h3, L3);
        *(__nv_bfloat162*)(Ohi + a0) = __halves2bfloat162(h0, h1);
        *(__nv_bfloat162*)(Olo + a0) = __halves2bfloat162(L0, L1);
        *(__nv_bfloat162*)(Ohi + a1) = __halves2bfloat162(h2, h3);
        *(__nv_bfloat162*)(Olo + a1) = __halves2bfloat162(L2, L3);
    }
}

// ---------------- embedding lookup ----------------
__global__ void embed_kernel(const int* __restrict__ tokens,
                             const float* __restrict__ emb,
                             float* __restrict__ x) {
    int row = blockIdx.x;
    int tok = tokens[row];
    const float4* src = (const float4*)(emb + (size_t)tok * DD);
    float4* dst = (float4*)(x + (size_t)row * DD);
    for (int i = threadIdx.x; i < DD/4; i += blockDim.x) dst[i] = src[i];
}

// ---------------- LN core: returns normalized value per index -------------
__device__ __forceinline__ void ln_stats(const float* xr, int tid,
                                         float& mean, float& rstd) {
    float s = 0.f, s2 = 0.f;
    for (int i = tid; i < DD; i += 256) {
        float v = xr[i];
        s += v;
        s2 = fmaf(v, v, s2);
    }
    __shared__ float rs[8], rs2[8];
    #pragma unroll
    for (int o = 16; o > 0; o >>= 1) {
        s  += __shfl_down_sync(0xffffffffu, s,  o);
        s2 += __shfl_down_sync(0xffffffffu, s2, o);
    }
    int w = tid >> 5;
    if ((tid & 31) == 0) { rs[w] = s; rs2[w] = s2; }
    __syncthreads();
    __shared__ float mean_s, rstd_s;
    if (tid == 0) {
        float ts = 0.f, ts2 = 0.f;
        #pragma unroll
        for (int i = 0; i < 8; i++) { ts += rs[i]; ts2 += rs2[i]; }
        float m = ts / (float)DD;
        mean_s = m;
        rstd_s = rsqrtf(ts2 / (float)DD - m * m + 1e-5f);
    }
    __syncthreads();
    mean = mean_s; rstd = rstd_s;
}

// ---------------- layernorm -> bf16 hi/lo planes (attention path) ---------
__global__ void ln_kernel(const float* __restrict__ x,
                          const float* __restrict__ gw,
                          const float* __restrict__ bw,
                          __nv_bfloat16* __restrict__ hi,
                          __nv_bfloat16* __restrict__ lo) {
    int row = blockIdx.x;
    const float* xr = x + (size_t)row * DD;
    int tid = threadIdx.x;
    float m, r;
    ln_stats(xr, tid, m, r);
    __nv_bfloat16* hrow = hi + (size_t)row * DD;
    __nv_bfloat16* lrow = lo + (size_t)row * DD;
    for (int i = tid; i < DD; i += 256) {
        float v = (xr[i] - m) * r * gw[i] + bw[i];
        __nv_bfloat16 vh, vl;
        split1(v, vh, vl);
        hrow[i] = vh;
        lrow[i] = vl;
    }
}

// ---------------- layernorm -> fp16 hi/lo planes (FFN path) ---------------
__global__ void ln_h2(const float* __restrict__ x,
                      const float* __restrict__ gw,
                      const float* __restrict__ bw,
                      __half* __restrict__ hi,
                      __half* __restrict__ lo) {
    int row = blockIdx.x;
    const float* xr = x + (size_t)row * DD;
    int tid = threadIdx.x;
    float m, r;
    ln_stats(xr, tid, m, r);
    __half* hrow = hi + (size_t)row * DD;
    __half* lrow = lo + (size_t)row * DD;
    for (int i = tid; i < DD; i += 256) {
        float v = (xr[i] - m) * r * gw[i] + bw[i];
        __half vh, vl;
        split1h(v, vh, vl);
        hrow[i] = vh;
        lrow[i] = vl;
    }
}

// ---------------- final layernorm -> fp16 single plane --------------------
__global__ void ln_h(const float* __restrict__ x,
                     const float* __restrict__ gw,
                     const float* __restrict__ bw,
                     __half* __restrict__ out) {
    int row = blockIdx.x;
    const float* xr = x + (size_t)row * DD;
    int tid = threadIdx.x;
    float m, r;
    ln_stats(xr, tid, m, r);
    __half* orow = out + (size_t)row * DD;
    for (int i = tid; i < DD; i += 256) {
        float v = (xr[i] - m) * r * gw[i] + bw[i];
        orow[i] = __float2half(v);
    }
}

// ---------------- SwiGLU (fp32 ff in) -> fp16 hi/lo planes ----------------
__global__ void swiglu_h2(const float* __restrict__ ff,
                          __half* __restrict__ hi, __half* __restrict__ lo) {
    int row = blockIdx.x;
    const float* fr = ff + (size_t)row * FFS;
    int tid = threadIdx.x;
    __half* hrow = hi + (size_t)row * DD;
    __half* lrow = lo + (size_t)row * DD;
    for (int i = tid; i < DD; i += 256) {
        float a = fr[i], c = fr[i + DD];
        float g = a / (1.f + __expf(-a)) * c;
        __half vh, vl;
        split1h(g, vh, vl);
        hrow[i] = vh;
        lrow[i] = vl;
    }
}

// ---------------- launch ----------------
extern "C" void kernel_launch(void* const* d_in, const int* in_sizes, int n_in,
                              void* d_out, int out_size) {
    const int*   tokens = (const int*)d_in[0];
    const float* emb    = (const float*)d_in[1];
    const float* wq     = (const float*)d_in[2];
    const float* wk     = (const float*)d_in[3];
    const float* wv     = (const float*)d_in[4];
    const float* wo     = (const float*)d_in[5];
    const float* ln1_g  = (const float*)d_in[6];
    const float* ln1_b  = (const float*)d_in[7];
    const float* ln2_g  = (const float*)d_in[8];
    const float* ln2_b  = (const float*)d_in[9];
    const float* w1     = (const float*)d_in[10];
    const float* w2     = (const float*)d_in[11];
    const float* w3     = (const float*)d_in[12];
    const float* lnf_g  = (const float*)d_in[13];
    const float* lnf_b  = (const float*)d_in[14];
    const float* w_out  = (const float*)d_in[15];
    float* out = (float*)d_out;

    float *px, *pff;
    cudaGetSymbolAddress((void**)&px, g_x);
    cudaGetSymbolAddress((void**)&pff, g_ff32);
    __nv_bfloat16 *whi, *wlo, *ahi, *alo, *qkvh, *qkvl;
    cudaGetSymbolAddress((void**)&whi, g_whi);
    cudaGetSymbolAddress((void**)&wlo, g_wlo);
    cudaGetSymbolAddress((void**)&ahi, g_ahi);
    cudaGetSymbolAddress((void**)&alo, g_alo);
    cudaGetSymbolAddress((void**)&qkvh, g_qkvh);
    cudaGetSymbolAddress((void**)&qkvl, g_qkvl);

    cudaFuncSetAttribute(attn_mma,
                         cudaFuncAttributeMaxDynamicSharedMemorySize, ASMEM);
    cudaFuncSetAttribute(gemm_mma<false,true>,
                         cudaFuncAttributeMaxDynamicSharedMemorySize, GSMEM);
    cudaFuncSetAttribute(gemm_mma<true,false>,
                         cudaFuncAttributeMaxDynamicSharedMemorySize, GSMEM);
    cudaFuncSetAttribute(gemm_h2<false>,
                         cudaFuncAttributeMaxDynamicSharedMemorySize, H2SMEM);
    cudaFuncSetAttribute(gemm_h2<true>,
                         cudaFuncAttributeMaxDynamicSharedMemorySize, H2SMEM);
    cudaFuncSetAttribute(gemm_f16,
                         cudaFuncAttributeMaxDynamicSharedMemorySize, HGSMEM);

    // ---- convert weights ----
    {
        int n4 = WMAT / 4;
        int gb = n4 / 1024;
        for (int l = 0; l < LL; l++) {
            size_t so = (size_t)l * WMAT;
            size_t qo = QKV_OFF + (size_t)l * 3 * WMAT;
            conv_split<<<gb, 256>>>(wq + so, whi + qo,          wlo + qo,          n4);
            conv_split<<<gb, 256>>>(wk + so, whi + qo + WMAT,   wlo + qo + WMAT,   n4);
            conv_split<<<gb, 256>>>(wv + so, whi + qo + 2*WMAT, wlo + qo + 2*WMAT, n4);
            size_t fo = W13_OFF + (size_t)l * 2 * WMAT;
            conv_h<<<gb, 256>>>(w1 + so, (__half*)whi + fo,        n4);
            conv_h<<<gb, 256>>>(w3 + so, (__half*)whi + fo + WMAT, n4);
            size_t to = W2_OFF + (size_t)l * WMAT;
            conv_h<<<gb, 256>>>(w2 + so, (__half*)whi + to, n4);
        }
        int n4L = (LL * WMAT) / 4;
        conv_split<<<n4L/1024, 256>>>(wo, whi + WO_OFF, wlo + WO_OFF, n4L);
        int n4o = (VV * DD) / 4;
        conv_h<<<n4o/1024, 256>>>(w_out, (__half*)whi + WOUT_OFF, n4o);
    }

    embed_kernel<<<MM, 256>>>(tokens, emb, px);

    dim3 gQKV(QKVS/128, MM/128);
    dim3 gD(DD/128, MM/128);
    dim3 gFF(FFS/128, MM/128);
    for (int l = 0; l < LL; l++) {
        size_t qo = QKV_OFF + (size_t)l * 3 * WMAT;
        size_t oo = WO_OFF + (size_t)l * WMAT;
        size_t fo = W13_OFF + (size_t)l * 2 * WMAT;
        size_t to = W2_OFF + (size_t)l * WMAT;

        // attention (3-term bf16)
        ln_kernel<<<MM, 256>>>(px, ln1_g + l*DD, ln1_b + l*DD, ahi, alo);
        gemm_mma<false,true><<<gQKV, 256, GSMEM>>>(ahi, alo, whi + qo, wlo + qo,
                                                   nullptr, nullptr, qkvh, qkvl, QKVS, DD);
        attn_mma<<<dim3(SS/64, BB*HH), 128, ASMEM>>>(qkvh, qkvl, ahi, alo);
        gemm_mma<true,false><<<gD, 256, GSMEM>>>(ahi, alo, whi + oo, wlo + oo,
                                                 px, px, nullptr, nullptr, DD, DD);

        // SwiGLU FFN (2-term fp16)
        ln_h2<<<MM, 256>>>(px, ln2_g + l*DD, ln2_b + l*DD, (__half*)ahi, (__half*)alo);
        gemm_h2<false><<<gFF, 256, H2SMEM>>>((const __half*)ahi, (const __half*)alo,
                                             (const __half*)whi + fo,
                                             nullptr, pff, FFS, DD);
        swiglu_h2<<<MM, 256>>>(pff, (__half*)ahi, (__half*)alo);
        gemm_h2<true><<<gD, 256, H2SMEM>>>((const __half*)ahi, (const __half*)alo,
                                           (const __half*)whi + to,
                                           px, px, DD, DD);
    }

    // final LN (fp16) + plain-fp16 logits GEMM
    ln_h<<<MM, 256>>>(px, lnf_g, lnf_b, (__half*)ahi);
    gemm_f16<<<dim3(VV/128, MM/128), 256, HGSMEM>>>(
        (const __half*)ahi, (const __half*)whi + WOUT_OFF, out, VV, DD);
}

// round 15
// speedup vs baseline: 3.2449x; 1.1533x over previous
#include <cuda_runtime.h>
#include <cuda_bf16.h>
#include <cuda_fp16.h>
#include <math.h>
#include <stdint.h>

// ---------------- problem constants ----------------
#define BB 2
#define SS 2048
#define DD 1024
#define HH 16
#define HD 64
#define LL 8
#define VV 32000
#define MM (BB*SS)          // 4096 rows
#define QKVS (3*DD)
#define FFS  (2*DD)

// ---------------- weight plane offsets (all fp16 single-plane) -------------
#define WMAT (DD*DD)
#define QKV_OFF 0                       // layer stride 3*WMAT (q,k,v row-blocks)
#define WO_OFF  (3*LL*WMAT)
#define W13_OFF (4*LL*WMAT)             // layer stride 2*WMAT (w1, w3)
#define W2_OFF  (6*LL*WMAT)
#define WOUT_OFF (7*LL*WMAT)
#define WTOT (WOUT_OFF + (size_t)VV*DD)

// ---------------- scratch (device globals) ----------
__device__ float g_x[MM*DD];
__device__ float g_ff32[MM*FFS];
__device__ __half g_wq16[WTOT];
__device__ __half g_ahi[MM*DD];
__device__ __half g_alo[MM*DD];
__device__ __nv_bfloat16 g_qkvh[MM*QKVS];
__device__ __nv_bfloat16 g_qkvl[MM*QKVS];

// ================= helpers =================
__device__ __forceinline__ uint32_t smem_u32(const void* p) {
    uint32_t a;
    asm("{ .reg .u64 t; cvta.to.shared.u64 t, %1; cvt.u32.u64 %0, t; }"
        : "=r"(a) : "l"(p));
    return a;
}
#define CP16(dst, src) \
    asm volatile("cp.async.cg.shared.global [%0], [%1], 16;" :: "r"(dst), "l"(src))
#define CP8(dst, src) \
    asm volatile("cp.async.ca.shared.global [%0], [%1], 8;" :: "r"(dst), "l"(src))
#define CP_COMMIT() asm volatile("cp.async.commit_group;" ::: "memory")
#define CP_WAIT1()  asm volatile("cp.async.wait_group 1;" ::: "memory")
#define CP_WAIT0()  asm volatile("cp.async.wait_group 0;" ::: "memory")
#define LDSM4(r, addr) \
    asm volatile("ldmatrix.sync.aligned.m8n8.x4.shared.b16 {%0,%1,%2,%3}, [%4];" \
        : "=r"((r)[0]), "=r"((r)[1]), "=r"((r)[2]), "=r"((r)[3]) : "r"(addr))
#define LDSM4T(r, addr) \
    asm volatile("ldmatrix.sync.aligned.m8n8.x4.trans.shared.b16 {%0,%1,%2,%3}, [%4];" \
        : "=r"((r)[0]), "=r"((r)[1]), "=r"((r)[2]), "=r"((r)[3]) : "r"(addr))
#define MMA16816(c, a, b0v, b1v) \
    asm volatile("mma.sync.aligned.m16n8k16.row.col.f32.bf16.bf16.f32 " \
        "{%0,%1,%2,%3}, {%4,%5,%6,%7}, {%8,%9}, {%0,%1,%2,%3};" \
        : "+f"((c)[0]), "+f"((c)[1]), "+f"((c)[2]), "+f"((c)[3]) \
        : "r"((a)[0]), "r"((a)[1]), "r"((a)[2]), "r"((a)[3]), "r"(b0v), "r"(b1v))
#define MMAH(c, a, b0v, b1v) \
    asm volatile("mma.sync.aligned.m16n8k16.row.col.f32.f16.f16.f32 " \
        "{%0,%1,%2,%3}, {%4,%5,%6,%7}, {%8,%9}, {%0,%1,%2,%3};" \
        : "+f"((c)[0]), "+f"((c)[1]), "+f"((c)[2]), "+f"((c)[3]) \
        : "r"((a)[0]), "r"((a)[1]), "r"((a)[2]), "r"((a)[3]), "r"(b0v), "r"(b1v))

__device__ __forceinline__ void split1(float x, __nv_bfloat16& h, __nv_bfloat16& l) {
    h = __float2bfloat16(x);
    l = __float2bfloat16(x - __bfloat162float(h));
}
__device__ __forceinline__ void split1h(float x, __half& h, __half& l) {
    h = __float2half(x);
    l = __float2half(x - __half2float(h));
}

// ---------------- fp32 -> fp16 plane, strided per-layer destination --------
// i4 indexes float4 quads over the whole source tensor. Layer = i4/plane4,
// dst quad = layer*stride4 + (i4 % plane4).
__global__ void conv_h_s(const float* __restrict__ src, __half* __restrict__ dst,
                         int n4, int plane4, int stride4) {
    int i = blockIdx.x * 256 + threadIdx.x;
    if (i >= n4) return;
    float4 v = ((const float4*)src)[i];
    __half2 a = __floats2half2_rn(v.x, v.y);
    __half2 b = __floats2half2_rn(v.z, v.w);
    int layer = i / plane4, rem = i - layer * plane4;
    ((uint2*)dst)[(size_t)layer * stride4 + rem] = make_uint2(*(uint32_t*)&a, *(uint32_t*)&b);
}

// ================= 2-term fp16 GEMM: D = (Ah+Al) @ Bq^T =====================
// A fp16 hi/lo planes (22-bit), B single fp16 plane. 3 smem planes, 2 MMAs
// per fragment pair. 128x128 tile, BK=32, 256 thr (8 warps 4x2), occ 2.
#define PLANE_B 10240
#define H2STAGE (3*PLANE_B)
#define H2SMEM  (2*H2STAGE)

template<int OUTMODE>   // 0: fp32 C   1: fp32 C + residual R   2: bf16 hi/lo split
__global__ void __launch_bounds__(256, 2)
gemm_h2(const __half* __restrict__ Ahi, const __half* __restrict__ Alo,
        const __half* __restrict__ B,
        const float* __restrict__ R, float* __restrict__ C,
        __nv_bfloat16* __restrict__ Chi, __nv_bfloat16* __restrict__ Clo,
        int N, int K) {
    extern __shared__ char sm_raw[];
    uint32_t sb = smem_u32(sm_raw);
    int tid = threadIdx.x, lane = tid & 31, wid = tid >> 5;
    int wm = wid & 3, wn = wid >> 2;
    int m0 = blockIdx.y * 128, n0 = blockIdx.x * 128;

    int prow = tid >> 1;
    int pc   = (tid & 1) * 2;
    const __half* srcs[3] = {Ahi, Alo, B};
    int nslab = K / 32;

    {
        #pragma unroll
        for (int p = 0; p < 3; p++) {
            int rb = (p < 2) ? m0 : n0;
            const __half* g = srcs[p] + (size_t)(rb + prow) * K + pc * 8;
            uint32_t d = sb + p * PLANE_B + prow * 80 + pc * 16;
            CP16(d, g);
            CP16(d + 16, g + 8);
        }
        CP_COMMIT();
    }

    float acc[2][8][4] = {};
    int gq = lane >> 3, rr = lane & 7;

    for (int s = 0; s < nslab; s++) {
        if (s + 1 < nslab) {
            uint32_t stb = sb + ((s + 1) & 1) * H2STAGE;
            int k0 = (s + 1) * 32;
            #pragma unroll
            for (int p = 0; p < 3; p++) {
                int rb = (p < 2) ? m0 : n0;
                const __half* g = srcs[p] + (size_t)(rb + prow) * K + k0 + pc * 8;
                uint32_t d = stb + p * PLANE_B + prow * 80 + pc * 16;
                CP16(d, g);
                CP16(d + 16, g + 8);
            }
            CP_COMMIT();
            CP_WAIT1();
        } else {
            CP_WAIT0();
        }
        __syncthreads();

        uint32_t stb = sb + (s & 1) * H2STAGE;
        #pragma unroll
        for (int ks = 0; ks < 2; ks++) {
            uint32_t ah[2][4], al[2][4];
            #pragma unroll
            for (int mf = 0; mf < 2; mf++) {
                int row = wm * 32 + mf * 16 + (gq & 1) * 8 + rr;
                int col = ks * 16 + (gq >> 1) * 8;
                uint32_t a = stb + row * 80 + col * 2;
                LDSM4(ah[mf], a);
                LDSM4(al[mf], a + PLANE_B);
            }
            #pragma unroll
            for (int np = 0; np < 4; np++) {
                uint32_t bh[4];
                int row = wn * 64 + np * 16 + (gq >> 1) * 8 + rr;
                int col = ks * 16 + (gq & 1) * 8;
                LDSM4(bh, stb + 2 * PLANE_B + row * 80 + col * 2);
                #pragma unroll
                for (int mf = 0; mf < 2; mf++) {
                    MMAH(acc[mf][np*2],   ah[mf], bh[0], bh[1]);
                    MMAH(acc[mf][np*2],   al[mf], bh[0], bh[1]);
                    MMAH(acc[mf][np*2+1], ah[mf], bh[2], bh[3]);
                    MMAH(acc[mf][np*2+1], al[mf], bh[2], bh[3]);
                }
            }
        }
        __syncthreads();
    }

    int rbase = m0 + wm * 32 + (lane >> 2);
    int cbase = n0 + wn * 64 + (lane & 3) * 2;
    #pragma unroll
    for (int mf = 0; mf < 2; mf++) {
        #pragma unroll
        for (int nf = 0; nf < 8; nf++) {
            int row = rbase + mf * 16;
            int col = cbase + nf * 8;
            float v0 = acc[mf][nf][0], v1 = acc[mf][nf][1];
            float v2 = acc[mf][nf][2], v3 = acc[mf][nf][3];
            size_t a0 = (size_t)row * N + col;
            size_t a1 = (size_t)(row + 8) * N + col;
            if (OUTMODE == 2) {
                __nv_bfloat16 h0,h1,h2,h3,L0,L1,L2,L3;
                split1(v0, h0, L0); split1(v1, h1, L1);
                split1(v2, h2, L2); split1(v3, h3, L3);
                *(__nv_bfloat162*)(Chi + a0) = __halves2bfloat162(h0, h1);
                *(__nv_bfloat162*)(Clo + a0) = __halves2bfloat162(L0, L1);
                *(__nv_bfloat162*)(Chi + a1) = __halves2bfloat162(h2, h3);
                *(__nv_bfloat162*)(Clo + a1) = __halves2bfloat162(L2, L3);
            } else {
                if (OUTMODE == 1) {
                    float2 r0 = *(const float2*)(R + a0);
                    float2 r1 = *(const float2*)(R + a1);
                    v0 += r0.x; v1 += r0.y; v2 += r1.x; v3 += r1.y;
                }
                *(float2*)(C + a0) = make_float2(v0, v1);
                *(float2*)(C + a1) = make_float2(v2, v3);
            }
        }
    }
}

// ================= plain fp16 GEMM (logits head) =================
#define HSTAGE (2*PLANE_B)
#define HGSMEM (2*HSTAGE)

__global__ void __launch_bounds__(256, 2)
gemm_f16(const __half* __restrict__ A, const __half* __restrict__ B,
         float* __restrict__ C, int N, int K) {
    extern __shared__ char sm_raw[];
    uint32_t sb = smem_u32(sm_raw);
    int tid = threadIdx.x, lane = tid & 31, wid = tid >> 5;
    int wm = wid & 3, wn = wid >> 2;
    int m0 = blockIdx.y * 128, n0 = blockIdx.x * 128;

    int prow = tid >> 1;
    int pc   = (tid & 1) * 2;
    const __half* srcs[2] = {A, B};
    int nslab = K / 32;

    {
        #pragma unroll
        for (int p = 0; p < 2; p++) {
            int rb = p ? n0 : m0;
            const __half* g = srcs[p] + (size_t)(rb + prow) * K + pc * 8;
            uint32_t d = sb + p * PLANE_B + prow * 80 + pc * 16;
            CP16(d, g);
            CP16(d + 16, g + 8);
        }
        CP_COMMIT();
    }

    float acc[2][8][4] = {};
    int gq = lane >> 3, rr = lane & 7;

    for (int s = 0; s < nslab; s++) {
        if (s + 1 < nslab) {
            uint32_t stb = sb + ((s + 1) & 1) * HSTAGE;
            int k0 = (s + 1) * 32;
            #pragma unroll
            for (int p = 0; p < 2; p++) {
                int rb = p ? n0 : m0;
                const __half* g = srcs[p] + (size_t)(rb + prow) * K + k0 + pc * 8;
                uint32_t d = stb + p * PLANE_B + prow * 80 + pc * 16;
                CP16(d, g);
                CP16(d + 16, g + 8);
            }
            CP_COMMIT();
            CP_WAIT1();
        } else {
            CP_WAIT0();
        }
        __syncthreads();

        uint32_t stb = sb + (s & 1) * HSTAGE;
        #pragma unroll
        for (int ks = 0; ks < 2; ks++) {
            uint32_t ah[2][4];
            #pragma unroll
            for (int mf = 0; mf < 2; mf++) {
                int row = wm * 32 + mf * 16 + (gq & 1) * 8 + rr;
                int col = ks * 16 + (gq >> 1) * 8;
                LDSM4(ah[mf], stb + row * 80 + col * 2);
            }
            #pragma unroll
            for (int np = 0; np < 4; np++) {
                uint32_t bh[4];
                int row = wn * 64 + np * 16 + (gq >> 1) * 8 + rr;
                int col = ks * 16 + (gq & 1) * 8;
                LDSM4(bh, stb + PLANE_B + row * 80 + col * 2);
                #pragma unroll
                for (int mf = 0; mf < 2; mf++) {
                    MMAH(acc[mf][np*2],   ah[mf], bh[0], bh[1]);
                    MMAH(acc[mf][np*2+1], ah[mf], bh[2], bh[3]);
                }
            }
        }
        __syncthreads();
    }

    int rbase = m0 + wm * 32 + (lane >> 2);
    int cbase = n0 + wn * 64 + (lane & 3) * 2;
    #pragma unroll
    for (int mf = 0; mf < 2; mf++) {
        #pragma unroll
        for (int nf = 0; nf < 8; nf++) {
            int row = rbase + mf * 16;
            int col = cbase + nf * 8;
            size_t a0 = (size_t)row * N + col;
            size_t a1 = (size_t)(row + 8) * N + col;
            *(float2*)(C + a0) = make_float2(acc[mf][nf][0], acc[mf][nf][1]);
            *(float2*)(C + a1) = make_float2(acc[mf][nf][2], acc[mf][nf][3]);
        }
    }
}

// ================= mma.sync flash attention (bf16 split planes) ============
// Output: fp16 hi/lo planes for the WO gemm_h2.
#define ALD 72
#define APLANE (64*ALD*2)
#define ASMEM  (6*APLANE)

__global__ void __launch_bounds__(128)
attn_mma(const __nv_bfloat16* __restrict__ Ph, const __nv_bfloat16* __restrict__ Pl,
         __half* __restrict__ Ohi, __half* __restrict__ Olo) {
    extern __shared__ char asmr[];
    uint32_t sb = smem_u32(asmr);
    const uint32_t QH = sb, QL = sb + APLANE, KH = sb + 2*APLANE,
                   KL = sb + 3*APLANE, VH = sb + 4*APLANE, VL = sb + 5*APLANE;

    int tid = threadIdx.x, lane = tid & 31, w = tid >> 5;
    int gq = lane >> 3, rr = lane & 7;
    int bh = blockIdx.y;
    int b = bh / HH, h = bh % HH;
    int qt = blockIdx.x;
    float slope = exp2f(-0.5f * (float)(h + 1));

    int lrow = tid >> 4;
    int lcol = (tid & 15) * 4;

    #pragma unroll
    for (int pass = 0; pass < 8; pass++) {
        int row = lrow + pass * 8;
        size_t ga = (size_t)(b*SS + qt*64 + row) * QKVS + h*HD + lcol;
        uint32_t off = (row*ALD + lcol) * 2;
        CP8(QH + off, Ph + ga);
        CP8(QL + off, Pl + ga);
    }
    CP_COMMIT();
    CP_WAIT0();
    __syncthreads();

    uint32_t qh[4][4], ql[4][4];
    #pragma unroll
    for (int kk = 0; kk < 4; kk++) {
        uint32_t off = ((w*16 + (gq & 1)*8 + rr)*ALD + kk*16 + (gq >> 1)*8) * 2;
        LDSM4(qh[kk], QH + off);
        LDSM4(ql[kk], QL + off);
    }

    float m0r = -INFINITY, m1r = -INFINITY, l0s = 0.f, l1s = 0.f;
    float o[8][4] = {};
    int qg0 = qt*64 + w*16 + (lane >> 2);
    int qg1 = qg0 + 8;

    for (int kt = 0; kt <= qt; kt++) {
        __syncthreads();
        #pragma unroll
        for (int pass = 0; pass < 8; pass++) {
            int row = lrow + pass * 8;
            size_t gr = (size_t)(b*SS + kt*64 + row) * QKVS + h*HD + lcol;
            uint32_t off = (row*ALD + lcol) * 2;
            CP8(KH + off, Ph + gr + DD);
            CP8(KL + off, Pl + gr + DD);
            CP8(VH + off, Ph + gr + 2*DD);
            CP8(VL + off, Pl + gr + 2*DD);
        }
        CP_COMMIT();
        CP_WAIT0();
        __syncthreads();

        float s[8][4] = {};
        #pragma unroll
        for (int kk = 0; kk < 4; kk++) {
            #pragma unroll
            for (int np = 0; np < 4; np++) {
                uint32_t kb[4], kl2[4];
                uint32_t off = ((np*16 + (gq >> 1)*8 + rr)*ALD + kk*16 + (gq & 1)*8) * 2;
                LDSM4(kb, KH + off);
                LDSM4(kl2, KL + off);
                MMA16816(s[np*2],   qh[kk], kb[0], kb[1]);
                MMA16816(s[np*2],   ql[kk], kb[0], kb[1]);
                MMA16816(s[np*2],   qh[kk], kl2[0], kl2[1]);
                MMA16816(s[np*2+1], qh[kk], kb[2], kb[3]);
                MMA16816(s[np*2+1], ql[kk], kb[2], kb[3]);
                MMA16816(s[np*2+1], qh[kk], kl2[2], kl2[3]);
            }
        }

        #pragma unroll
        for (int nf = 0; nf < 8; nf++) {
            #pragma unroll
            for (int c = 0; c < 2; c++) {
                int kg = kt*64 + nf*8 + (lane & 3)*2 + c;
                float sv0 = s[nf][c]   * 0.125f;
                float sv1 = s[nf][2+c] * 0.125f;
                s[nf][c]   = (kg <= qg0) ? sv0 + slope*(float)(kg - qg0) : -1e30f;
                s[nf][2+c] = (kg <= qg1) ? sv1 + slope*(float)(kg - qg1) : -1e30f;
            }
        }

        float mx0 = -1e30f, mx1 = -1e30f;
        #pragma unroll
        for (int nf = 0; nf < 8; nf++) {
            mx0 = fmaxf(mx0, fmaxf(s[nf][0], s[nf][1]));
            mx1 = fmaxf(mx1, fmaxf(s[nf][2], s[nf][3]));
        }
        #pragma unroll
        for (int off = 1; off <= 2; off <<= 1) {
            mx0 = fmaxf(mx0, __shfl_xor_sync(0xffffffffu, mx0, off));
            mx1 = fmaxf(mx1, __shfl_xor_sync(0xffffffffu, mx1, off));
        }
        float mn0 = fmaxf(m0r, mx0), mn1 = fmaxf(m1r, mx1);
        float al0 = __expf(m0r - mn0), al1 = __expf(m1r - mn1);
        float rs0 = 0.f, rs1 = 0.f;
        #pragma unroll
        for (int nf = 0; nf < 8; nf++) {
            s[nf][0] = __expf(s[nf][0] - mn0);
            s[nf][1] = __expf(s[nf][1] - mn0);
            s[nf][2] = __expf(s[nf][2] - mn1);
            s[nf][3] = __expf(s[nf][3] - mn1);
            rs0 += s[nf][0] + s[nf][1];
            rs1 += s[nf][2] + s[nf][3];
        }
        #pragma unroll
        for (int off = 1; off <= 2; off <<= 1) {
            rs0 += __shfl_xor_sync(0xffffffffu, rs0, off);
            rs1 += __shfl_xor_sync(0xffffffffu, rs1, off);
        }
        l0s = l0s * al0 + rs0;
        l1s = l1s * al1 + rs1;
        m0r = mn0; m1r = mn1;

        #pragma unroll
        for (int nf = 0; nf < 8; nf++) {
            o[nf][0] *= al0; o[nf][1] *= al0;
            o[nf][2] *= al1; o[nf][3] *= al1;
        }

        #pragma unroll
        for (int kk = 0; kk < 4; kk++) {
            uint32_t Ah[4], Al2[4];
            #pragma unroll
            for (int half = 0; half < 2; half++) {
                float* sv = s[2*kk + half];
                __nv_bfloat162 h01 = __floats2bfloat162_rn(sv[0], sv[1]);
                __nv_bfloat162 h23 = __floats2bfloat162_rn(sv[2], sv[3]);
                __nv_bfloat162 L01 = __floats2bfloat162_rn(
                    sv[0] - __bfloat162float(__low2bfloat16(h01)),
                    sv[1] - __bfloat162float(__high2bfloat16(h01)));
                __nv_bfloat162 L23 = __floats2bfloat162_rn(
                    sv[2] - __bfloat162float(__low2bfloat16(h23)),
                    sv[3] - __bfloat162float(__high2bfloat16(h23)));
                Ah[half*2 + 0] = *(uint32_t*)&h01;
                Ah[half*2 + 1] = *(uint32_t*)&h23;
                Al2[half*2 + 0] = *(uint32_t*)&L01;
                Al2[half*2 + 1] = *(uint32_t*)&L23;
            }
            #pragma unroll
            for (int np = 0; np < 4; np++) {
                uint32_t vb[4], vl2[4];
                uint32_t off = ((kk*16 + (gq & 1)*8 + rr)*ALD + np*16 + (gq >> 1)*8) * 2;
                LDSM4T(vb, VH + off);
                LDSM4T(vl2, VL + off);
                MMA16816(o[np*2],   Ah,  vb[0], vb[1]);
                MMA16816(o[np*2],   Al2, vb[0], vb[1]);
                MMA16816(o[np*2],   Ah,  vl2[0], vl2[1]);
                MMA16816(o[np*2+1], Ah,  vb[2], vb[3]);
                MMA16816(o[np*2+1], Al2, vb[2], vb[3]);
                MMA16816(o[np*2+1], Ah,  vl2[2], vl2[3]);
            }
        }
    }

    float inv0 = 1.f / l0s, inv1 = 1.f / l1s;
    int row0 = b*SS + qt*64 + w*16 + (lane >> 2);
    int colb = h*HD + (lane & 3)*2;
    #pragma unroll
    for (int nf = 0; nf < 8; nf++) {
        float v0 = o[nf][0]*inv0, v1 = o[nf][1]*inv0;
        float v2 = o[nf][2]*inv1, v3 = o[nf][3]*inv1;
        size_t a0 = (size_t)row0 * DD + colb + nf*8;
        size_t a1 = (size_t)(row0 + 8) * DD + colb + nf*8;
        __half h0,h1,h2,h3,L0,L1,L2,L3;
        split1h(v0, h0, L0); split1h(v1, h1, L1);
        split1h(v2, h2, L2); split1h(v3, h3, L3);
        *(__half2*)(Ohi + a0) = __halves2half2(h0, h1);
        *(__half2*)(Olo + a0) = __halves2half2(L0, L1);
        *(__half2*)(Ohi + a1) = __halves2half2(h2, h3);
        *(__half2*)(Olo + a1) = __halves2half2(L2, L3);
    }
}

// ---------------- embedding lookup ----------------
__global__ void embed_kernel(const int* __restrict__ tokens,
                             const float* __restrict__ emb,
                             float* __restrict__ x) {
    int row = blockIdx.x;
    int tok = tokens[row];
    const float4* src = (const float4*)(emb + (size_t)tok * DD);
    float4* dst = (float4*)(x + (size_t)row * DD);
    for (int i = threadIdx.x; i < DD/4; i += blockDim.x) dst[i] = src[i];
}

// ---------------- LN core -------------------------------------------------
__device__ __forceinline__ void ln_stats(const float* xr, int tid,
                                         float& mean, float& rstd) {
    float s = 0.f, s2 = 0.f;
    for (int i = tid; i < DD; i += 256) {
        float v = xr[i];
        s += v;
        s2 = fmaf(v, v, s2);
    }
    __shared__ float rs[8], rs2[8];
    #pragma unroll
    for (int o = 16; o > 0; o >>= 1) {
        s  += __shfl_down_sync(0xffffffffu, s,  o);
        s2 += __shfl_down_sync(0xffffffffu, s2, o);
    }
    int w = tid >> 5;
    if ((tid & 31) == 0) { rs[w] = s; rs2[w] = s2; }
    __syncthreads();
    __shared__ float mean_s, rstd_s;
    if (tid == 0) {
        float ts = 0.f, ts2 = 0.f;
        #pragma unroll
        for (int i = 0; i < 8; i++) { ts += rs[i]; ts2 += rs2[i]; }
        float m = ts / (float)DD;
        mean_s = m;
        rstd_s = rsqrtf(ts2 / (float)DD - m * m + 1e-5f);
    }
    __syncthreads();
    mean = mean_s; rstd = rstd_s;
}

// ---------------- layernorm -> fp16 hi/lo planes --------------------------
__global__ void ln_h2(const float* __restrict__ x,
                      const float* __restrict__ gw,
                      const float* __restrict__ bw,
                      __half* __restrict__ hi,
                      __half* __restrict__ lo) {
    int row = blockIdx.x;
    const float* xr = x + (size_t)row * DD;
    int tid = threadIdx.x;
    float m, r;
    ln_stats(xr, tid, m, r);
    __half* hrow = hi + (size_t)row * DD;
    __half* lrow = lo + (size_t)row * DD;
    for (int i = tid; i < DD; i += 256) {
        float v = (xr[i] - m) * r * gw[i] + bw[i];
        __half vh, vl;
        split1h(v, vh, vl);
        hrow[i] = vh;
        lrow[i] = vl;
    }
}

// ---------------- final layernorm -> fp16 single plane --------------------
__global__ void ln_h(const float* __restrict__ x,
                     const float* __restrict__ gw,
                     const float* __restrict__ bw,
                     __half* __restrict__ out) {
    int row = blockIdx.x;
    const float* xr = x + (size_t)row * DD;
    int tid = threadIdx.x;
    float m, r;
    ln_stats(xr, tid, m, r);
    __half* orow = out + (size_t)row * DD;
    for (int i = tid; i < DD; i += 256) {
        float v = (xr[i] - m) * r * gw[i] + bw[i];
        orow[i] = __float2half(v);
    }
}

// ---------------- SwiGLU (fp32 ff in) -> fp16 hi/lo planes ----------------
__global__ void swiglu_h2(const float* __restrict__ ff,
                          __half* __restrict__ hi, __half* __restrict__ lo) {
    int row = blockIdx.x;
    const float* fr = ff + (size_t)row * FFS;
    int tid = threadIdx.x;
    __half* hrow = hi + (size_t)row * DD;
    __half* lrow = lo + (size_t)row * DD;
    for (int i = tid; i < DD; i += 256) {
        float a = fr[i], c = fr[i + DD];
        float g = a / (1.f + __expf(-a)) * c;
        __half vh, vl;
        split1h(g, vh, vl);
        hrow[i] = vh;
        lrow[i] = vl;
    }
}

// ---------------- launch ----------------
extern "C" void kernel_launch(void* const* d_in, const int* in_sizes, int n_in,
                              void* d_out, int out_size) {
    const int*   tokens = (const int*)d_in[0];
    const float* emb    = (const float*)d_in[1];
    const float* wq     = (const float*)d_in[2];
    const float* wk     = (const float*)d_in[3];
    const float* wv     = (const float*)d_in[4];
    const float* wo     = (const float*)d_in[5];
    const float* ln1_g  = (const float*)d_in[6];
    const float* ln1_b  = (const float*)d_in[7];
    const float* ln2_g  = (const float*)d_in[8];
    const float* ln2_b  = (const float*)d_in[9];
    const float* w1     = (const float*)d_in[10];
    const float* w2     = (const float*)d_in[11];
    const float* w3     = (const float*)d_in[12];
    const float* lnf_g  = (const float*)d_in[13];
    const float* lnf_b  = (const float*)d_in[14];
    const float* w_out  = (const float*)d_in[15];
    float* out = (float*)d_out;

    float *px, *pff;
    cudaGetSymbolAddress((void**)&px, g_x);
    cudaGetSymbolAddress((void**)&pff, g_ff32);
    __half *wq16, *ahi, *alo;
    cudaGetSymbolAddress((void**)&wq16, g_wq16);
    cudaGetSymbolAddress((void**)&ahi, g_ahi);
    cudaGetSymbolAddress((void**)&alo, g_alo);
    __nv_bfloat16 *qkvh, *qkvl;
    cudaGetSymbolAddress((void**)&qkvh, g_qkvh);
    cudaGetSymbolAddress((void**)&qkvl, g_qkvl);

    cudaFuncSetAttribute(attn_mma,
                         cudaFuncAttributeMaxDynamicSharedMemorySize, ASMEM);
    cudaFuncSetAttribute(gemm_h2<0>,
                         cudaFuncAttributeMaxDynamicSharedMemorySize, H2SMEM);
    cudaFuncSetAttribute(gemm_h2<1>,
                         cudaFuncAttributeMaxDynamicSharedMemorySize, H2SMEM);
    cudaFuncSetAttribute(gemm_h2<2>,
                         cudaFuncAttributeMaxDynamicSharedMemorySize, H2SMEM);
    cudaFuncSetAttribute(gemm_f16,
                         cudaFuncAttributeMaxDynamicSharedMemorySize, HGSMEM);

    // ---- convert all weights to fp16 planes (7 big strided launches) ----
    {
        int n4L = (LL * WMAT) / 4;       // quads per 8-layer weight tensor
        int p4  = WMAT / 4;              // quads per layer matrix
        conv_h_s<<<n4L/256, 256>>>(wq, wq16 + QKV_OFF,            n4L, p4, 3*p4);
        conv_h_s<<<n4L/256, 256>>>(wk, wq16 + QKV_OFF + WMAT,     n4L, p4, 3*p4);
        conv_h_s<<<n4L/256, 256>>>(wv, wq16 + QKV_OFF + 2*WMAT,   n4L, p4, 3*p4);
        conv_h_s<<<n4L/256, 256>>>(wo, wq16 + WO_OFF,             n4L, p4, p4);
        conv_h_s<<<n4L/256, 256>>>(w1, wq16 + W13_OFF,            n4L, p4, 2*p4);
        conv_h_s<<<n4L/256, 256>>>(w3, wq16 + W13_OFF + WMAT,     n4L, p4, 2*p4);
        conv_h_s<<<n4L/256, 256>>>(w2, wq16 + W2_OFF,             n4L, p4, p4);
        int n4o = (VV * DD) / 4;
        conv_h_s<<<n4o/256, 256>>>(w_out, wq16 + WOUT_OFF, n4o, n4o, n4o);
    }

    embed_kernel<<<MM, 256>>>(tokens, emb, px);

    dim3 gQKV(QKVS/128, MM/128);
    dim3 gD(DD/128, MM/128);
    dim3 gFF(FFS/128, MM/128);
    for (int l = 0; l < LL; l++) {
        size_t qo = QKV_OFF + (size_t)l * 3 * WMAT;
        size_t oo = WO_OFF + (size_t)l * WMAT;
        size_t fo = W13_OFF + (size_t)l * 2 * WMAT;
        size_t to = W2_OFF + (size_t)l * WMAT;

        // attention (2-term fp16 GEMMs; bf16 3-term core)
        ln_h2<<<MM, 256>>>(px, ln1_g + l*DD, ln1_b + l*DD, ahi, alo);
        gemm_h2<2><<<gQKV, 256, H2SMEM>>>(ahi, alo, wq16 + qo,
                                          nullptr, nullptr, qkvh, qkvl, QKVS, DD);
        attn_mma<<<dim3(SS/64, BB*HH), 128, ASMEM>>>(qkvh, qkvl, ahi, alo);
        gemm_h2<1><<<gD, 256, H2SMEM>>>(ahi, alo, wq16 + oo,
                                        px, px, nullptr, nullptr, DD, DD);

        // SwiGLU FFN (2-term fp16)
        ln_h2<<<MM, 256>>>(px, ln2_g + l*DD, ln2_b + l*DD, ahi, alo);
        gemm_h2<0><<<gFF, 256, H2SMEM>>>(ahi, alo, wq16 + fo,
                                         nullptr, pff, nullptr, nullptr, FFS, DD);
        swiglu_h2<<<MM, 256>>>(pff, ahi, alo);
        gemm_h2<1><<<gD, 256, H2SMEM>>>(ahi, alo, wq16 + to,
                                        px, px, nullptr, nullptr, DD, DD);
    }

    // final LN (fp16) + plain-fp16 logits GEMM
    ln_h<<<MM, 256>>>(px, lnf_g, lnf_b, ahi);
    gemm_f16<<<dim3(VV/128, MM/128), 256, HGSMEM>>>(
        ahi, wq16 + WOUT_OFF, out, VV, DD);
}

// round 16
// speedup vs baseline: 3.2743x; 1.0090x over previous
#include <cuda_runtime.h>
#include <cuda_bf16.h>
#include <cuda_fp16.h>
#include <math.h>
#include <stdint.h>

// ---------------- problem constants ----------------
#define BB 2
#define SS 2048
#define DD 1024
#define HH 16
#define HD 64
#define LL 8
#define VV 32000
#define MM (BB*SS)          // 4096 rows
#define QKVS (3*DD)
#define FFS  (2*DD)

// ---------------- weight plane offsets (all fp16 single-plane) -------------
#define WMAT (DD*DD)
#define QKV_OFF 0                       // layer stride 3*WMAT (q,k,v row-blocks)
#define WO_OFF  (3*LL*WMAT)
#define W13_OFF (4*LL*WMAT)             // layer stride 2*WMAT (w1/w3 interleaved)
#define W2_OFF  (6*LL*WMAT)
#define WOUT_OFF (7*LL*WMAT)
#define WTOT (WOUT_OFF + (size_t)VV*DD)

// ---------------- scratch (device globals) ----------
__device__ float g_x[MM*DD];
__device__ __half g_wq16[WTOT];
__device__ __half g_ahi[MM*DD];
__device__ __half g_alo[MM*DD];
__device__ __half g_bhi[MM*DD];
__device__ __half g_blo[MM*DD];
__device__ __nv_bfloat16 g_qkvh[MM*QKVS];
__device__ __nv_bfloat16 g_qkvl[MM*QKVS];

// ================= helpers =================
__device__ __forceinline__ uint32_t smem_u32(const void* p) {
    uint32_t a;
    asm("{ .reg .u64 t; cvta.to.shared.u64 t, %1; cvt.u32.u64 %0, t; }"
        : "=r"(a) : "l"(p));
    return a;
}
#define CP16(dst, src) \
    asm volatile("cp.async.cg.shared.global [%0], [%1], 16;" :: "r"(dst), "l"(src))
#define CP8(dst, src) \
    asm volatile("cp.async.ca.shared.global [%0], [%1], 8;" :: "r"(dst), "l"(src))
#define CP_COMMIT() asm volatile("cp.async.commit_group;" ::: "memory")
#define CP_WAIT1()  asm volatile("cp.async.wait_group 1;" ::: "memory")
#define CP_WAIT0()  asm volatile("cp.async.wait_group 0;" ::: "memory")
#define LDSM4(r, addr) \
    asm volatile("ldmatrix.sync.aligned.m8n8.x4.shared.b16 {%0,%1,%2,%3}, [%4];" \
        : "=r"((r)[0]), "=r"((r)[1]), "=r"((r)[2]), "=r"((r)[3]) : "r"(addr))
#define LDSM4T(r, addr) \
    asm volatile("ldmatrix.sync.aligned.m8n8.x4.trans.shared.b16 {%0,%1,%2,%3}, [%4];" \
        : "=r"((r)[0]), "=r"((r)[1]), "=r"((r)[2]), "=r"((r)[3]) : "r"(addr))
#define MMA16816(c, a, b0v, b1v) \
    asm volatile("mma.sync.aligned.m16n8k16.row.col.f32.bf16.bf16.f32 " \
        "{%0,%1,%2,%3}, {%4,%5,%6,%7}, {%8,%9}, {%0,%1,%2,%3};" \
        : "+f"((c)[0]), "+f"((c)[1]), "+f"((c)[2]), "+f"((c)[3]) \
        : "r"((a)[0]), "r"((a)[1]), "r"((a)[2]), "r"((a)[3]), "r"(b0v), "r"(b1v))
#define MMAH(c, a, b0v, b1v) \
    asm volatile("mma.sync.aligned.m16n8k16.row.col.f32.f16.f16.f32 " \
        "{%0,%1,%2,%3}, {%4,%5,%6,%7}, {%8,%9}, {%0,%1,%2,%3};" \
        : "+f"((c)[0]), "+f"((c)[1]), "+f"((c)[2]), "+f"((c)[3]) \
        : "r"((a)[0]), "r"((a)[1]), "r"((a)[2]), "r"((a)[3]), "r"(b0v), "r"(b1v))

__device__ __forceinline__ void split1(float x, __nv_bfloat16& h, __nv_bfloat16& l) {
    h = __float2bfloat16(x);
    l = __float2bfloat16(x - __bfloat162float(h));
}
__device__ __forceinline__ void split1h(float x, __half& h, __half& l) {
    h = __float2half(x);
    l = __float2half(x - __half2float(h));
}
__device__ __forceinline__ float silu_mul(float x, float c) {
    return x / (1.f + __expf(-x)) * c;
}

// ---------------- fp32 -> fp16 plane, strided per-layer destination --------
__global__ void conv_h_s(const float* __restrict__ src, __half* __restrict__ dst,
                         int n4, int plane4, int stride4) {
    int i = blockIdx.x * 256 + threadIdx.x;
    if (i >= n4) return;
    float4 v = ((const float4*)src)[i];
    __half2 a = __floats2half2_rn(v.x, v.y);
    __half2 b = __floats2half2_rn(v.z, v.w);
    int layer = i / plane4, rem = i - layer * plane4;
    ((uint2*)dst)[(size_t)layer * stride4 + rem] = make_uint2(*(uint32_t*)&a, *(uint32_t*)&b);
}

// ---------------- w1/w3 -> interleaved packed fp16 (8-row groups) ----------
// packed row p: g=p>>3, inner=p&7; even g -> w1 row (g>>1)*8+inner,
// odd g -> w3 same logical row. Grid: LL*2048 blocks x 256 threads.
__global__ void conv_w13(const float* __restrict__ w1, const float* __restrict__ w3,
                         __half* __restrict__ dst) {
    int i = blockIdx.x * 256 + threadIdx.x;  // quad index
    int l = i >> 19;                          // / (2048*256)
    int rem = i & 524287;
    int p = rem >> 8;                         // packed row 0..2047
    int q = rem & 255;                        // float4 quad within row
    int g = p >> 3, inner = p & 7;
    int jrow = (g >> 1) * 8 + inner;
    const float* src = (g & 1) ? w3 : w1;
    float4 v = ((const float4*)src)[((size_t)l * DD + jrow) * 256 + q];
    __half2 a = __floats2half2_rn(v.x, v.y);
    __half2 b = __floats2half2_rn(v.z, v.w);
    ((uint2*)dst)[((size_t)l * 2048 + p) * 256 + q] = make_uint2(*(uint32_t*)&a, *(uint32_t*)&b);
}

// ================= 2-term fp16 GEMM: D = (Ah+Al) @ Bq^T =====================
// OUTMODE 0: fp32 C   1: fp32 C + residual R   2: bf16 hi/lo split planes
// OUTMODE 3: fused SwiGLU on interleaved W13 -> fp16 hi/lo planes (logical DD)
#define PLANE_B 10240
#define H2STAGE (3*PLANE_B)
#define H2SMEM  (2*H2STAGE)

template<int OUTMODE>
__global__ void __launch_bounds__(256, 2)
gemm_h2(const __half* __restrict__ Ahi, const __half* __restrict__ Alo,
        const __half* __restrict__ B,
        const float* __restrict__ R, float* __restrict__ C,
        __nv_bfloat16* __restrict__ Chi, __nv_bfloat16* __restrict__ Clo,
        __half* __restrict__ Hhi, __half* __restrict__ Hlo,
        int N, int K) {
    extern __shared__ char sm_raw[];
    uint32_t sb = smem_u32(sm_raw);
    int tid = threadIdx.x, lane = tid & 31, wid = tid >> 5;
    int wm = wid & 3, wn = wid >> 2;
    int m0 = blockIdx.y * 128, n0 = blockIdx.x * 128;

    int prow = tid >> 1;
    int pc   = (tid & 1) * 2;
    const __half* srcs[3] = {Ahi, Alo, B};
    int nslab = K / 32;

    {
        #pragma unroll
        for (int p = 0; p < 3; p++) {
            int rb = (p < 2) ? m0 : n0;
            const __half* g = srcs[p] + (size_t)(rb + prow) * K + pc * 8;
            uint32_t d = sb + p * PLANE_B + prow * 80 + pc * 16;
            CP16(d, g);
            CP16(d + 16, g + 8);
        }
        CP_COMMIT();
    }

    float acc[2][8][4] = {};
    int gq = lane >> 3, rr = lane & 7;

    for (int s = 0; s < nslab; s++) {
        if (s + 1 < nslab) {
            uint32_t stb = sb + ((s + 1) & 1) * H2STAGE;
            int k0 = (s + 1) * 32;
            #pragma unroll
            for (int p = 0; p < 3; p++) {
                int rb = (p < 2) ? m0 : n0;
                const __half* g = srcs[p] + (size_t)(rb + prow) * K + k0 + pc * 8;
                uint32_t d = stb + p * PLANE_B + prow * 80 + pc * 16;
                CP16(d, g);
                CP16(d + 16, g + 8);
            }
            CP_COMMIT();
            CP_WAIT1();
        } else {
            CP_WAIT0();
        }
        __syncthreads();

        uint32_t stb = sb + (s & 1) * H2STAGE;
        #pragma unroll
        for (int ks = 0; ks < 2; ks++) {
            uint32_t ah[2][4], al[2][4];
            #pragma unroll
            for (int mf = 0; mf < 2; mf++) {
                int row = wm * 32 + mf * 16 + (gq & 1) * 8 + rr;
                int col = ks * 16 + (gq >> 1) * 8;
                uint32_t a = stb + row * 80 + col * 2;
                LDSM4(ah[mf], a);
                LDSM4(al[mf], a + PLANE_B);
            }
            #pragma unroll
            for (int np = 0; np < 4; np++) {
                uint32_t bh[4];
                int row = wn * 64 + np * 16 + (gq >> 1) * 8 + rr;
                int col = ks * 16 + (gq & 1) * 8;
                LDSM4(bh, stb + 2 * PLANE_B + row * 80 + col * 2);
                #pragma unroll
                for (int mf = 0; mf < 2; mf++) {
                    MMAH(acc[mf][np*2],   ah[mf], bh[0], bh[1]);
                    MMAH(acc[mf][np*2],   al[mf], bh[0], bh[1]);
                    MMAH(acc[mf][np*2+1], ah[mf], bh[2], bh[3]);
                    MMAH(acc[mf][np*2+1], al[mf], bh[2], bh[3]);
                }
            }
        }
        __syncthreads();
    }

    int rbase = m0 + wm * 32 + (lane >> 2);
    int cbase = n0 + wn * 64 + (lane & 3) * 2;
    if (OUTMODE == 3) {
        // fused SwiGLU: even nf = w1 outputs, odd nf = w3 outputs (same logical j)
        #pragma unroll
        for (int mf = 0; mf < 2; mf++) {
            int row = rbase + mf * 16;
            #pragma unroll
            for (int nfp = 0; nfp < 4; nfp++) {
                int col1 = cbase + nfp * 16;           // even-fragment packed col
                int j = ((col1 >> 4) << 3) + (col1 & 7);
                float* v1 = acc[mf][nfp*2];
                float* v3 = acc[mf][nfp*2 + 1];
                float g0 = silu_mul(v1[0], v3[0]);
                float g1 = silu_mul(v1[1], v3[1]);
                float g2 = silu_mul(v1[2], v3[2]);
                float g3 = silu_mul(v1[3], v3[3]);
                __half h0,h1,h2,h3,L0,L1,L2,L3;
                split1h(g0, h0, L0); split1h(g1, h1, L1);
                split1h(g2, h2, L2); split1h(g3, h3, L3);
                size_t a0 = (size_t)row * DD + j;
                size_t a1 = (size_t)(row + 8) * DD + j;
                *(__half2*)(Hhi + a0) = __halves2half2(h0, h1);
                *(__half2*)(Hlo + a0) = __halves2half2(L0, L1);
                *(__half2*)(Hhi + a1) = __halves2half2(h2, h3);
                *(__half2*)(Hlo + a1) = __halves2half2(L2, L3);
            }
        }
        return;
    }
    #pragma unroll
    for (int mf = 0; mf < 2; mf++) {
        #pragma unroll
        for (int nf = 0; nf < 8; nf++) {
            int row = rbase + mf * 16;
            int col = cbase + nf * 8;
            float v0 = acc[mf][nf][0], v1 = acc[mf][nf][1];
            float v2 = acc[mf][nf][2], v3 = acc[mf][nf][3];
            size_t a0 = (size_t)row * N + col;
            size_t a1 = (size_t)(row + 8) * N + col;
            if (OUTMODE == 2) {
                __nv_bfloat16 h0,h1,h2,h3,L0,L1,L2,L3;
                split1(v0, h0, L0); split1(v1, h1, L1);
                split1(v2, h2, L2); split1(v3, h3, L3);
                *(__nv_bfloat162*)(Chi + a0) = __halves2bfloat162(h0, h1);
                *(__nv_bfloat162*)(Clo + a0) = __halves2bfloat162(L0, L1);
                *(__nv_bfloat162*)(Chi + a1) = __halves2bfloat162(h2, h3);
                *(__nv_bfloat162*)(Clo + a1) = __halves2bfloat162(L2, L3);
            } else {
                if (OUTMODE == 1) {
                    float2 r0 = *(const float2*)(R + a0);
                    float2 r1 = *(const float2*)(R + a1);
                    v0 += r0.x; v1 += r0.y; v2 += r1.x; v3 += r1.y;
                }
                *(float2*)(C + a0) = make_float2(v0, v1);
                *(float2*)(C + a1) = make_float2(v2, v3);
            }
        }
    }
}

// ================= plain fp16 GEMM (logits head) =================
#define HSTAGE (2*PLANE_B)
#define HGSMEM (2*HSTAGE)

__global__ void __launch_bounds__(256, 2)
gemm_f16(const __half* __restrict__ A, const __half* __restrict__ B,
         float* __restrict__ C, int N, int K) {
    extern __shared__ char sm_raw[];
    uint32_t sb = smem_u32(sm_raw);
    int tid = threadIdx.x, lane = tid & 31, wid = tid >> 5;
    int wm = wid & 3, wn = wid >> 2;
    int m0 = blockIdx.y * 128, n0 = blockIdx.x * 128;

    int prow = tid >> 1;
    int pc   = (tid & 1) * 2;
    const __half* srcs[2] = {A, B};
    int nslab = K / 32;

    {
        #pragma unroll
        for (int p = 0; p < 2; p++) {
            int rb = p ? n0 : m0;
            const __half* g = srcs[p] + (size_t)(rb + prow) * K + pc * 8;
            uint32_t d = sb + p * PLANE_B + prow * 80 + pc * 16;
            CP16(d, g);
            CP16(d + 16, g + 8);
        }
        CP_COMMIT();
    }

    float acc[2][8][4] = {};
    int gq = lane >> 3, rr = lane & 7;

    for (int s = 0; s < nslab; s++) {
        if (s + 1 < nslab) {
            uint32_t stb = sb + ((s + 1) & 1) * HSTAGE;
            int k0 = (s + 1) * 32;
            #pragma unroll
            for (int p = 0; p < 2; p++) {
                int rb = p ? n0 : m0;
                const __half* g = srcs[p] + (size_t)(rb + prow) * K + k0 + pc * 8;
                uint32_t d = stb + p * PLANE_B + prow * 80 + pc * 16;
                CP16(d, g);
                CP16(d + 16, g + 8);
            }
            CP_COMMIT();
            CP_WAIT1();
        } else {
            CP_WAIT0();
        }
        __syncthreads();

        uint32_t stb = sb + (s & 1) * HSTAGE;
        #pragma unroll
        for (int ks = 0; ks < 2; ks++) {
            uint32_t ah[2][4];
            #pragma unroll
            for (int mf = 0; mf < 2; mf++) {
                int row = wm * 32 + mf * 16 + (gq & 1) * 8 + rr;
                int col = ks * 16 + (gq >> 1) * 8;
                LDSM4(ah[mf], stb + row * 80 + col * 2);
            }
            #pragma unroll
            for (int np = 0; np < 4; np++) {
                uint32_t bh[4];
                int row = wn * 64 + np * 16 + (gq >> 1) * 8 + rr;
                int col = ks * 16 + (gq & 1) * 8;
                LDSM4(bh, stb + PLANE_B + row * 80 + col * 2);
                #pragma unroll
                for (int mf = 0; mf < 2; mf++) {
                    MMAH(acc[mf][np*2],   ah[mf], bh[0], bh[1]);
                    MMAH(acc[mf][np*2+1], ah[mf], bh[2], bh[3]);
                }
            }
        }
        __syncthreads();
    }

    int rbase = m0 + wm * 32 + (lane >> 2);
    int cbase = n0 + wn * 64 + (lane & 3) * 2;
    #pragma unroll
    for (int mf = 0; mf < 2; mf++) {
        #pragma unroll
        for (int nf = 0; nf < 8; nf++) {
            int row = rbase + mf * 16;
            int col = cbase + nf * 8;
            size_t a0 = (size_t)row * N + col;
            size_t a1 = (size_t)(row + 8) * N + col;
            *(float2*)(C + a0) = make_float2(acc[mf][nf][0], acc[mf][nf][1]);
            *(float2*)(C + a1) = make_float2(acc[mf][nf][2], acc[mf][nf][3]);
        }
    }
}

// ================= mma.sync flash attention (bf16 split planes) ============
#define ALD 72
#define APLANE (64*ALD*2)
#define ASMEM  (6*APLANE)

__global__ void __launch_bounds__(128)
attn_mma(const __nv_bfloat16* __restrict__ Ph, const __nv_bfloat16* __restrict__ Pl,
         __half* __restrict__ Ohi, __half* __restrict__ Olo) {
    extern __shared__ char asmr[];
    uint32_t sb = smem_u32(asmr);
    const uint32_t QH = sb, QL = sb + APLANE, KH = sb + 2*APLANE,
                   KL = sb + 3*APLANE, VH = sb + 4*APLANE, VL = sb + 5*APLANE;

    int tid = threadIdx.x, lane = tid & 31, w = tid >> 5;
    int gq = lane >> 3, rr = lane & 7;
    int bh = blockIdx.y;
    int b = bh / HH, h = bh % HH;
    int qt = blockIdx.x;
    float slope = exp2f(-0.5f * (float)(h + 1));

    int lrow = tid >> 4;
    int lcol = (tid & 15) * 4;

    #pragma unroll
    for (int pass = 0; pass < 8; pass++) {
        int row = lrow + pass * 8;
        size_t ga = (size_t)(b*SS + qt*64 + row) * QKVS + h*HD + lcol;
        uint32_t off = (row*ALD + lcol) * 2;
        CP8(QH + off, Ph + ga);
        CP8(QL + off, Pl + ga);
    }
    CP_COMMIT();
    CP_WAIT0();
    __syncthreads();

    uint32_t qh[4][4], ql[4][4];
    #pragma unroll
    for (int kk = 0; kk < 4; kk++) {
        uint32_t off = ((w*16 + (gq & 1)*8 + rr)*ALD + kk*16 + (gq >> 1)*8) * 2;
        LDSM4(qh[kk], QH + off);
        LDSM4(ql[kk], QL + off);
    }

    float m0r = -INFINITY, m1r = -INFINITY, l0s = 0.f, l1s = 0.f;
    float o[8][4] = {};
    int qg0 = qt*64 + w*16 + (lane >> 2);
    int qg1 = qg0 + 8;

    for (int kt = 0; kt <= qt; kt++) {
        __syncthreads();
        #pragma unroll
        for (int pass = 0; pass < 8; pass++) {
            int row = lrow + pass * 8;
            size_t gr = (size_t)(b*SS + kt*64 + row) * QKVS + h*HD + lcol;
            uint32_t off = (row*ALD + lcol) * 2;
            CP8(KH + off, Ph + gr + DD);
            CP8(KL + off, Pl + gr + DD);
            CP8(VH + off, Ph + gr + 2*DD);
            CP8(VL + off, Pl + gr + 2*DD);
        }
        CP_COMMIT();
        CP_WAIT0();
        __syncthreads();

        float s[8][4] = {};
        #pragma unroll
        for (int kk = 0; kk < 4; kk++) {
            #pragma unroll
            for (int np = 0; np < 4; np++) {
                uint32_t kb[4], kl2[4];
                uint32_t off = ((np*16 + (gq >> 1)*8 + rr)*ALD + kk*16 + (gq & 1)*8) * 2;
                LDSM4(kb, KH + off);
                LDSM4(kl2, KL + off);
                MMA16816(s[np*2],   qh[kk], kb[0], kb[1]);
                MMA16816(s[np*2],   ql[kk], kb[0], kb[1]);
                MMA16816(s[np*2],   qh[kk], kl2[0], kl2[1]);
                MMA16816(s[np*2+1], qh[kk], kb[2], kb[3]);
                MMA16816(s[np*2+1], ql[kk], kb[2], kb[3]);
                MMA16816(s[np*2+1], qh[kk], kl2[2], kl2[3]);
            }
        }

        #pragma unroll
        for (int nf = 0; nf < 8; nf++) {
            #pragma unroll
            for (int c = 0; c < 2; c++) {
                int kg = kt*64 + nf*8 + (lane & 3)*2 + c;
                float sv0 = s[nf][c]   * 0.125f;
                float sv1 = s[nf][2+c] * 0.125f;
                s[nf][c]   = (kg <= qg0) ? sv0 + slope*(float)(kg - qg0) : -1e30f;
                s[nf][2+c] = (kg <= qg1) ? sv1 + slope*(float)(kg - qg1) : -1e30f;
            }
        }

        float mx0 = -1e30f, mx1 = -1e30f;
        #pragma unroll
        for (int nf = 0; nf < 8; nf++) {
            mx0 = fmaxf(mx0, fmaxf(s[nf][0], s[nf][1]));
            mx1 = fmaxf(mx1, fmaxf(s[nf][2], s[nf][3]));
        }
        #pragma unroll
        for (int off = 1; off <= 2; off <<= 1) {
            mx0 = fmaxf(mx0, __shfl_xor_sync(0xffffffffu, mx0, off));
            mx1 = fmaxf(mx1, __shfl_xor_sync(0xffffffffu, mx1, off));
        }
        float mn0 = fmaxf(m0r, mx0), mn1 = fmaxf(m1r, mx1);
        float al0 = __expf(m0r - mn0), al1 = __expf(m1r - mn1);
        float rs0 = 0.f, rs1 = 0.f;
        #pragma unroll
        for (int nf = 0; nf < 8; nf++) {
            s[nf][0] = __expf(s[nf][0] - mn0);
            s[nf][1] = __expf(s[nf][1] - mn0);
            s[nf][2] = __expf(s[nf][2] - mn1);
            s[nf][3] = __expf(s[nf][3] - mn1);
            rs0 += s[nf][0] + s[nf][1];
            rs1 += s[nf][2] + s[nf][3];
        }
        #pragma unroll
        for (int off = 1; off <= 2; off <<= 1) {
            rs0 += __shfl_xor_sync(0xffffffffu, rs0, off);
            rs1 += __shfl_xor_sync(0xffffffffu, rs1, off);
        }
        l0s = l0s * al0 + rs0;
        l1s = l1s * al1 + rs1;
        m0r = mn0; m1r = mn1;

        #pragma unroll
        for (int nf = 0; nf < 8; nf++) {
            o[nf][0] *= al0; o[nf][1] *= al0;
            o[nf][2] *= al1; o[nf][3] *= al1;
        }

        #pragma unroll
        for (int kk = 0; kk < 4; kk++) {
            uint32_t Ah[4], Al2[4];
            #pragma unroll
            for (int half = 0; half < 2; half++) {
                float* sv = s[2*kk + half];
                __nv_bfloat162 h01 = __floats2bfloat162_rn(sv[0], sv[1]);
                __nv_bfloat162 h23 = __floats2bfloat162_rn(sv[2], sv[3]);
                __nv_bfloat162 L01 = __floats2bfloat162_rn(
                    sv[0] - __bfloat162float(__low2bfloat16(h01)),
                    sv[1] - __bfloat162float(__high2bfloat16(h01)));
                __nv_bfloat162 L23 = __floats2bfloat162_rn(
                    sv[2] - __bfloat162float(__low2bfloat16(h23)),
                    sv[3] - __bfloat162float(__high2bfloat16(h23)));
                Ah[half*2 + 0] = *(uint32_t*)&h01;
                Ah[half*2 + 1] = *(uint32_t*)&h23;
                Al2[half*2 + 0] = *(uint32_t*)&L01;
                Al2[half*2 + 1] = *(uint32_t*)&L23;
            }
            #pragma unroll
            for (int np = 0; np < 4; np++) {
                uint32_t vb[4], vl2[4];
                uint32_t off = ((kk*16 + (gq & 1)*8 + rr)*ALD + np*16 + (gq >> 1)*8) * 2;
                LDSM4T(vb, VH + off);
                LDSM4T(vl2, VL + off);
                MMA16816(o[np*2],   Ah,  vb[0], vb[1]);
                MMA16816(o[np*2],   Al2, vb[0], vb[1]);
                MMA16816(o[np*2],   Ah,  vl2[0], vl2[1]);
                MMA16816(o[np*2+1], Ah,  vb[2], vb[3]);
                MMA16816(o[np*2+1], Al2, vb[2], vb[3]);
                MMA16816(o[np*2+1], Ah,  vl2[2], vl2[3]);
            }
        }
    }

    float inv0 = 1.f / l0s, inv1 = 1.f / l1s;
    int row0 = b*SS + qt*64 + w*16 + (lane >> 2);
    int colb = h*HD + (lane & 3)*2;
    #pragma unroll
    for (int nf = 0; nf < 8; nf++) {
        float v0 = o[nf][0]*inv0, v1 = o[nf][1]*inv0;
        float v2 = o[nf][2]*inv1, v3 = o[nf][3]*inv1;
        size_t a0 = (size_t)row0 * DD + colb + nf*8;
        size_t a1 = (size_t)(row0 + 8) * DD + colb + nf*8;
        __half h0,h1,h2,h3,L0,L1,L2,L3;
        split1h(v0, h0, L0); split1h(v1, h1, L1);
        split1h(v2, h2, L2); split1h(v3, h3, L3);
        *(__half2*)(Ohi + a0) = __halves2half2(h0, h1);
        *(__half2*)(Olo + a0) = __halves2half2(L0, L1);
        *(__half2*)(Ohi + a1) = __halves2half2(h2, h3);
        *(__half2*)(Olo + a1) = __halves2half2(L2, L3);
    }
}

// ---------------- embedding lookup ----------------
__global__ void embed_kernel(const int* __restrict__ tokens,
                             const float* __restrict__ emb,
                             float* __restrict__ x) {
    int row = blockIdx.x;
    int tok = tokens[row];
    const float4* src = (const float4*)(emb + (size_t)tok * DD);
    float4* dst = (float4*)(x + (size_t)row * DD);
    for (int i = threadIdx.x; i < DD/4; i += blockDim.x) dst[i] = src[i];
}

// ---------------- LN core -------------------------------------------------
__device__ __forceinline__ void ln_stats(const float* xr, int tid,
                                         float& mean, float& rstd) {
    float s = 0.f, s2 = 0.f;
    for (int i = tid; i < DD; i += 256) {
        float v = xr[i];
        s += v;
        s2 = fmaf(v, v, s2);
    }
    __shared__ float rs[8], rs2[8];
    #pragma unroll
    for (int o = 16; o > 0; o >>= 1) {
        s  += __shfl_down_sync(0xffffffffu, s,  o);
        s2 += __shfl_down_sync(0xffffffffu, s2, o);
    }
    int w = tid >> 5;
    if ((tid & 31) == 0) { rs[w] = s; rs2[w] = s2; }
    __syncthreads();
    __shared__ float mean_s, rstd_s;
    if (tid == 0) {
        float ts = 0.f, ts2 = 0.f;
        #pragma unroll
        for (int i = 0; i < 8; i++) { ts += rs[i]; ts2 += rs2[i]; }
        float m = ts / (float)DD;
        mean_s = m;
        rstd_s = rsqrtf(ts2 / (float)DD - m * m + 1e-5f);
    }
    __syncthreads();
    mean = mean_s; rstd = rstd_s;
}

// ---------------- layernorm -> fp16 hi/lo planes --------------------------
__global__ void ln_h2(const float* __restrict__ x,
                      const float* __restrict__ gw,
                      const float* __restrict__ bw,
                      __half* __restrict__ hi,
                      __half* __restrict__ lo) {
    int row = blockIdx.x;
    const float* xr = x + (size_t)row * DD;
    int tid = threadIdx.x;
    float m, r;
    ln_stats(xr, tid, m, r);
    __half* hrow = hi + (size_t)row * DD;
    __half* lrow = lo + (size_t)row * DD;
    for (int i = tid; i < DD; i += 256) {
        float v = (xr[i] - m) * r * gw[i] + bw[i];
        __half vh, vl;
        split1h(v, vh, vl);
        hrow[i] = vh;
        lrow[i] = vl;
    }
}

// ---------------- final layernorm -> fp16 single plane --------------------
__global__ void ln_h(const float* __restrict__ x,
                     const float* __restrict__ gw,
                     const float* __restrict__ bw,
                     __half* __restrict__ out) {
    int row = blockIdx.x;
    const float* xr = x + (size_t)row * DD;
    int tid = threadIdx.x;
    float m, r;
    ln_stats(xr, tid, m, r);
    __half* orow = out + (size_t)row * DD;
    for (int i = tid; i < DD; i += 256) {
        float v = (xr[i] - m) * r * gw[i] + bw[i];
        orow[i] = __float2half(v);
    }
}

// ---------------- launch ----------------
extern "C" void kernel_launch(void* const* d_in, const int* in_sizes, int n_in,
                              void* d_out, int out_size) {
    const int*   tokens = (const int*)d_in[0];
    const float* emb    = (const float*)d_in[1];
    const float* wq     = (const float*)d_in[2];
    const float* wk     = (const float*)d_in[3];
    const float* wv     = (const float*)d_in[4];
    const float* wo     = (const float*)d_in[5];
    const float* ln1_g  = (const float*)d_in[6];
    const float* ln1_b  = (const float*)d_in[7];
    const float* ln2_g  = (const float*)d_in[8];
    const float* ln2_b  = (const float*)d_in[9];
    const float* w1     = (const float*)d_in[10];
    const float* w2     = (const float*)d_in[11];
    const float* w3     = (const float*)d_in[12];
    const float* lnf_g  = (const float*)d_in[13];
    const float* lnf_b  = (const float*)d_in[14];
    const float* w_out  = (const float*)d_in[15];
    float* out = (float*)d_out;

    float* px;
    cudaGetSymbolAddress((void**)&px, g_x);
    __half *wq16, *ahi, *alo, *bhi, *blo;
    cudaGetSymbolAddress((void**)&wq16, g_wq16);
    cudaGetSymbolAddress((void**)&ahi, g_ahi);
    cudaGetSymbolAddress((void**)&alo, g_alo);
    cudaGetSymbolAddress((void**)&bhi, g_bhi);
    cudaGetSymbolAddress((void**)&blo, g_blo);
    __nv_bfloat16 *qkvh, *qkvl;
    cudaGetSymbolAddress((void**)&qkvh, g_qkvh);
    cudaGetSymbolAddress((void**)&qkvl, g_qkvl);

    cudaFuncSetAttribute(attn_mma,
                         cudaFuncAttributeMaxDynamicSharedMemorySize, ASMEM);
    cudaFuncSetAttribute(gemm_h2<1>,
                         cudaFuncAttributeMaxDynamicSharedMemorySize, H2SMEM);
    cudaFuncSetAttribute(gemm_h2<2>,
                         cudaFuncAttributeMaxDynamicSharedMemorySize, H2SMEM);
    cudaFuncSetAttribute(gemm_h2<3>,
                         cudaFuncAttributeMaxDynamicSharedMemorySize, H2SMEM);
    cudaFuncSetAttribute(gemm_f16,
                         cudaFuncAttributeMaxDynamicSharedMemorySize, HGSMEM);

    // ---- convert all weights to fp16 planes ----
    {
        int n4L = (LL * WMAT) / 4;
        int p4  = WMAT / 4;
        conv_h_s<<<n4L/256, 256>>>(wq, wq16 + QKV_OFF,          n4L, p4, 3*p4);
        conv_h_s<<<n4L/256, 256>>>(wk, wq16 + QKV_OFF + WMAT,   n4L, p4, 3*p4);
        conv_h_s<<<n4L/256, 256>>>(wv, wq16 + QKV_OFF + 2*WMAT, n4L, p4, 3*p4);
        conv_h_s<<<n4L/256, 256>>>(wo, wq16 + WO_OFF,           n4L, p4, p4);
        conv_w13<<<LL*2048, 256>>>(w1, w3, wq16 + W13_OFF);
        conv_h_s<<<n4L/256, 256>>>(w2, wq16 + W2_OFF,           n4L, p4, p4);
        int n4o = (VV * DD) / 4;
        conv_h_s<<<n4o/256, 256>>>(w_out, wq16 + WOUT_OFF, n4o, n4o, n4o);
    }

    embed_kernel<<<MM, 256>>>(tokens, emb, px);

    dim3 gQKV(QKVS/128, MM/128);
    dim3 gD(DD/128, MM/128);
    dim3 gFF(FFS/128, MM/128);
    for (int l = 0; l < LL; l++) {
        size_t qo = QKV_OFF + (size_t)l * 3 * WMAT;
        size_t oo = WO_OFF + (size_t)l * WMAT;
        size_t fo = W13_OFF + (size_t)l * 2 * WMAT;
        size_t to = W2_OFF + (size_t)l * WMAT;

        // attention (2-term fp16 GEMMs; bf16 3-term core)
        ln_h2<<<MM, 256>>>(px, ln1_g + l*DD, ln1_b + l*DD, ahi, alo);
        gemm_h2<2><<<gQKV, 256, H2SMEM>>>(ahi, alo, wq16 + qo,
                                          nullptr, nullptr, qkvh, qkvl,
                                          nullptr, nullptr, QKVS, DD);
        attn_mma<<<dim3(SS/64, BB*HH), 128, ASMEM>>>(qkvh, qkvl, ahi, alo);
        gemm_h2<1><<<gD, 256, H2SMEM>>>(ahi, alo, wq16 + oo,
                                        px, px, nullptr, nullptr,
                                        nullptr, nullptr, DD, DD);

        // SwiGLU FFN (fused: W13 GEMM epilogue does silu*gate -> fp16 planes)
        ln_h2<<<MM, 256>>>(px, ln2_g + l*DD, ln2_b + l*DD, ahi, alo);
        gemm_h2<3><<<gFF, 256, H2SMEM>>>(ahi, alo, wq16 + fo,
                                         nullptr, nullptr, nullptr, nullptr,
                                         bhi, blo, FFS, DD);
        gemm_h2<1><<<gD, 256, H2SMEM>>>(bhi, blo, wq16 + to,
                                        px, px, nullptr, nullptr,
                                        nullptr, nullptr, DD, DD);
    }

    // final LN (fp16) + plain-fp16 logits GEMM
    ln_h<<<MM, 256>>>(px, lnf_g, lnf_b, ahi);
    gemm_f16<<<dim3(VV/128, MM/128), 256, HGSMEM>>>(
        ahi, wq16 + WOUT_OFF, out, VV, DD);
}

// round 17
// speedup vs baseline: 3.2969x; 1.0069x over previous
#include <cuda_runtime.h>
#include <cuda_fp16.h>
#include <math.h>
#include <stdint.h>

// ---------------- problem constants ----------------
#define BB 2
#define SS 2048
#define DD 1024
#define HH 16
#define HD 64
#define LL 8
#define VV 32000
#define MM (BB*SS)          // 4096 rows
#define QKVS (3*DD)
#define FFS  (2*DD)

// ---------------- weight plane offsets (all fp16 single-plane) -------------
#define WMAT (DD*DD)
#define QKV_OFF 0                       // layer stride 3*WMAT (q,k,v row-blocks)
#define WO_OFF  (3*LL*WMAT)
#define W13_OFF (4*LL*WMAT)             // layer stride 2*WMAT (w1/w3 interleaved)
#define W2_OFF  (6*LL*WMAT)
#define WOUT_OFF (7*LL*WMAT)
#define WTOT (WOUT_OFF + (size_t)VV*DD)

// ---------------- scratch (device globals) ----------
__device__ float g_x[MM*DD];
__device__ __half g_wq16[WTOT];
__device__ __half g_ahi[MM*DD];
__device__ __half g_alo[MM*DD];
__device__ __half g_bhi[MM*DD];
__device__ __half g_blo[MM*DD];
__device__ __half g_qkvh[MM*QKVS];
__device__ __half g_qkvl[MM*QKVS];

// ================= helpers =================
__device__ __forceinline__ uint32_t smem_u32(const void* p) {
    uint32_t a;
    asm("{ .reg .u64 t; cvta.to.shared.u64 t, %1; cvt.u32.u64 %0, t; }"
        : "=r"(a) : "l"(p));
    return a;
}
#define CP16(dst, src) \
    asm volatile("cp.async.cg.shared.global [%0], [%1], 16;" :: "r"(dst), "l"(src))
#define CP8(dst, src) \
    asm volatile("cp.async.ca.shared.global [%0], [%1], 8;" :: "r"(dst), "l"(src))
#define CP_COMMIT() asm volatile("cp.async.commit_group;" ::: "memory")
#define CP_WAIT2()  asm volatile("cp.async.wait_group 2;" ::: "memory")
#define CP_WAIT1()  asm volatile("cp.async.wait_group 1;" ::: "memory")
#define CP_WAIT0()  asm volatile("cp.async.wait_group 0;" ::: "memory")
#define LDSM4(r, addr) \
    asm volatile("ldmatrix.sync.aligned.m8n8.x4.shared.b16 {%0,%1,%2,%3}, [%4];" \
        : "=r"((r)[0]), "=r"((r)[1]), "=r"((r)[2]), "=r"((r)[3]) : "r"(addr))
#define LDSM4T(r, addr) \
    asm volatile("ldmatrix.sync.aligned.m8n8.x4.trans.shared.b16 {%0,%1,%2,%3}, [%4];" \
        : "=r"((r)[0]), "=r"((r)[1]), "=r"((r)[2]), "=r"((r)[3]) : "r"(addr))
#define MMAH(c, a, b0v, b1v) \
    asm volatile("mma.sync.aligned.m16n8k16.row.col.f32.f16.f16.f32 " \
        "{%0,%1,%2,%3}, {%4,%5,%6,%7}, {%8,%9}, {%0,%1,%2,%3};" \
        : "+f"((c)[0]), "+f"((c)[1]), "+f"((c)[2]), "+f"((c)[3]) \
        : "r"((a)[0]), "r"((a)[1]), "r"((a)[2]), "r"((a)[3]), "r"(b0v), "r"(b1v))

__device__ __forceinline__ void split1h(float x, __half& h, __half& l) {
    h = __float2half(x);
    l = __float2half(x - __half2float(h));
}
__device__ __forceinline__ float silu_mul(float x, float c) {
    return x / (1.f + __expf(-x)) * c;
}

// ---------------- fp32 -> fp16 plane, strided per-layer destination --------
__global__ void conv_h_s(const float* __restrict__ src, __half* __restrict__ dst,
                         int n4, int plane4, int stride4) {
    int i = blockIdx.x * 256 + threadIdx.x;
    if (i >= n4) return;
    float4 v = ((const float4*)src)[i];
    __half2 a = __floats2half2_rn(v.x, v.y);
    __half2 b = __floats2half2_rn(v.z, v.w);
    int layer = i / plane4, rem = i - layer * plane4;
    ((uint2*)dst)[(size_t)layer * stride4 + rem] = make_uint2(*(uint32_t*)&a, *(uint32_t*)&b);
}

// ---------------- w1/w3 -> interleaved packed fp16 (8-row groups) ----------
__global__ void conv_w13(const float* __restrict__ w1, const float* __restrict__ w3,
                         __half* __restrict__ dst) {
    int i = blockIdx.x * 256 + threadIdx.x;
    int l = i >> 19;
    int rem = i & 524287;
    int p = rem >> 8;
    int q = rem & 255;
    int g = p >> 3, inner = p & 7;
    int jrow = (g >> 1) * 8 + inner;
    const float* src = (g & 1) ? w3 : w1;
    float4 v = ((const float4*)src)[((size_t)l * DD + jrow) * 256 + q];
    __half2 a = __floats2half2_rn(v.x, v.y);
    __half2 b = __floats2half2_rn(v.z, v.w);
    ((uint2*)dst)[((size_t)l * 2048 + p) * 256 + q] = make_uint2(*(uint32_t*)&a, *(uint32_t*)&b);
}

// ================= 2-term fp16 GEMM: D = (Ah+Al) @ Bq^T =====================
// OUTMODE 1: fp32 C + residual R    2: fp16 hi/lo planes, stride N
// OUTMODE 3: fused SwiGLU on interleaved W13 -> fp16 hi/lo planes (stride DD)
#define PLANE_B 10240
#define H2STAGE (3*PLANE_B)
#define H2SMEM  (2*H2STAGE)

template<int OUTMODE>
__global__ void __launch_bounds__(256, 2)
gemm_h2(const __half* __restrict__ Ahi, const __half* __restrict__ Alo,
        const __half* __restrict__ B,
        const float* __restrict__ R, float* __restrict__ C,
        __half* __restrict__ Hhi, __half* __restrict__ Hlo,
        int N, int K) {
    extern __shared__ char sm_raw[];
    uint32_t sb = smem_u32(sm_raw);
    int tid = threadIdx.x, lane = tid & 31, wid = tid >> 5;
    int wm = wid & 3, wn = wid >> 2;
    int m0 = blockIdx.y * 128, n0 = blockIdx.x * 128;

    int prow = tid >> 1;
    int pc   = (tid & 1) * 2;
    const __half* srcs[3] = {Ahi, Alo, B};
    int nslab = K / 32;

    {
        #pragma unroll
        for (int p = 0; p < 3; p++) {
            int rb = (p < 2) ? m0 : n0;
            const __half* g = srcs[p] + (size_t)(rb + prow) * K + pc * 8;
            uint32_t d = sb + p * PLANE_B + prow * 80 + pc * 16;
            CP16(d, g);
            CP16(d + 16, g + 8);
        }
        CP_COMMIT();
    }

    float acc[2][8][4] = {};
    int gq = lane >> 3, rr = lane & 7;

    for (int s = 0; s < nslab; s++) {
        if (s + 1 < nslab) {
            uint32_t stb = sb + ((s + 1) & 1) * H2STAGE;
            int k0 = (s + 1) * 32;
            #pragma unroll
            for (int p = 0; p < 3; p++) {
                int rb = (p < 2) ? m0 : n0;
                const __half* g = srcs[p] + (size_t)(rb + prow) * K + k0 + pc * 8;
                uint32_t d = stb + p * PLANE_B + prow * 80 + pc * 16;
                CP16(d, g);
                CP16(d + 16, g + 8);
            }
            CP_COMMIT();
            CP_WAIT1();
        } else {
            CP_WAIT0();
        }
        __syncthreads();

        uint32_t stb = sb + (s & 1) * H2STAGE;
        #pragma unroll
        for (int ks = 0; ks < 2; ks++) {
            uint32_t ah[2][4], al[2][4];
            #pragma unroll
            for (int mf = 0; mf < 2; mf++) {
                int row = wm * 32 + mf * 16 + (gq & 1) * 8 + rr;
                int col = ks * 16 + (gq >> 1) * 8;
                uint32_t a = stb + row * 80 + col * 2;
                LDSM4(ah[mf], a);
                LDSM4(al[mf], a + PLANE_B);
            }
            #pragma unroll
            for (int np = 0; np < 4; np++) {
                uint32_t bh[4];
                int row = wn * 64 + np * 16 + (gq >> 1) * 8 + rr;
                int col = ks * 16 + (gq & 1) * 8;
                LDSM4(bh, stb + 2 * PLANE_B + row * 80 + col * 2);
                #pragma unroll
                for (int mf = 0; mf < 2; mf++) {
                    MMAH(acc[mf][np*2],   ah[mf], bh[0], bh[1]);
                    MMAH(acc[mf][np*2],   al[mf], bh[0], bh[1]);
                    MMAH(acc[mf][np*2+1], ah[mf], bh[2], bh[3]);
                    MMAH(acc[mf][np*2+1], al[mf], bh[2], bh[3]);
                }
            }
        }
        __syncthreads();
    }

    int rbase = m0 + wm * 32 + (lane >> 2);
    int cbase = n0 + wn * 64 + (lane & 3) * 2;
    if (OUTMODE == 3) {
        #pragma unroll
        for (int mf = 0; mf < 2; mf++) {
            int row = rbase + mf * 16;
            #pragma unroll
            for (int nfp = 0; nfp < 4; nfp++) {
                int col1 = cbase + nfp * 16;
                int j = ((col1 >> 4) << 3) + (col1 & 7);
                float* v1 = acc[mf][nfp*2];
                float* v3 = acc[mf][nfp*2 + 1];
                float g0 = silu_mul(v1[0], v3[0]);
                float g1 = silu_mul(v1[1], v3[1]);
                float g2 = silu_mul(v1[2], v3[2]);
                float g3 = silu_mul(v1[3], v3[3]);
                __half h0,h1,h2,h3,L0,L1,L2,L3;
                split1h(g0, h0, L0); split1h(g1, h1, L1);
                split1h(g2, h2, L2); split1h(g3, h3, L3);
                size_t a0 = (size_t)row * DD + j;
                size_t a1 = (size_t)(row + 8) * DD + j;
                *(__half2*)(Hhi + a0) = __halves2half2(h0, h1);
                *(__half2*)(Hlo + a0) = __halves2half2(L0, L1);
                *(__half2*)(Hhi + a1) = __halves2half2(h2, h3);
                *(__half2*)(Hlo + a1) = __halves2half2(L2, L3);
            }
        }
        return;
    }
    #pragma unroll
    for (int mf = 0; mf < 2; mf++) {
        #pragma unroll
        for (int nf = 0; nf < 8; nf++) {
            int row = rbase + mf * 16;
            int col = cbase + nf * 8;
            float v0 = acc[mf][nf][0], v1 = acc[mf][nf][1];
            float v2 = acc[mf][nf][2], v3 = acc[mf][nf][3];
            size_t a0 = (size_t)row * N + col;
            size_t a1 = (size_t)(row + 8) * N + col;
            if (OUTMODE == 2) {
                __half h0,h1,h2,h3,L0,L1,L2,L3;
                split1h(v0, h0, L0); split1h(v1, h1, L1);
                split1h(v2, h2, L2); split1h(v3, h3, L3);
                *(__half2*)(Hhi + a0) = __halves2half2(h0, h1);
                *(__half2*)(Hlo + a0) = __halves2half2(L0, L1);
                *(__half2*)(Hhi + a1) = __halves2half2(h2, h3);
                *(__half2*)(Hlo + a1) = __halves2half2(L2, L3);
            } else {
                float2 r0 = *(const float2*)(R + a0);
                float2 r1 = *(const float2*)(R + a1);
                v0 += r0.x; v1 += r0.y; v2 += r1.x; v3 += r1.y;
                *(float2*)(C + a0) = make_float2(v0, v1);
                *(float2*)(C + a1) = make_float2(v2, v3);
            }
        }
    }
}

// ================= plain fp16 GEMM (logits head) =================
#define HSTAGE (2*PLANE_B)
#define HGSMEM (2*HSTAGE)

__global__ void __launch_bounds__(256, 2)
gemm_f16(const __half* __restrict__ A, const __half* __restrict__ B,
         float* __restrict__ C, int N, int K) {
    extern __shared__ char sm_raw[];
    uint32_t sb = smem_u32(sm_raw);
    int tid = threadIdx.x, lane = tid & 31, wid = tid >> 5;
    int wm = wid & 3, wn = wid >> 2;
    int m0 = blockIdx.y * 128, n0 = blockIdx.x * 128;

    int prow = tid >> 1;
    int pc   = (tid & 1) * 2;
    const __half* srcs[2] = {A, B};
    int nslab = K / 32;

    {
        #pragma unroll
        for (int p = 0; p < 2; p++) {
            int rb = p ? n0 : m0;
            const __half* g = srcs[p] + (size_t)(rb + prow) * K + pc * 8;
            uint32_t d = sb + p * PLANE_B + prow * 80 + pc * 16;
            CP16(d, g);
            CP16(d + 16, g + 8);
        }
        CP_COMMIT();
    }

    float acc[2][8][4] = {};
    int gq = lane >> 3, rr = lane & 7;

    for (int s = 0; s < nslab; s++) {
        if (s + 1 < nslab) {
            uint32_t stb = sb + ((s + 1) & 1) * HSTAGE;
            int k0 = (s + 1) * 32;
            #pragma unroll
            for (int p = 0; p < 2; p++) {
                int rb = p ? n0 : m0;
                const __half* g = srcs[p] + (size_t)(rb + prow) * K + k0 + pc * 8;
                uint32_t d = stb + p * PLANE_B + prow * 80 + pc * 16;
                CP16(d, g);
                CP16(d + 16, g + 8);
            }
            CP_COMMIT();
            CP_WAIT1();
        } else {
            CP_WAIT0();
        }
        __syncthreads();

        uint32_t stb = sb + (s & 1) * HSTAGE;
        #pragma unroll
        for (int ks = 0; ks < 2; ks++) {
            uint32_t ah[2][4];
            #pragma unroll
            for (int mf = 0; mf < 2; mf++) {
                int row = wm * 32 + mf * 16 + (gq & 1) * 8 + rr;
                int col = ks * 16 + (gq >> 1) * 8;
                LDSM4(ah[mf], stb + row * 80 + col * 2);
            }
            #pragma unroll
            for (int np = 0; np < 4; np++) {
                uint32_t bh[4];
                int row = wn * 64 + np * 16 + (gq >> 1) * 8 + rr;
                int col = ks * 16 + (gq & 1) * 8;
                LDSM4(bh, stb + PLANE_B + row * 80 + col * 2);
                #pragma unroll
                for (int mf = 0; mf < 2; mf++) {
                    MMAH(acc[mf][np*2],   ah[mf], bh[0], bh[1]);
                    MMAH(acc[mf][np*2+1], ah[mf], bh[2], bh[3]);
                }
            }
        }
        __syncthreads();
    }

    int rbase = m0 + wm * 32 + (lane >> 2);
    int cbase = n0 + wn * 64 + (lane & 3) * 2;
    #pragma unroll
    for (int mf = 0; mf < 2; mf++) {
        #pragma unroll
        for (int nf = 0; nf < 8; nf++) {
            int row = rbase + mf * 16;
            int col = cbase + nf * 8;
            size_t a0 = (size_t)row * N + col;
            size_t a1 = (size_t)(row + 8) * N + col;
            *(float2*)(C + a0) = make_float2(acc[mf][nf][0], acc[mf][nf][1]);
            *(float2*)(C + a1) = make_float2(acc[mf][nf][2], acc[mf][nf][3]);
        }
    }
}

// ================= mma.sync flash attention (fp16 planes, pipelined) =======
// K and V tiles commit as separate cp.async groups; K_{t+1} loads during
// softmax/PV of tile t, V_{t+1} loads during QK of tile t+1. Zero extra smem.
#define ALD 72
#define APLANE (64*ALD*2)
#define ASMEM  (6*APLANE)

__global__ void __launch_bounds__(128)
attn_mma(const __half* __restrict__ Ph, const __half* __restrict__ Pl,
         __half* __restrict__ Ohi, __half* __restrict__ Olo) {
    extern __shared__ char asmr[];
    uint32_t sb = smem_u32(asmr);
    const uint32_t QH = sb, QL = sb + APLANE, KH = sb + 2*APLANE,
                   KL = sb + 3*APLANE, VH = sb + 4*APLANE, VL = sb + 5*APLANE;

    int tid = threadIdx.x, lane = tid & 31, w = tid >> 5;
    int gq = lane >> 3, rr = lane & 7;
    int bh = blockIdx.y;
    int b = bh / HH, h = bh % HH;
    int qt = blockIdx.x;
    float slope = exp2f(-0.5f * (float)(h + 1));

    int lrow = tid >> 4;          // 0..7
    int lcol = (tid & 15) * 4;    // 0..60

    // ---- group 1: Q planes ----
    #pragma unroll
    for (int pass = 0; pass < 8; pass++) {
        int row = lrow + pass * 8;
        size_t ga = (size_t)(b*SS + qt*64 + row) * QKVS + h*HD + lcol;
        uint32_t off = (row*ALD + lcol) * 2;
        CP8(QH + off, Ph + ga);
        CP8(QL + off, Pl + ga);
    }
    CP_COMMIT();
    // ---- group 2: K tile 0 ----
    #pragma unroll
    for (int pass = 0; pass < 8; pass++) {
        int row = lrow + pass * 8;
        size_t gr = (size_t)(b*SS + row) * QKVS + h*HD + lcol;
        uint32_t off = (row*ALD + lcol) * 2;
        CP8(KH + off, Ph + gr + DD);
        CP8(KL + off, Pl + gr + DD);
    }
    CP_COMMIT();
    // ---- group 3: V tile 0 ----
    #pragma unroll
    for (int pass = 0; pass < 8; pass++) {
        int row = lrow + pass * 8;
        size_t gr = (size_t)(b*SS + row) * QKVS + h*HD + lcol;
        uint32_t off = (row*ALD + lcol) * 2;
        CP8(VH + off, Ph + gr + 2*DD);
        CP8(VL + off, Pl + gr + 2*DD);
    }
    CP_COMMIT();

    CP_WAIT2();        // Q ready (K0/V0 may still be in flight)
    __syncthreads();

    uint32_t qh[4][4], ql[4][4];
    #pragma unroll
    for (int kk = 0; kk < 4; kk++) {
        uint32_t off = ((w*16 + (gq & 1)*8 + rr)*ALD + kk*16 + (gq >> 1)*8) * 2;
        LDSM4(qh[kk], QH + off);
        LDSM4(ql[kk], QL + off);
    }

    float m0r = -INFINITY, m1r = -INFINITY, l0s = 0.f, l1s = 0.f;
    float o[8][4] = {};
    int qg0 = qt*64 + w*16 + (lane >> 2);
    int qg1 = qg0 + 8;

    for (int kt = 0; kt <= qt; kt++) {
        CP_WAIT1();          // K_kt complete (V_kt may be pending)
        __syncthreads();

        // ---- S = Q @ K^T (3-term fp16) ----
        float s[8][4] = {};
        #pragma unroll
        for (int kk = 0; kk < 4; kk++) {
            #pragma unroll
            for (int np = 0; np < 4; np++) {
                uint32_t kb[4], kl2[4];
                uint32_t off = ((np*16 + (gq >> 1)*8 + rr)*ALD + kk*16 + (gq & 1)*8) * 2;
                LDSM4(kb, KH + off);
                LDSM4(kl2, KL + off);
                MMAH(s[np*2],   qh[kk], kb[0], kb[1]);
                MMAH(s[np*2],   ql[kk], kb[0], kb[1]);
                MMAH(s[np*2],   qh[kk], kl2[0], kl2[1]);
                MMAH(s[np*2+1], qh[kk], kb[2], kb[3]);
                MMAH(s[np*2+1], ql[kk], kb[2], kb[3]);
                MMAH(s[np*2+1], qh[kk], kl2[2], kl2[3]);
            }
        }
        __syncthreads();     // all warps done reading K planes

        // prefetch K_{kt+1} into K planes (overlaps softmax + PV below)
        if (kt < qt) {
            #pragma unroll
            for (int pass = 0; pass < 8; pass++) {
                int row = lrow + pass * 8;
                size_t gr = (size_t)(b*SS + (kt+1)*64 + row) * QKVS + h*HD + lcol;
                uint32_t off = (row*ALD + lcol) * 2;
                CP8(KH + off, Ph + gr + DD);
                CP8(KL + off, Pl + gr + DD);
            }
            CP_COMMIT();
        }

        // ---- scale + ALiBi + causal mask ----
        #pragma unroll
        for (int nf = 0; nf < 8; nf++) {
            #pragma unroll
            for (int c = 0; c < 2; c++) {
                int kg = kt*64 + nf*8 + (lane & 3)*2 + c;
                float sv0 = s[nf][c]   * 0.125f;
                float sv1 = s[nf][2+c] * 0.125f;
                s[nf][c]   = (kg <= qg0) ? sv0 + slope*(float)(kg - qg0) : -1e30f;
                s[nf][2+c] = (kg <= qg1) ? sv1 + slope*(float)(kg - qg1) : -1e30f;
            }
        }

        // ---- online softmax (registers + shfl) ----
        float mx0 = -1e30f, mx1 = -1e30f;
        #pragma unroll
        for (int nf = 0; nf < 8; nf++) {
            mx0 = fmaxf(mx0, fmaxf(s[nf][0], s[nf][1]));
            mx1 = fmaxf(mx1, fmaxf(s[nf][2], s[nf][3]));
        }
        #pragma unroll
        for (int off = 1; off <= 2; off <<= 1) {
            mx0 = fmaxf(mx0, __shfl_xor_sync(0xffffffffu, mx0, off));
            mx1 = fmaxf(mx1, __shfl_xor_sync(0xffffffffu, mx1, off));
        }
        float mn0 = fmaxf(m0r, mx0), mn1 = fmaxf(m1r, mx1);
        float al0 = __expf(m0r - mn0), al1 = __expf(m1r - mn1);
        float rs0 = 0.f, rs1 = 0.f;
        #pragma unroll
        for (int nf = 0; nf < 8; nf++) {
            s[nf][0] = __expf(s[nf][0] - mn0);
            s[nf][1] = __expf(s[nf][1] - mn0);
            s[nf][2] = __expf(s[nf][2] - mn1);
            s[nf][3] = __expf(s[nf][3] - mn1);
            rs0 += s[nf][0] + s[nf][1];
            rs1 += s[nf][2] + s[nf][3];
        }
        #pragma unroll
        for (int off = 1; off <= 2; off <<= 1) {
            rs0 += __shfl_xor_sync(0xffffffffu, rs0, off);
            rs1 += __shfl_xor_sync(0xffffffffu, rs1, off);
        }
        l0s = l0s * al0 + rs0;
        l1s = l1s * al1 + rs1;
        m0r = mn0; m1r = mn1;

        #pragma unroll
        for (int nf = 0; nf < 8; nf++) {
            o[nf][0] *= al0; o[nf][1] *= al0;
            o[nf][2] *= al1; o[nf][3] *= al1;
        }

        // ---- wait V_kt ----
        if (kt < qt) CP_WAIT1(); else CP_WAIT0();
        __syncthreads();

        // ---- O += P @ V (P split fp16; V 2-plane; 3-term) ----
        #pragma unroll
        for (int kk = 0; kk < 4; kk++) {
            uint32_t Ah[4], Al2[4];
            #pragma unroll
            for (int half = 0; half < 2; half++) {
                float* sv = s[2*kk + half];
                __half2 h01 = __floats2half2_rn(sv[0], sv[1]);
                __half2 h23 = __floats2half2_rn(sv[2], sv[3]);
                __half2 L01 = __floats2half2_rn(
                    sv[0] - __half2float(__low2half(h01)),
                    sv[1] - __half2float(__high2half(h01)));
                __half2 L23 = __floats2half2_rn(
                    sv[2] - __half2float(__low2half(h23)),
                    sv[3] - __half2float(__high2half(h23)));
                Ah[half*2 + 0] = *(uint32_t*)&h01;
                Ah[half*2 + 1] = *(uint32_t*)&h23;
                Al2[half*2 + 0] = *(uint32_t*)&L01;
                Al2[half*2 + 1] = *(uint32_t*)&L23;
            }
            #pragma unroll
            for (int np = 0; np < 4; np++) {
                uint32_t vb[4], vl2[4];
                uint32_t off = ((kk*16 + (gq & 1)*8 + rr)*ALD + np*16 + (gq >> 1)*8) * 2;
                LDSM4T(vb, VH + off);
                LDSM4T(vl2, VL + off);
                MMAH(o[np*2],   Ah,  vb[0], vb[1]);
                MMAH(o[np*2],   Al2, vb[0], vb[1]);
                MMAH(o[np*2],   Ah,  vl2[0], vl2[1]);
                MMAH(o[np*2+1], Ah,  vb[2], vb[3]);
                MMAH(o[np*2+1], Al2, vb[2], vb[3]);
                MMAH(o[np*2+1], Ah,  vl2[2], vl2[3]);
            }
        }
        __syncthreads();     // all warps done reading V planes

        // prefetch V_{kt+1} (overlaps next tile's QK)
        if (kt < qt) {
            #pragma unroll
            for (int pass = 0; pass < 8; pass++) {
                int row = lrow + pass * 8;
                size_t gr = (size_t)(b*SS + (kt+1)*64 + row) * QKVS + h*HD + lcol;
                uint32_t off = (row*ALD + lcol) * 2;
                CP8(VH + off, Ph + gr + 2*DD);
                CP8(VL + off, Pl + gr + 2*DD);
            }
            CP_COMMIT();
        }
    }

    // ---- epilogue: fp16 hi/lo planes for WO GEMM ----
    float inv0 = 1.f / l0s, inv1 = 1.f / l1s;
    int row0 = b*SS + qt*64 + w*16 + (lane >> 2);
    int colb = h*HD + (lane & 3)*2;
    #pragma unroll
    for (int nf = 0; nf < 8; nf++) {
        float v0 = o[nf][0]*inv0, v1 = o[nf][1]*inv0;
        float v2 = o[nf][2]*inv1, v3 = o[nf][3]*inv1;
        size_t a0 = (size_t)row0 * DD + colb + nf*8;
        size_t a1 = (size_t)(row0 + 8) * DD + colb + nf*8;
        __half h0,h1,h2,h3,L0,L1,L2,L3;
        split1h(v0, h0, L0); split1h(v1, h1, L1);
        split1h(v2, h2, L2); split1h(v3, h3, L3);
        *(__half2*)(Ohi + a0) = __halves2half2(h0, h1);
        *(__half2*)(Olo + a0) = __halves2half2(L0, L1);
        *(__half2*)(Ohi + a1) = __halves2half2(h2, h3);
        *(__half2*)(Olo + a1) = __halves2half2(L2, L3);
    }
}

// ---------------- embedding lookup ----------------
__global__ void embed_kernel(const int* __restrict__ tokens,
                             const float* __restrict__ emb,
                             float* __restrict__ x) {
    int row = blockIdx.x;
    int tok = tokens[row];
    const float4* src = (const float4*)(emb + (size_t)tok * DD);
    float4* dst = (float4*)(x + (size_t)row * DD);
    for (int i = threadIdx.x; i < DD/4; i += blockDim.x) dst[i] = src[i];
}

// ---------------- LN core -------------------------------------------------
__device__ __forceinline__ void ln_stats(const float* xr, int tid,
                                         float& mean, float& rstd) {
    float s = 0.f, s2 = 0.f;
    for (int i = tid; i < DD; i += 256) {
        float v = xr[i];
        s += v;
        s2 = fmaf(v, v, s2);
    }
    __shared__ float rs[8], rs2[8];
    #pragma unroll
    for (int o = 16; o > 0; o >>= 1) {
        s  += __shfl_down_sync(0xffffffffu, s,  o);
        s2 += __shfl_down_sync(0xffffffffu, s2, o);
    }
    int w = tid >> 5;
    if ((tid & 31) == 0) { rs[w] = s; rs2[w] = s2; }
    __syncthreads();
    __shared__ float mean_s, rstd_s;
    if (tid == 0) {
        float ts = 0.f, ts2 = 0.f;
        #pragma unroll
        for (int i = 0; i < 8; i++) { ts += rs[i]; ts2 += rs2[i]; }
        float m = ts / (float)DD;
        mean_s = m;
        rstd_s = rsqrtf(ts2 / (float)DD - m * m + 1e-5f);
    }
    __syncthreads();
    mean = mean_s; rstd = rstd_s;
}

// ---------------- layernorm -> fp16 hi/lo planes --------------------------
__global__ void ln_h2(const float* __restrict__ x,
                      const float* __restrict__ gw,
                      const float* __restrict__ bw,
                      __half* __restrict__ hi,
                      __half* __restrict__ lo) {
    int row = blockIdx.x;
    const float* xr = x + (size_t)row * DD;
    int tid = threadIdx.x;
    float m, r;
    ln_stats(xr, tid, m, r);
    __half* hrow = hi + (size_t)row * DD;
    __half* lrow = lo + (size_t)row * DD;
    for (int i = tid; i < DD; i += 256) {
        float v = (xr[i] - m) * r * gw[i] + bw[i];
        __half vh, vl;
        split1h(v, vh, vl);
        hrow[i] = vh;
        lrow[i] = vl;
    }
}

// ---------------- final layernorm -> fp16 single plane --------------------
__global__ void ln_h(const float* __restrict__ x,
                     const float* __restrict__ gw,
                     const float* __restrict__ bw,
                     __half* __restrict__ out) {
    int row = blockIdx.x;
    const float* xr = x + (size_t)row * DD;
    int tid = threadIdx.x;
    float m, r;
    ln_stats(xr, tid, m, r);
    __half* orow = out + (size_t)row * DD;
    for (int i = tid; i < DD; i += 256) {
        float v = (xr[i] - m) * r * gw[i] + bw[i];
        orow[i] = __float2half(v);
    }
}

// ---------------- launch ----------------
extern "C" void kernel_launch(void* const* d_in, const int* in_sizes, int n_in,
                              void* d_out, int out_size) {
    const int*   tokens = (const int*)d_in[0];
    const float* emb    = (const float*)d_in[1];
    const float* wq     = (const float*)d_in[2];
    const float* wk     = (const float*)d_in[3];
    const float* wv     = (const float*)d_in[4];
    const float* wo     = (const float*)d_in[5];
    const float* ln1_g  = (const float*)d_in[6];
    const float* ln1_b  = (const float*)d_in[7];
    const float* ln2_g  = (const float*)d_in[8];
    const float* ln2_b  = (const float*)d_in[9];
    const float* w1     = (const float*)d_in[10];
    const float* w2     = (const float*)d_in[11];
    const float* w3     = (const float*)d_in[12];
    const float* lnf_g  = (const float*)d_in[13];
    const float* lnf_b  = (const float*)d_in[14];
    const float* w_out  = (const float*)d_in[15];
    float* out = (float*)d_out;

    float* px;
    cudaGetSymbolAddress((void**)&px, g_x);
    __half *wq16, *ahi, *alo, *bhi, *blo, *qkvh, *qkvl;
    cudaGetSymbolAddress((void**)&wq16, g_wq16);
    cudaGetSymbolAddress((void**)&ahi, g_ahi);
    cudaGetSymbolAddress((void**)&alo, g_alo);
    cudaGetSymbolAddress((void**)&bhi, g_bhi);
    cudaGetSymbolAddress((void**)&blo, g_blo);
    cudaGetSymbolAddress((void**)&qkvh, g_qkvh);
    cudaGetSymbolAddress((void**)&qkvl, g_qkvl);

    cudaFuncSetAttribute(attn_mma,
                         cudaFuncAttributeMaxDynamicSharedMemorySize, ASMEM);
    cudaFuncSetAttribute(gemm_h2<1>,
                         cudaFuncAttributeMaxDynamicSharedMemorySize, H2SMEM);
    cudaFuncSetAttribute(gemm_h2<2>,
                         cudaFuncAttributeMaxDynamicSharedMemorySize, H2SMEM);
    cudaFuncSetAttribute(gemm_h2<3>,
                         cudaFuncAttributeMaxDynamicSharedMemorySize, H2SMEM);
    cudaFuncSetAttribute(gemm_f16,
                         cudaFuncAttributeMaxDynamicSharedMemorySize, HGSMEM);

    // ---- convert all weights to fp16 planes ----
    {
        int n4L = (LL * WMAT) / 4;
        int p4  = WMAT / 4;
        conv_h_s<<<n4L/256, 256>>>(wq, wq16 + QKV_OFF,          n4L, p4, 3*p4);
        conv_h_s<<<n4L/256, 256>>>(wk, wq16 + QKV_OFF + WMAT,   n4L, p4, 3*p4);
        conv_h_s<<<n4L/256, 256>>>(wv, wq16 + QKV_OFF + 2*WMAT, n4L, p4, 3*p4);
        conv_h_s<<<n4L/256, 256>>>(wo, wq16 + WO_OFF,           n4L, p4, p4);
        conv_w13<<<LL*2048, 256>>>(w1, w3, wq16 + W13_OFF);
        conv_h_s<<<n4L/256, 256>>>(w2, wq16 + W2_OFF,           n4L, p4, p4);
        int n4o = (VV * DD) / 4;
        conv_h_s<<<n4o/256, 256>>>(w_out, wq16 + WOUT_OFF, n4o, n4o, n4o);
    }

    embed_kernel<<<MM, 256>>>(tokens, emb, px);

    dim3 gQKV(QKVS/128, MM/128);
    dim3 gD(DD/128, MM/128);
    dim3 gFF(FFS/128, MM/128);
    for (int l = 0; l < LL; l++) {
        size_t qo = QKV_OFF + (size_t)l * 3 * WMAT;
        size_t oo = WO_OFF + (size_t)l * WMAT;
        size_t fo = W13_OFF + (size_t)l * 2 * WMAT;
        size_t to = W2_OFF + (size_t)l * WMAT;

        // attention
        ln_h2<<<MM, 256>>>(px, ln1_g + l*DD, ln1_b + l*DD, ahi, alo);
        gemm_h2<2><<<gQKV, 256, H2SMEM>>>(ahi, alo, wq16 + qo,
                                          nullptr, nullptr, qkvh, qkvl, QKVS, DD);
        attn_mma<<<dim3(SS/64, BB*HH), 128, ASMEM>>>(qkvh, qkvl, ahi, alo);
        gemm_h2<1><<<gD, 256, H2SMEM>>>(ahi, alo, wq16 + oo,
                                        px, px, nullptr, nullptr, DD, DD);

        // SwiGLU FFN (fused W13 epilogue)
        ln_h2<<<MM, 256>>>(px, ln2_g + l*DD, ln2_b + l*DD, ahi, alo);
        gemm_h2<3><<<gFF, 256, H2SMEM>>>(ahi, alo, wq16 + fo,
                                         nullptr, nullptr, bhi, blo, FFS, DD);
        gemm_h2<1><<<gD, 256, H2SMEM>>>(bhi, blo, wq16 + to,
                                        px, px, nullptr, nullptr, DD, DD);
    }

    // final LN (fp16) + plain-fp16 logits GEMM
    ln_h<<<MM, 256>>>(px, lnf_g, lnf_b, ahi);
    gemm_f16<<<dim3(VV/128, MM/128), 256, HGSMEM>>>(
        ahi, wq16 + WOUT_OFF, out, VV, DD);
}